// round 3
// baseline (speedup 1.0000x reference)
#include <cuda_runtime.h>
#include <math.h>

// ---------------------------------------------------------------------------
// LoFTR linear attention, fp32 SIMT baseline.
//   B=8, L=8192, E=256, H=8, D=32, M = B*L = 65536
// Pipeline:
//   zero_kv  : clear KV/Ksum accumulators
//   proj_kv  : Q/K/V projections + feature map; Qf -> scratch; KV,Ksum atomically
//   msg_out  : Z + msg (Qf @ KV * Z) + output projection (@ Wm^T)
// ---------------------------------------------------------------------------

#define Bb 8
#define Ls 8192
#define Es 256
#define Hh 8
#define Dd 32
#define Mrows (Bb * Ls)

// scratch (static device allocations are allowed)
__device__ float g_Qf[(size_t)Mrows * Es];       // 64 MB
__device__ float g_KV[Bb * Hh * Dd * Dd];        // 65536 floats
__device__ float g_Ksum[Bb * Hh * Dd];           // 2048 floats

__device__ __forceinline__ float fmap(float x) {
    // elu(x)+1
    return x > 0.0f ? x + 1.0f : expf(x);
}

// ---------------------------------------------------------------------------
__global__ void zero_kv_kernel() {
    int i = blockIdx.x * blockDim.x + threadIdx.x;
    if (i < Bb * Hh * Dd * Dd) g_KV[i] = 0.0f;
    if (i < Bb * Hh * Dd)      g_Ksum[i] = 0.0f;
}

// ---------------------------------------------------------------------------
// Kernel 1: projections + feature map + KV/Ksum accumulation
//   block: 256 threads, row tile TM=128, N slab 64 (=2 heads), K step 16
// smem layout (floats):
//   sXT [16][132]   staging, X transposed      : 2112
//   sWT [16][68]    staging, W transposed      : 1088
//   sKf [128][66]   Kf slab                    : 8448
//   sVn [128][66]   V slab                     : 8448
// total 20096 floats = 80384 B
#define K1_SMEM_FLOATS 20096
#define K1_SMEM_BYTES  (K1_SMEM_FLOATS * 4)

__global__ __launch_bounds__(256)
void proj_kv_kernel(const float* __restrict__ q,
                    const float* __restrict__ kin,
                    const float* __restrict__ vin,
                    const float* __restrict__ Wq, const float* __restrict__ bq,
                    const float* __restrict__ Wk, const float* __restrict__ bk,
                    const float* __restrict__ Wv, const float* __restrict__ bv) {
    extern __shared__ float smem[];
    float* sXT = smem;                 // [16][132]
    float* sWT = smem + 2112;          // [16][68]
    float* sKf = smem + 3200;          // [128][66]
    float* sVn = smem + 11648;         // [128][66]

    const int tile = blockIdx.x;           // 0..511
    const int row0 = tile * 128;
    const int b    = row0 >> 13;           // row0 / 8192

    const int t  = threadIdx.x;
    const int ty = t >> 4;                 // 0..15 (8 rows each)
    const int tx = t & 15;                 // 0..15 (4 cols each)

    for (int nt = 0; nt < 4; ++nt) {
        const int n0 = nt * 64;

        for (int mat = 0; mat < 3; ++mat) {
            const float* X  = (mat == 0) ? q  : (mat == 1) ? kin : vin;
            const float* W  = (mat == 0) ? Wq : (mat == 1) ? Wk  : Wv;
            const float* bi = (mat == 0) ? bq : (mat == 1) ? bk  : bv;

            float acc[8][4];
#pragma unroll
            for (int i = 0; i < 8; ++i)
#pragma unroll
                for (int j = 0; j < 4; ++j) acc[i][j] = 0.0f;

            for (int k0 = 0; k0 < Es; k0 += 16) {
                __syncthreads();
                // stage X tile [128 x 16] transposed
#pragma unroll
                for (int s = t; s < 512; s += 256) {
                    int r  = s >> 2;
                    int c4 = (s & 3) << 2;
                    float4 xv = *(const float4*)(X + (size_t)(row0 + r) * Es + k0 + c4);
                    sXT[(c4 + 0) * 132 + r] = xv.x;
                    sXT[(c4 + 1) * 132 + r] = xv.y;
                    sXT[(c4 + 2) * 132 + r] = xv.z;
                    sXT[(c4 + 3) * 132 + r] = xv.w;
                }
                // stage W tile [64 x 16] transposed
                {
                    int n  = t >> 2;
                    int c4 = (t & 3) << 2;
                    float4 wv = *(const float4*)(W + (size_t)(n0 + n) * Es + k0 + c4);
                    sWT[(c4 + 0) * 68 + n] = wv.x;
                    sWT[(c4 + 1) * 68 + n] = wv.y;
                    sWT[(c4 + 2) * 68 + n] = wv.z;
                    sWT[(c4 + 3) * 68 + n] = wv.w;
                }
                __syncthreads();
#pragma unroll
                for (int kk = 0; kk < 16; ++kk) {
                    float4 a0 = *(const float4*)&sXT[kk * 132 + ty * 8];
                    float4 a1 = *(const float4*)&sXT[kk * 132 + ty * 8 + 4];
                    float4 b0 = *(const float4*)&sWT[kk * 68 + tx * 4];
                    float a[8] = {a0.x, a0.y, a0.z, a0.w, a1.x, a1.y, a1.z, a1.w};
                    float bb[4] = {b0.x, b0.y, b0.z, b0.w};
#pragma unroll
                    for (int i = 0; i < 8; ++i)
#pragma unroll
                        for (int j = 0; j < 4; ++j)
                            acc[i][j] += a[i] * bb[j];
                }
            }

            // epilogue
            float4 bias4 = *(const float4*)(bi + n0 + tx * 4);
            float bb[4] = {bias4.x, bias4.y, bias4.z, bias4.w};

            if (mat == 0) {
#pragma unroll
                for (int i = 0; i < 8; ++i) {
                    float4 o;
                    o.x = fmap(acc[i][0] + bb[0]);
                    o.y = fmap(acc[i][1] + bb[1]);
                    o.z = fmap(acc[i][2] + bb[2]);
                    o.w = fmap(acc[i][3] + bb[3]);
                    *(float4*)(g_Qf + (size_t)(row0 + ty * 8 + i) * Es + n0 + tx * 4) = o;
                }
            } else if (mat == 1) {
#pragma unroll
                for (int i = 0; i < 8; ++i)
#pragma unroll
                    for (int j = 0; j < 4; ++j)
                        sKf[(ty * 8 + i) * 66 + tx * 4 + j] = fmap(acc[i][j] + bb[j]);
            } else {
#pragma unroll
                for (int i = 0; i < 8; ++i)
#pragma unroll
                    for (int j = 0; j < 4; ++j)
                        sVn[(ty * 8 + i) * 66 + tx * 4 + j] = acc[i][j] + bb[j];
            }
        }

        __syncthreads();
        // KV accumulation for the two heads in this slab: 2*32*32 = 2048 outputs
        for (int o = t; o < 2048; o += 256) {
            int hh = o >> 10;            // head within slab
            int d  = (o >> 5) & 31;
            int e  = o & 31;
            int ck = hh * 32 + d;
            int cv = hh * 32 + e;
            float accKV = 0.0f;
#pragma unroll 4
            for (int r = 0; r < 128; ++r)
                accKV += sKf[r * 66 + ck] * sVn[r * 66 + cv];
            int hg = nt * 2 + hh;
            atomicAdd(&g_KV[((b * Hh + hg) * Dd + d) * Dd + e], accKV);
        }
        // Ksum for the 64 columns of this slab
        if (t < 64) {
            float s = 0.0f;
#pragma unroll 4
            for (int r = 0; r < 128; ++r) s += sKf[r * 66 + t];
            int hg = nt * 2 + (t >> 5);
            int d  = t & 31;
            atomicAdd(&g_Ksum[(b * Hh + hg) * Dd + d], s);
        }
        __syncthreads();
    }
}

// ---------------------------------------------------------------------------
// Kernel 2: Z + msg + output projection
//   block: 256 threads, row tile 64
// smem layout (floats):
//   sQf  [64][260]  : 16640
//   sMsg [64][260]  : 16640
//   sKV  [8192]     : 8192
//   sKsum[256]      : 256
//   sZ   [512]      : 512
//   sWT2 [16][68]   : 1088
// total 43328 floats = 173312 B
#define K2_SMEM_FLOATS 43328
#define K2_SMEM_BYTES  (K2_SMEM_FLOATS * 4)

__global__ __launch_bounds__(256)
void msg_out_kernel(const float* __restrict__ Wm, float* __restrict__ out) {
    extern __shared__ float smem[];
    float* sQf   = smem;            // [64][260]
    float* sMsg  = smem + 16640;    // [64][260]
    float* sKV   = smem + 33280;    // [8][32][32]
    float* sKsum = smem + 41472;    // [256]
    float* sZ    = smem + 41728;    // [64][8]
    float* sWT2  = smem + 42240;    // [16][68]

    const int tile = blockIdx.x;        // 0..1023
    const int row0 = tile * 64;
    const int b    = row0 >> 13;

    const int t = threadIdx.x;

    // Phase A: load Qf tile, KV, Ksum
    const float* Qfb = g_Qf + (size_t)row0 * Es;
    for (int s = t; s < 64 * 64; s += 256) {
        int r  = s >> 6;
        int c4 = (s & 63) << 2;
        float4 v4 = *(const float4*)(Qfb + r * Es + c4);
        *(float4*)&sQf[r * 260 + c4] = v4;
    }
    for (int s = t; s < 2048; s += 256) {
        float4 v4 = *(const float4*)(g_KV + b * 8192 + s * 4);
        *(float4*)&sKV[s * 4] = v4;
    }
    if (t < 64) {
        float4 v4 = *(const float4*)(g_Ksum + b * 256 + t * 4);
        *(float4*)&sKsum[t * 4] = v4;
    }
    __syncthreads();

    // Phase B: Z = 1 / (Qf . Ksum + eps)
    for (int task = t; task < 512; task += 256) {
        int r = task >> 3;
        int h = task & 7;
        float dot = 0.0f;
#pragma unroll
        for (int d = 0; d < 32; ++d)
            dot += sQf[r * 260 + h * 32 + d] * sKsum[h * 32 + d];
        sZ[r * 8 + h] = 1.0f / (dot + 1e-6f);
    }
    __syncthreads();

    // Phase C: msg[r][c] = Z * sum_d Qf[r][h*32+d] * KV[h][d][e], c = t
    {
        int h = t >> 5;
        int e = t & 31;
        float kvreg[32];
#pragma unroll
        for (int d = 0; d < 32; ++d) kvreg[d] = sKV[h * 1024 + d * 32 + e];
        for (int r = 0; r < 64; ++r) {
            float a = 0.0f;
#pragma unroll
            for (int d4 = 0; d4 < 8; ++d4) {
                float4 qv = *(const float4*)&sQf[r * 260 + h * 32 + d4 * 4];
                a += qv.x * kvreg[d4 * 4 + 0];
                a += qv.y * kvreg[d4 * 4 + 1];
                a += qv.z * kvreg[d4 * 4 + 2];
                a += qv.w * kvreg[d4 * 4 + 3];
            }
            sMsg[r * 260 + t] = a * sZ[r * 8 + h];
        }
    }
    __syncthreads();

    // Phase D: out tile = sMsg @ Wm^T   (64x256 @ 256x256)
    const int ty = t >> 4;   // 0..15, 4 rows each
    const int tx = t & 15;   // 0..15, 4 cols each
    for (int nt = 0; nt < 4; ++nt) {
        const int n0 = nt * 64;
        float acc[4][4];
#pragma unroll
        for (int i = 0; i < 4; ++i)
#pragma unroll
            for (int j = 0; j < 4; ++j) acc[i][j] = 0.0f;

        for (int k0 = 0; k0 < Es; k0 += 16) {
            __syncthreads();
            {
                int n  = t >> 2;
                int c4 = (t & 3) << 2;
                float4 wv = *(const float4*)(Wm + (size_t)(n0 + n) * Es + k0 + c4);
                sWT2[(c4 + 0) * 68 + n] = wv.x;
                sWT2[(c4 + 1) * 68 + n] = wv.y;
                sWT2[(c4 + 2) * 68 + n] = wv.z;
                sWT2[(c4 + 3) * 68 + n] = wv.w;
            }
            __syncthreads();
#pragma unroll
            for (int kk = 0; kk < 16; ++kk) {
                float4 b0 = *(const float4*)&sWT2[kk * 68 + tx * 4];
                float bb[4] = {b0.x, b0.y, b0.z, b0.w};
                float a0 = sMsg[(ty * 4 + 0) * 260 + k0 + kk];
                float a1 = sMsg[(ty * 4 + 1) * 260 + k0 + kk];
                float a2 = sMsg[(ty * 4 + 2) * 260 + k0 + kk];
                float a3 = sMsg[(ty * 4 + 3) * 260 + k0 + kk];
                float a[4] = {a0, a1, a2, a3};
#pragma unroll
                for (int i = 0; i < 4; ++i)
#pragma unroll
                    for (int j = 0; j < 4; ++j)
                        acc[i][j] += a[i] * bb[j];
            }
        }
#pragma unroll
        for (int i = 0; i < 4; ++i) {
            float4 o = {acc[i][0], acc[i][1], acc[i][2], acc[i][3]};
            *(float4*)(out + (size_t)(row0 + ty * 4 + i) * Es + n0 + tx * 4) = o;
        }
    }
}

// ---------------------------------------------------------------------------
extern "C" void kernel_launch(void* const* d_in, const int* in_sizes, int n_in,
                              void* d_out, int out_size) {
    const float* q  = (const float*)d_in[0];
    const float* k  = (const float*)d_in[1];
    const float* v  = (const float*)d_in[2];
    const float* Wq = (const float*)d_in[3];
    const float* bq = (const float*)d_in[4];
    const float* Wk = (const float*)d_in[5];
    const float* bk = (const float*)d_in[6];
    const float* Wv = (const float*)d_in[7];
    const float* bv = (const float*)d_in[8];
    const float* Wm = (const float*)d_in[9];
    float* out = (float*)d_out;

    cudaFuncSetAttribute(proj_kv_kernel,
                         cudaFuncAttributeMaxDynamicSharedMemorySize, K1_SMEM_BYTES);
    cudaFuncSetAttribute(msg_out_kernel,
                         cudaFuncAttributeMaxDynamicSharedMemorySize, K2_SMEM_BYTES);

    zero_kv_kernel<<<(Bb * Hh * Dd * Dd + 255) / 256, 256>>>();
    proj_kv_kernel<<<Mrows / 128, 256, K1_SMEM_BYTES>>>(q, k, v, Wq, bq, Wk, bk, Wv, bv);
    msg_out_kernel<<<Mrows / 64, 256, K2_SMEM_BYTES>>>(Wm, out);
}

// round 5
// speedup vs baseline: 1.9880x; 1.9880x over previous
#include <cuda_runtime.h>
#include <cuda_bf16.h>
#include <math.h>
#include <stdint.h>
#include <string.h>

// LoFTR linear attention via ldmatrix + mma.sync (bf16 hi/lo split, base sm_103 ISA).
// B=8, L=8192, E=256, H=8, D=32. 512 tiles x 128 rows.

#define Es 256
#define NT 512

// ---------------- device scratch ----------------
__device__ __nv_bfloat16 g_W[4][2][256][256];            // [mat][hi/lo][n][k]
__device__ unsigned char g_Qf[(size_t)NT * 131072];      // [tile][hi/lo][128][256] bf16
__device__ float g_KVp[NT][8192];                        // per-tile KV partials
__device__ float g_Ksp[NT][256];                         // per-tile Ksum partials
__device__ float g_Ksum[8 * 256];
__device__ __nv_bfloat16 g_BD[8][8][2][32][40];          // [b][h][hi/lo][e][d(pad 40)] = KV^T

// ---------------- helpers ----------------
__device__ __forceinline__ float fmap(float x) { return x > 0.0f ? x + 1.0f : expf(x); }

__device__ __forceinline__ void hilo(float x, __nv_bfloat16& h, __nv_bfloat16& l) {
    h = __float2bfloat16(x);
    l = __float2bfloat16(x - __bfloat162float(h));
}
__device__ __forceinline__ uint32_t pk(__nv_bfloat16 a, __nv_bfloat16 b) {
    __nv_bfloat162 v = __halves2bfloat162(a, b);
    uint32_t r; memcpy(&r, &v, 4); return r;
}
__device__ __forceinline__ uint32_t smem_u32(const void* p) {
    uint32_t a;
    asm("{ .reg .u64 t; cvta.to.shared.u64 t, %1; cvt.u32.u64 %0, t; }" : "=r"(a) : "l"(p));
    return a;
}
__device__ __forceinline__ void ldsm4(uint32_t& r0, uint32_t& r1, uint32_t& r2, uint32_t& r3,
                                      uint32_t a) {
    asm volatile("ldmatrix.sync.aligned.m8n8.x4.shared.b16 {%0,%1,%2,%3}, [%4];"
                 : "=r"(r0), "=r"(r1), "=r"(r2), "=r"(r3) : "r"(a));
}
__device__ __forceinline__ void mma16816(float* d, const uint32_t* a, uint32_t b0, uint32_t b1) {
    asm volatile(
        "mma.sync.aligned.m16n8k16.row.col.f32.bf16.bf16.f32 "
        "{%0,%1,%2,%3},{%4,%5,%6,%7},{%8,%9},{%0,%1,%2,%3};"
        : "+f"(d[0]), "+f"(d[1]), "+f"(d[2]), "+f"(d[3])
        : "r"(a[0]), "r"(a[1]), "r"(a[2]), "r"(a[3]), "r"(b0), "r"(b1));
}

// smem layout shared by k1/k2 (bytes)
#define SM_AH 0               // A hi: 128 x 264 bf16 = 67584
#define SM_AL 67584           // A lo
#define SM_BH 135168          // B chunk hi: 128 x 40 bf16 = 10240
#define SM_BL 145408          // B chunk lo
#define K1_KF 155648          // Kf fp32: 128 x 132 = 67584
#define K1_BIAS 223232        // bq|bk|bv: 3 x 256 fp32
#define K1_SMEM 226304
#define K2_BD 155648          // 8 heads x 2 x 32 x 40 bf16 = 40960
#define K2_Z  196608          // 128 x 8 fp32
#define K2_KS 200704          // 256 fp32
#define K2_SMEM 201728

// A operand: stride 264 bf16; B operand: stride 40 bf16.
// Warp computes m64 x n32 with 4x4 m16n8 atoms; 3 split products (hh, hl, lh).
__device__ __forceinline__ void mma_block(float acc[4][4][4],
                                          uint32_t aH, uint32_t aL, int m0, int ka,
                                          uint32_t bH, uint32_t bL, int n0, int kb, int lane) {
    uint32_t Ah[4][4], Al[4][4], Bh[2][4], Bl[2][4];
    int ar = m0 + (lane & 15);
    int ac = ka + ((lane >> 4) << 3);
    uint32_t aoff = (uint32_t)(ar * 264 + ac) * 2;
#pragma unroll
    for (int ma = 0; ma < 4; ++ma) {
        ldsm4(Ah[ma][0], Ah[ma][1], Ah[ma][2], Ah[ma][3], aH + aoff + ma * 16 * 528);
        ldsm4(Al[ma][0], Al[ma][1], Al[ma][2], Al[ma][3], aL + aoff + ma * 16 * 528);
    }
    int br = n0 + (lane & 7) + ((lane >> 4) << 3);
    int bc = kb + (((lane >> 3) & 1) << 3);
    uint32_t boff = (uint32_t)(br * 40 + bc) * 2;
#pragma unroll
    for (int nb = 0; nb < 2; ++nb) {
        ldsm4(Bh[nb][0], Bh[nb][1], Bh[nb][2], Bh[nb][3], bH + boff + nb * 16 * 80);
        ldsm4(Bl[nb][0], Bl[nb][1], Bl[nb][2], Bl[nb][3], bL + boff + nb * 16 * 80);
    }
#pragma unroll
    for (int ma = 0; ma < 4; ++ma)
#pragma unroll
        for (int na = 0; na < 4; ++na) {
            uint32_t b0h = Bh[na >> 1][(na & 1) * 2], b1h = Bh[na >> 1][(na & 1) * 2 + 1];
            uint32_t b0l = Bl[na >> 1][(na & 1) * 2], b1l = Bl[na >> 1][(na & 1) * 2 + 1];
            mma16816(acc[ma][na], Ah[ma], b0h, b1h);
            mma16816(acc[ma][na], Ah[ma], b0l, b1l);
            mma16816(acc[ma][na], Al[ma], b0h, b1h);
        }
}

__device__ __forceinline__ void build_A(unsigned char* sm, int t, int row0,
                                        const float* __restrict__ X) {
    __syncthreads();
#pragma unroll
    for (int i = 0; i < 32; ++i) {
        int idx = t + i * 256;
        int r = idx >> 6, c = (idx & 63) * 4;
        float4 xv = *(const float4*)(X + (size_t)(row0 + r) * Es + c);
        __nv_bfloat16 h0, l0, h1, l1, h2, l2, h3, l3;
        hilo(xv.x, h0, l0); hilo(xv.y, h1, l1);
        hilo(xv.z, h2, l2); hilo(xv.w, h3, l3);
        uint32_t off = (uint32_t)(r * 264 + c) * 2;
        *(uint2*)(sm + SM_AH + off) = make_uint2(pk(h0, h1), pk(h2, h3));
        *(uint2*)(sm + SM_AL + off) = make_uint2(pk(l0, l1), pk(l2, l3));
    }
    __syncthreads();
}

__device__ __forceinline__ void load_WB(unsigned char* sm, int t, int mat, int nh, int kc) {
#pragma unroll
    for (int p = 0; p < 2; ++p) {
        const uint4* src = (const uint4*)&g_W[mat][p][nh * 128][kc * 32];
        unsigned char* dst = sm + (p ? SM_BL : SM_BH);
#pragma unroll
        for (int i = 0; i < 2; ++i) {
            int s = t + i * 256, r = s >> 2, qq = s & 3;
            *(uint4*)(dst + r * 80 + qq * 16) = src[(size_t)r * 32 + qq];
        }
    }
}

// ---------------- prep kernels ----------------
__global__ __launch_bounds__(256) void prep_w_kernel(const float* __restrict__ Wq,
                                                     const float* __restrict__ Wk,
                                                     const float* __restrict__ Wv,
                                                     const float* __restrict__ Wm) {
    int id = blockIdx.x * 256 + threadIdx.x;   // 32768
    int m = id >> 13, rem = id & 8191, n = rem >> 5, g = rem & 31;
    const float* W = (m == 0) ? Wq : (m == 1) ? Wk : (m == 2) ? Wv : Wm;
    float4 a = *(const float4*)(W + (size_t)n * 256 + g * 8);
    float4 c = *(const float4*)(W + (size_t)n * 256 + g * 8 + 4);
    float xs[8] = {a.x, a.y, a.z, a.w, c.x, c.y, c.z, c.w};
    __nv_bfloat16 h[8], l[8];
#pragma unroll
    for (int p = 0; p < 8; ++p) hilo(xs[p], h[p], l[p]);
    *(uint4*)&g_W[m][0][n][g * 8] =
        make_uint4(pk(h[0], h[1]), pk(h[2], h[3]), pk(h[4], h[5]), pk(h[6], h[7]));
    *(uint4*)&g_W[m][1][n][g * 8] =
        make_uint4(pk(l[0], l[1]), pk(l[2], l[3]), pk(l[4], l[5]), pk(l[6], l[7]));
}

__global__ __launch_bounds__(256) void reduce_bd_kernel() {
    int id = blockIdx.x * 256 + threadIdx.x;   // 65536
    int b = id >> 13, i = id & 8191;
    float s = 0.0f;
#pragma unroll 8
    for (int j = 0; j < 64; ++j) s += g_KVp[b * 64 + j][i];
    int h = i >> 10, d = (i >> 5) & 31, e = i & 31;
    __nv_bfloat16 hi, lo; hilo(s, hi, lo);
    g_BD[b][h][0][e][d] = hi;
    g_BD[b][h][1][e][d] = lo;
    if (id < 2048) {
        int bb = id >> 8, c = id & 255;
        float ks = 0.0f;
#pragma unroll 8
        for (int j = 0; j < 64; ++j) ks += g_Ksp[bb * 64 + j][c];
        g_Ksum[bb * 256 + c] = ks;
    }
}

// ---------------- K1: projections + KV partials ----------------
__global__ __launch_bounds__(256, 1)
void k1_kernel(const float* __restrict__ q, const float* __restrict__ kin,
               const float* __restrict__ vin,
               const float* __restrict__ bq, const float* __restrict__ bk,
               const float* __restrict__ bv) {
    extern __shared__ unsigned char sm[];
    const uint32_t sb = smem_u32(sm);
    const int t = threadIdx.x, lane = t & 31, wid = t >> 5;
    const int wm = wid & 1, wn = wid >> 1;
    const int tile = blockIdx.x, row0 = tile * 128;

    float* sKf = (float*)(sm + K1_KF);
    float* sV  = (float*)(sm + SM_AH);     // alias: valid after V MMAs complete
    float* sB  = (float*)(sm + K1_BIAS);

    if (t < 192) {
        const float* src = (t < 64) ? bq : (t < 128) ? bk : bv;
        ((float4*)sB)[t] = ((const float4*)src)[t & 63];
    }

    const uint32_t aH = sb + SM_AH, aL = sb + SM_AL;
    const uint32_t bH = sb + SM_BH, bL = sb + SM_BL;

    // ---- Phase Q ----
    build_A(sm, t, row0, q);
    for (int nh = 0; nh < 2; ++nh) {
        float acc[4][4][4];
#pragma unroll
        for (int ma = 0; ma < 4; ++ma)
#pragma unroll
            for (int na = 0; na < 4; ++na)
#pragma unroll
                for (int i = 0; i < 4; ++i) acc[ma][na][i] = 0.0f;
        for (int kc = 0; kc < 8; ++kc) {
            load_WB(sm, t, 0, nh, kc);
            __syncthreads();
            mma_block(acc, aH, aL, wm * 64, kc * 32,      bH, bL, wn * 32, 0,  lane);
            mma_block(acc, aH, aL, wm * 64, kc * 32 + 16, bH, bL, wn * 32, 16, lane);
            __syncthreads();
        }
        // epilogue: bias + fmap -> hi/lo -> g_Qf
        unsigned char* dH = g_Qf + (size_t)tile * 131072;
        unsigned char* dL = dH + 65536;
#pragma unroll
        for (int ma = 0; ma < 4; ++ma) {
            int r1 = wm * 64 + ma * 16 + (lane >> 2);
            int r2 = r1 + 8;
#pragma unroll
            for (int na = 0; na < 4; ++na) {
                int cg = nh * 128 + wn * 32 + na * 8 + (lane & 3) * 2;
                float x0 = fmap(acc[ma][na][0] + sB[cg]);
                float x1 = fmap(acc[ma][na][1] + sB[cg + 1]);
                float x2 = fmap(acc[ma][na][2] + sB[cg]);
                float x3 = fmap(acc[ma][na][3] + sB[cg + 1]);
                __nv_bfloat16 h0, l0, h1, l1, h2, l2, h3, l3;
                hilo(x0, h0, l0); hilo(x1, h1, l1);
                hilo(x2, h2, l2); hilo(x3, h3, l3);
                *(uint32_t*)(dH + (uint32_t)(r1 * 256 + cg) * 2) = pk(h0, h1);
                *(uint32_t*)(dL + (uint32_t)(r1 * 256 + cg) * 2) = pk(l0, l1);
                *(uint32_t*)(dH + (uint32_t)(r2 * 256 + cg) * 2) = pk(h2, h3);
                *(uint32_t*)(dL + (uint32_t)(r2 * 256 + cg) * 2) = pk(l2, l3);
            }
        }
    }

    // ---- Phase K/V per n-half (4 heads at a time) ----
    for (int nh = 0; nh < 2; ++nh) {
        // K projection
        build_A(sm, t, row0, kin);
        {
            float acc[4][4][4];
#pragma unroll
            for (int ma = 0; ma < 4; ++ma)
#pragma unroll
                for (int na = 0; na < 4; ++na)
#pragma unroll
                    for (int i = 0; i < 4; ++i) acc[ma][na][i] = 0.0f;
            for (int kc = 0; kc < 8; ++kc) {
                load_WB(sm, t, 1, nh, kc);
                __syncthreads();
                mma_block(acc, aH, aL, wm * 64, kc * 32,      bH, bL, wn * 32, 0,  lane);
                mma_block(acc, aH, aL, wm * 64, kc * 32 + 16, bH, bL, wn * 32, 16, lane);
                __syncthreads();
            }
#pragma unroll
            for (int ma = 0; ma < 4; ++ma) {
                int r1 = wm * 64 + ma * 16 + (lane >> 2);
                int r2 = r1 + 8;
#pragma unroll
                for (int na = 0; na < 4; ++na) {
                    int lc = wn * 32 + na * 8 + (lane & 3) * 2;
                    int cg = nh * 128 + lc;
                    sKf[r1 * 132 + lc]     = fmap(acc[ma][na][0] + sB[256 + cg]);
                    sKf[r1 * 132 + lc + 1] = fmap(acc[ma][na][1] + sB[256 + cg + 1]);
                    sKf[r2 * 132 + lc]     = fmap(acc[ma][na][2] + sB[256 + cg]);
                    sKf[r2 * 132 + lc + 1] = fmap(acc[ma][na][3] + sB[256 + cg + 1]);
                }
            }
        }
        // V projection
        build_A(sm, t, row0, vin);
        {
            float acc[4][4][4];
#pragma unroll
            for (int ma = 0; ma < 4; ++ma)
#pragma unroll
                for (int na = 0; na < 4; ++na)
#pragma unroll
                    for (int i = 0; i < 4; ++i) acc[ma][na][i] = 0.0f;
            for (int kc = 0; kc < 8; ++kc) {
                load_WB(sm, t, 2, nh, kc);
                __syncthreads();
                mma_block(acc, aH, aL, wm * 64, kc * 32,      bH, bL, wn * 32, 0,  lane);
                mma_block(acc, aH, aL, wm * 64, kc * 32 + 16, bH, bL, wn * 32, 16, lane);
                __syncthreads();
            }
            // write V fp32 into A region (safe: all MMAs done)
#pragma unroll
            for (int ma = 0; ma < 4; ++ma) {
                int r1 = wm * 64 + ma * 16 + (lane >> 2);
                int r2 = r1 + 8;
#pragma unroll
                for (int na = 0; na < 4; ++na) {
                    int lc = wn * 32 + na * 8 + (lane & 3) * 2;
                    int cg = nh * 128 + lc;
                    sV[r1 * 132 + lc]     = acc[ma][na][0] + sB[512 + cg];
                    sV[r1 * 132 + lc + 1] = acc[ma][na][1] + sB[512 + cg + 1];
                    sV[r2 * 132 + lc]     = acc[ma][na][2] + sB[512 + cg];
                    sV[r2 * 132 + lc + 1] = acc[ma][na][3] + sB[512 + cg + 1];
                }
            }
        }
        __syncthreads();
        // KV partials: 4 heads x 32d x 32e, each over 128 rows
        for (int o4 = t; o4 < 1024; o4 += 256) {
            int h = o4 >> 8, d = (o4 >> 3) & 31, e0 = (o4 & 7) * 4;
            float a0 = 0, a1 = 0, a2 = 0, a3 = 0;
#pragma unroll 4
            for (int r = 0; r < 128; ++r) {
                float kf = sKf[r * 132 + h * 32 + d];
                float4 vv = *(const float4*)&sV[r * 132 + h * 32 + e0];
                a0 += kf * vv.x; a1 += kf * vv.y; a2 += kf * vv.z; a3 += kf * vv.w;
            }
            int hg = nh * 4 + h;
            *(float4*)&g_KVp[tile][(hg * 32 + d) * 32 + e0] = make_float4(a0, a1, a2, a3);
        }
        if (t < 128) {
            float s = 0.0f;
#pragma unroll 4
            for (int r = 0; r < 128; ++r) s += sKf[r * 132 + t];
            g_Ksp[tile][nh * 128 + t] = s;
        }
        __syncthreads();
    }
}

// ---------------- K2: Z + msg + output projection ----------------
__global__ __launch_bounds__(256, 1)
void k2_kernel(float* __restrict__ out) {
    extern __shared__ unsigned char sm[];
    const uint32_t sb = smem_u32(sm);
    const int t = threadIdx.x, lane = t & 31, wid = t >> 5;
    const int wm = wid & 1, wn = wid >> 1;
    const int tile = blockIdx.x, row0 = tile * 128, b = tile >> 6;

    float* sZ  = (float*)(sm + K2_Z);
    float* sKs = (float*)(sm + K2_KS);
    const uint32_t aH = sb + SM_AH, aL = sb + SM_AL;
    const uint32_t bH = sb + SM_BH, bL = sb + SM_BL;

    // load Qf tile into padded A smem
#pragma unroll
    for (int p = 0; p < 2; ++p) {
        const uint4* src = (const uint4*)(g_Qf + (size_t)tile * 131072 + p * 65536);
        unsigned char* dst = sm + (p ? SM_AL : SM_AH);
#pragma unroll
        for (int i = 0; i < 16; ++i) {
            int s = t + i * 256;
            int r = s >> 5, qq = s & 31;
            *(uint4*)(dst + r * 528 + qq * 16) = src[(size_t)r * 32 + qq];
        }
    }
    // load BD (all 8 heads) + Ksum
    {
        const uint4* src = (const uint4*)&g_BD[b][0][0][0][0];
        uint4* dst = (uint4*)(sm + K2_BD);
#pragma unroll
        for (int i = 0; i < 10; ++i) dst[t + i * 256] = src[t + i * 256];
        if (t < 64) ((float4*)sKs)[t] = ((const float4*)(g_Ksum + b * 256))[t];
    }
    __syncthreads();

    // Z = 1/(Qf . Ksum + eps)
#pragma unroll
    for (int i = 0; i < 4; ++i) {
        int task = t + i * 256;
        int r = task >> 3, h = task & 7;
        float dot = 0.0f;
#pragma unroll
        for (int dp = 0; dp < 16; ++dp) {
            int c = h * 32 + dp * 2;
            uint32_t off = (uint32_t)(r * 264 + c) * 2;
            uint32_t hw = *(const uint32_t*)(sm + SM_AH + off);
            uint32_t lw = *(const uint32_t*)(sm + SM_AL + off);
            __nv_bfloat162 hv, lv;
            memcpy(&hv, &hw, 4); memcpy(&lv, &lw, 4);
            float x0 = __bfloat162float(hv.x) + __bfloat162float(lv.x);
            float x1 = __bfloat162float(hv.y) + __bfloat162float(lv.y);
            dot += x0 * sKs[c] + x1 * sKs[c + 1];
        }
        sZ[r * 8 + h] = 1.0f / (dot + 1e-6f);
    }
    __syncthreads();

    // msg per head: m128 x n32(e) x k32(d), then scale by Z and overwrite A
    for (int nh = 0; nh < 2; ++nh) {
        int head = nh * 4 + wn;
        float acc[4][4][4];
#pragma unroll
        for (int ma = 0; ma < 4; ++ma)
#pragma unroll
            for (int na = 0; na < 4; ++na)
#pragma unroll
                for (int i = 0; i < 4; ++i) acc[ma][na][i] = 0.0f;
        uint32_t bdH = sb + K2_BD + head * 5120;
        uint32_t bdL = bdH + 2560;
        mma_block(acc, aH, aL, wm * 64, head * 32,      bdH, bdL, 0, 0,  lane);
        mma_block(acc, aH, aL, wm * 64, head * 32 + 16, bdH, bdL, 0, 16, lane);
        __syncwarp();
#pragma unroll
        for (int ma = 0; ma < 4; ++ma) {
            int r1 = wm * 64 + ma * 16 + (lane >> 2);
            int r2 = r1 + 8;
            float z1 = sZ[r1 * 8 + head], z2 = sZ[r2 * 8 + head];
#pragma unroll
            for (int na = 0; na < 4; ++na) {
                int cg = head * 32 + na * 8 + (lane & 3) * 2;
                float x0 = acc[ma][na][0] * z1, x1 = acc[ma][na][1] * z1;
                float x2 = acc[ma][na][2] * z2, x3 = acc[ma][na][3] * z2;
                __nv_bfloat16 h0, l0, h1, l1, h2, l2, h3, l3;
                hilo(x0, h0, l0); hilo(x1, h1, l1);
                hilo(x2, h2, l2); hilo(x3, h3, l3);
                uint32_t o1 = (uint32_t)(r1 * 264 + cg) * 2;
                uint32_t o2 = (uint32_t)(r2 * 264 + cg) * 2;
                *(uint32_t*)(sm + SM_AH + o1) = pk(h0, h1);
                *(uint32_t*)(sm + SM_AL + o1) = pk(l0, l1);
                *(uint32_t*)(sm + SM_AH + o2) = pk(h2, h3);
                *(uint32_t*)(sm + SM_AL + o2) = pk(l2, l3);
            }
        }
    }
    __syncthreads();

    // out = msg @ Wm^T
    for (int nh = 0; nh < 2; ++nh) {
        float acc[4][4][4];
#pragma unroll
        for (int ma = 0; ma < 4; ++ma)
#pragma unroll
            for (int na = 0; na < 4; ++na)
#pragma unroll
                for (int i = 0; i < 4; ++i) acc[ma][na][i] = 0.0f;
        for (int kc = 0; kc < 8; ++kc) {
            load_WB(sm, t, 3, nh, kc);
            __syncthreads();
            mma_block(acc, aH, aL, wm * 64, kc * 32,      bH, bL, wn * 32, 0,  lane);
            mma_block(acc, aH, aL, wm * 64, kc * 32 + 16, bH, bL, wn * 32, 16, lane);
            __syncthreads();
        }
#pragma unroll
        for (int ma = 0; ma < 4; ++ma) {
            int r1 = wm * 64 + ma * 16 + (lane >> 2);
            int r2 = r1 + 8;
#pragma unroll
            for (int na = 0; na < 4; ++na) {
                int cg = nh * 128 + wn * 32 + na * 8 + (lane & 3) * 2;
                *(float2*)(out + (size_t)(row0 + r1) * 256 + cg) =
                    make_float2(acc[ma][na][0], acc[ma][na][1]);
                *(float2*)(out + (size_t)(row0 + r2) * 256 + cg) =
                    make_float2(acc[ma][na][2], acc[ma][na][3]);
            }
        }
    }
}

// ---------------------------------------------------------------------------
extern "C" void kernel_launch(void* const* d_in, const int* in_sizes, int n_in,
                              void* d_out, int out_size) {
    const float* q  = (const float*)d_in[0];
    const float* k  = (const float*)d_in[1];
    const float* v  = (const float*)d_in[2];
    const float* Wq = (const float*)d_in[3];
    const float* bq = (const float*)d_in[4];
    const float* Wk = (const float*)d_in[5];
    const float* bk = (const float*)d_in[6];
    const float* Wv = (const float*)d_in[7];
    const float* bv = (const float*)d_in[8];
    const float* Wm = (const float*)d_in[9];
    float* out = (float*)d_out;

    cudaFuncSetAttribute(k1_kernel, cudaFuncAttributeMaxDynamicSharedMemorySize, K1_SMEM);
    cudaFuncSetAttribute(k2_kernel, cudaFuncAttributeMaxDynamicSharedMemorySize, K2_SMEM);

    prep_w_kernel<<<128, 256>>>(Wq, Wk, Wv, Wm);
    k1_kernel<<<NT, 256, K1_SMEM>>>(q, k, v, bq, bk, bv);
    reduce_bd_kernel<<<256, 256>>>();
    k2_kernel<<<NT, 256, K2_SMEM>>>(out);
}

// round 6
// speedup vs baseline: 2.2625x; 1.1381x over previous
#include <cuda_runtime.h>
#include <cuda_bf16.h>
#include <math.h>
#include <stdint.h>
#include <string.h>

// LoFTR linear attention via ldmatrix + mma.sync (bf16 hi/lo split, base sm_103 ISA).
// B=8, L=8192, E=256, H=8, D=32. 512 tiles x 128 rows.
// Round 6: register-pipelined weight staging (overlap LDG with MMA).

#define Es 256
#define NT 512

// ---------------- device scratch ----------------
__device__ __nv_bfloat16 g_W[4][2][256][256];            // [mat][hi/lo][n][k]
__device__ unsigned char g_Qf[(size_t)NT * 131072];      // [tile][hi/lo][128][256] bf16
__device__ float g_KVp[NT][8192];                        // per-tile KV partials
__device__ float g_Ksp[NT][256];                         // per-tile Ksum partials
__device__ float g_Ksum[8 * 256];
__device__ __nv_bfloat16 g_BD[8][8][2][32][40];          // [b][h][hi/lo][e][d(pad 40)] = KV^T

// ---------------- helpers ----------------
__device__ __forceinline__ float fmap(float x) { return x > 0.0f ? x + 1.0f : expf(x); }

__device__ __forceinline__ void hilo(float x, __nv_bfloat16& h, __nv_bfloat16& l) {
    h = __float2bfloat16(x);
    l = __float2bfloat16(x - __bfloat162float(h));
}
__device__ __forceinline__ uint32_t pk(__nv_bfloat16 a, __nv_bfloat16 b) {
    __nv_bfloat162 v = __halves2bfloat162(a, b);
    uint32_t r; memcpy(&r, &v, 4); return r;
}
__device__ __forceinline__ uint32_t smem_u32(const void* p) {
    uint32_t a;
    asm("{ .reg .u64 t; cvta.to.shared.u64 t, %1; cvt.u32.u64 %0, t; }" : "=r"(a) : "l"(p));
    return a;
}
__device__ __forceinline__ void ldsm4(uint32_t& r0, uint32_t& r1, uint32_t& r2, uint32_t& r3,
                                      uint32_t a) {
    asm volatile("ldmatrix.sync.aligned.m8n8.x4.shared.b16 {%0,%1,%2,%3}, [%4];"
                 : "=r"(r0), "=r"(r1), "=r"(r2), "=r"(r3) : "r"(a));
}
__device__ __forceinline__ void mma16816(float* d, const uint32_t* a, uint32_t b0, uint32_t b1) {
    asm volatile(
        "mma.sync.aligned.m16n8k16.row.col.f32.bf16.bf16.f32 "
        "{%0,%1,%2,%3},{%4,%5,%6,%7},{%8,%9},{%0,%1,%2,%3};"
        : "+f"(d[0]), "+f"(d[1]), "+f"(d[2]), "+f"(d[3])
        : "r"(a[0]), "r"(a[1]), "r"(a[2]), "r"(a[3]), "r"(b0), "r"(b1));
}

// smem layout shared by k1/k2 (bytes)
#define SM_AH 0               // A hi: 128 x 264 bf16 = 67584
#define SM_AL 67584           // A lo
#define SM_BH 135168          // B chunk hi: 128 x 40 bf16 = 10240
#define SM_BL 145408          // B chunk lo
#define K1_KF 155648          // Kf fp32: 128 x 132 = 67584
#define K1_BIAS 223232        // bq|bk|bv: 3 x 256 fp32
#define K1_SMEM 226304
#define K2_BD 155648          // 8 heads x 2 x 32 x 40 bf16 = 40960
#define K2_Z  196608          // 128 x 8 fp32
#define K2_KS 200704          // 256 fp32
#define K2_SMEM 201728

// A operand: stride 264 bf16; B operand: stride 40 bf16.
// Warp computes m64 x n32 with 4x4 m16n8 atoms; 3 split products (hh, hl, lh).
__device__ __forceinline__ void mma_block(float acc[4][4][4],
                                          uint32_t aH, uint32_t aL, int m0, int ka,
                                          uint32_t bH, uint32_t bL, int n0, int kb, int lane) {
    uint32_t Ah[4][4], Al[4][4], Bh[2][4], Bl[2][4];
    int ar = m0 + (lane & 15);
    int ac = ka + ((lane >> 4) << 3);
    uint32_t aoff = (uint32_t)(ar * 264 + ac) * 2;
#pragma unroll
    for (int ma = 0; ma < 4; ++ma) {
        ldsm4(Ah[ma][0], Ah[ma][1], Ah[ma][2], Ah[ma][3], aH + aoff + ma * 16 * 528);
        ldsm4(Al[ma][0], Al[ma][1], Al[ma][2], Al[ma][3], aL + aoff + ma * 16 * 528);
    }
    int br = n0 + (lane & 7) + ((lane >> 4) << 3);
    int bc = kb + (((lane >> 3) & 1) << 3);
    uint32_t boff = (uint32_t)(br * 40 + bc) * 2;
#pragma unroll
    for (int nb = 0; nb < 2; ++nb) {
        ldsm4(Bh[nb][0], Bh[nb][1], Bh[nb][2], Bh[nb][3], bH + boff + nb * 16 * 80);
        ldsm4(Bl[nb][0], Bl[nb][1], Bl[nb][2], Bl[nb][3], bL + boff + nb * 16 * 80);
    }
#pragma unroll
    for (int ma = 0; ma < 4; ++ma)
#pragma unroll
        for (int na = 0; na < 4; ++na) {
            uint32_t b0h = Bh[na >> 1][(na & 1) * 2], b1h = Bh[na >> 1][(na & 1) * 2 + 1];
            uint32_t b0l = Bl[na >> 1][(na & 1) * 2], b1l = Bl[na >> 1][(na & 1) * 2 + 1];
            mma16816(acc[ma][na], Ah[ma], b0h, b1h);
            mma16816(acc[ma][na], Ah[ma], b0l, b1l);
            mma16816(acc[ma][na], Al[ma], b0h, b1h);
        }
}

__device__ __forceinline__ void build_A(unsigned char* sm, int t, int row0,
                                        const float* __restrict__ X) {
    __syncthreads();
#pragma unroll
    for (int i = 0; i < 32; ++i) {
        int idx = t + i * 256;
        int r = idx >> 6, c = (idx & 63) * 4;
        float4 xv = *(const float4*)(X + (size_t)(row0 + r) * Es + c);
        __nv_bfloat16 h0, l0, h1, l1, h2, l2, h3, l3;
        hilo(xv.x, h0, l0); hilo(xv.y, h1, l1);
        hilo(xv.z, h2, l2); hilo(xv.w, h3, l3);
        uint32_t off = (uint32_t)(r * 264 + c) * 2;
        *(uint2*)(sm + SM_AH + off) = make_uint2(pk(h0, h1), pk(h2, h3));
        *(uint2*)(sm + SM_AL + off) = make_uint2(pk(l0, l1), pk(l2, l3));
    }
    __syncthreads();
}

// ---- register-pipelined weight staging ----
__device__ __forceinline__ void ldg_WB(uint4 r[4], int mat, int nh, int kc, int t) {
    const uint4* srcH = (const uint4*)&g_W[mat][0][nh * 128][kc * 32];
    const uint4* srcL = (const uint4*)&g_W[mat][1][nh * 128][kc * 32];
    int s0 = t, s1 = t + 256;
    r[0] = srcH[(size_t)(s0 >> 2) * 32 + (s0 & 3)];
    r[1] = srcH[(size_t)(s1 >> 2) * 32 + (s1 & 3)];
    r[2] = srcL[(size_t)(s0 >> 2) * 32 + (s0 & 3)];
    r[3] = srcL[(size_t)(s1 >> 2) * 32 + (s1 & 3)];
}
__device__ __forceinline__ void st_WB(unsigned char* sm, const uint4 r[4], int t) {
    int s0 = t, s1 = t + 256;
    *(uint4*)(sm + SM_BH + (s0 >> 2) * 80 + (s0 & 3) * 16) = r[0];
    *(uint4*)(sm + SM_BH + (s1 >> 2) * 80 + (s1 & 3) * 16) = r[1];
    *(uint4*)(sm + SM_BL + (s0 >> 2) * 80 + (s0 & 3) * 16) = r[2];
    *(uint4*)(sm + SM_BL + (s1 >> 2) * 80 + (s1 & 3) * 16) = r[3];
}

// Full 256-deep GEMM pass against weights of `mat`, n-half `nh`.
// Prefetches chunk kc+1 into registers while MMAs run on chunk kc.
__device__ __forceinline__ void run_wgemm(float acc[4][4][4], unsigned char* sm,
                                          uint32_t aH, uint32_t aL,
                                          uint32_t bHa, uint32_t bLa,
                                          int t, int lane, int wm, int wn,
                                          int mat, int nh) {
    uint4 wreg[4];
    ldg_WB(wreg, mat, nh, 0, t);
    for (int kc = 0; kc < 8; ++kc) {
        __syncthreads();
        st_WB(sm, wreg, t);
        __syncthreads();
        if (kc < 7) ldg_WB(wreg, mat, nh, kc + 1, t);
        mma_block(acc, aH, aL, wm * 64, kc * 32,      bHa, bLa, wn * 32, 0,  lane);
        mma_block(acc, aH, aL, wm * 64, kc * 32 + 16, bHa, bLa, wn * 32, 16, lane);
    }
}

// ---------------- prep kernels ----------------
__global__ __launch_bounds__(256) void prep_w_kernel(const float* __restrict__ Wq,
                                                     const float* __restrict__ Wk,
                                                     const float* __restrict__ Wv,
                                                     const float* __restrict__ Wm) {
    int id = blockIdx.x * 256 + threadIdx.x;   // 32768
    int m = id >> 13, rem = id & 8191, n = rem >> 5, g = rem & 31;
    const float* W = (m == 0) ? Wq : (m == 1) ? Wk : (m == 2) ? Wv : Wm;
    float4 a = *(const float4*)(W + (size_t)n * 256 + g * 8);
    float4 c = *(const float4*)(W + (size_t)n * 256 + g * 8 + 4);
    float xs[8] = {a.x, a.y, a.z, a.w, c.x, c.y, c.z, c.w};
    __nv_bfloat16 h[8], l[8];
#pragma unroll
    for (int p = 0; p < 8; ++p) hilo(xs[p], h[p], l[p]);
    *(uint4*)&g_W[m][0][n][g * 8] =
        make_uint4(pk(h[0], h[1]), pk(h[2], h[3]), pk(h[4], h[5]), pk(h[6], h[7]));
    *(uint4*)&g_W[m][1][n][g * 8] =
        make_uint4(pk(l[0], l[1]), pk(l[2], l[3]), pk(l[4], l[5]), pk(l[6], l[7]));
}

__global__ __launch_bounds__(256) void reduce_bd_kernel() {
    int id = blockIdx.x * 256 + threadIdx.x;   // 65536
    int b = id >> 13, i = id & 8191;
    float s = 0.0f;
#pragma unroll 8
    for (int j = 0; j < 64; ++j) s += g_KVp[b * 64 + j][i];
    int h = i >> 10, d = (i >> 5) & 31, e = i & 31;
    __nv_bfloat16 hi, lo; hilo(s, hi, lo);
    g_BD[b][h][0][e][d] = hi;
    g_BD[b][h][1][e][d] = lo;
    if (id < 2048) {
        int bb = id >> 8, c = id & 255;
        float ks = 0.0f;
#pragma unroll 8
        for (int j = 0; j < 64; ++j) ks += g_Ksp[bb * 64 + j][c];
        g_Ksum[bb * 256 + c] = ks;
    }
}

// ---------------- K1: projections + KV partials ----------------
__global__ __launch_bounds__(256, 1)
void k1_kernel(const float* __restrict__ q, const float* __restrict__ kin,
               const float* __restrict__ vin,
               const float* __restrict__ bq, const float* __restrict__ bk,
               const float* __restrict__ bv) {
    extern __shared__ unsigned char sm[];
    const uint32_t sb = smem_u32(sm);
    const int t = threadIdx.x, lane = t & 31, wid = t >> 5;
    const int wm = wid & 1, wn = wid >> 1;
    const int tile = blockIdx.x, row0 = tile * 128;

    float* sKf = (float*)(sm + K1_KF);
    float* sV  = (float*)(sm + SM_AH);     // alias: valid after V MMAs complete
    float* sB  = (float*)(sm + K1_BIAS);

    if (t < 192) {
        const float* src = (t < 64) ? bq : (t < 128) ? bk : bv;
        ((float4*)sB)[t] = ((const float4*)src)[t & 63];
    }

    const uint32_t aH = sb + SM_AH, aL = sb + SM_AL;
    const uint32_t bH = sb + SM_BH, bL = sb + SM_BL;

    // ---- Phase Q ----
    build_A(sm, t, row0, q);
    for (int nh = 0; nh < 2; ++nh) {
        float acc[4][4][4];
#pragma unroll
        for (int ma = 0; ma < 4; ++ma)
#pragma unroll
            for (int na = 0; na < 4; ++na)
#pragma unroll
                for (int i = 0; i < 4; ++i) acc[ma][na][i] = 0.0f;
        run_wgemm(acc, sm, aH, aL, bH, bL, t, lane, wm, wn, 0, nh);
        // epilogue: bias + fmap -> hi/lo -> g_Qf
        unsigned char* dH = g_Qf + (size_t)tile * 131072;
        unsigned char* dL = dH + 65536;
#pragma unroll
        for (int ma = 0; ma < 4; ++ma) {
            int r1 = wm * 64 + ma * 16 + (lane >> 2);
            int r2 = r1 + 8;
#pragma unroll
            for (int na = 0; na < 4; ++na) {
                int cg = nh * 128 + wn * 32 + na * 8 + (lane & 3) * 2;
                float x0 = fmap(acc[ma][na][0] + sB[cg]);
                float x1 = fmap(acc[ma][na][1] + sB[cg + 1]);
                float x2 = fmap(acc[ma][na][2] + sB[cg]);
                float x3 = fmap(acc[ma][na][3] + sB[cg + 1]);
                __nv_bfloat16 h0, l0, h1, l1, h2, l2, h3, l3;
                hilo(x0, h0, l0); hilo(x1, h1, l1);
                hilo(x2, h2, l2); hilo(x3, h3, l3);
                *(uint32_t*)(dH + (uint32_t)(r1 * 256 + cg) * 2) = pk(h0, h1);
                *(uint32_t*)(dL + (uint32_t)(r1 * 256 + cg) * 2) = pk(l0, l1);
                *(uint32_t*)(dH + (uint32_t)(r2 * 256 + cg) * 2) = pk(h2, h3);
                *(uint32_t*)(dL + (uint32_t)(r2 * 256 + cg) * 2) = pk(l2, l3);
            }
        }
    }

    // ---- Phase K/V per n-half (4 heads at a time) ----
    for (int nh = 0; nh < 2; ++nh) {
        // K projection
        build_A(sm, t, row0, kin);
        {
            float acc[4][4][4];
#pragma unroll
            for (int ma = 0; ma < 4; ++ma)
#pragma unroll
                for (int na = 0; na < 4; ++na)
#pragma unroll
                    for (int i = 0; i < 4; ++i) acc[ma][na][i] = 0.0f;
            run_wgemm(acc, sm, aH, aL, bH, bL, t, lane, wm, wn, 1, nh);
#pragma unroll
            for (int ma = 0; ma < 4; ++ma) {
                int r1 = wm * 64 + ma * 16 + (lane >> 2);
                int r2 = r1 + 8;
#pragma unroll
                for (int na = 0; na < 4; ++na) {
                    int lc = wn * 32 + na * 8 + (lane & 3) * 2;
                    int cg = nh * 128 + lc;
                    sKf[r1 * 132 + lc]     = fmap(acc[ma][na][0] + sB[256 + cg]);
                    sKf[r1 * 132 + lc + 1] = fmap(acc[ma][na][1] + sB[256 + cg + 1]);
                    sKf[r2 * 132 + lc]     = fmap(acc[ma][na][2] + sB[256 + cg]);
                    sKf[r2 * 132 + lc + 1] = fmap(acc[ma][na][3] + sB[256 + cg + 1]);
                }
            }
        }
        // V projection
        build_A(sm, t, row0, vin);
        {
            float acc[4][4][4];
#pragma unroll
            for (int ma = 0; ma < 4; ++ma)
#pragma unroll
                for (int na = 0; na < 4; ++na)
#pragma unroll
                    for (int i = 0; i < 4; ++i) acc[ma][na][i] = 0.0f;
            run_wgemm(acc, sm, aH, aL, bH, bL, t, lane, wm, wn, 2, nh);
            __syncthreads();   // all V MMAs done before aliasing A region with sV
            // write V fp32 into A region (safe: all MMAs done)
#pragma unroll
            for (int ma = 0; ma < 4; ++ma) {
                int r1 = wm * 64 + ma * 16 + (lane >> 2);
                int r2 = r1 + 8;
#pragma unroll
                for (int na = 0; na < 4; ++na) {
                    int lc = wn * 32 + na * 8 + (lane & 3) * 2;
                    int cg = nh * 128 + lc;
                    sV[r1 * 132 + lc]     = acc[ma][na][0] + sB[512 + cg];
                    sV[r1 * 132 + lc + 1] = acc[ma][na][1] + sB[512 + cg + 1];
                    sV[r2 * 132 + lc]     = acc[ma][na][2] + sB[512 + cg];
                    sV[r2 * 132 + lc + 1] = acc[ma][na][3] + sB[512 + cg + 1];
                }
            }
        }
        __syncthreads();
        // KV partials: 4 heads x 32d x 32e, each over 128 rows
        for (int o4 = t; o4 < 1024; o4 += 256) {
            int h = o4 >> 8, d = (o4 >> 3) & 31, e0 = (o4 & 7) * 4;
            float a0 = 0, a1 = 0, a2 = 0, a3 = 0;
#pragma unroll 4
            for (int r = 0; r < 128; ++r) {
                float kf = sKf[r * 132 + h * 32 + d];
                float4 vv = *(const float4*)&sV[r * 132 + h * 32 + e0];
                a0 += kf * vv.x; a1 += kf * vv.y; a2 += kf * vv.z; a3 += kf * vv.w;
            }
            int hg = nh * 4 + h;
            *(float4*)&g_KVp[tile][(hg * 32 + d) * 32 + e0] = make_float4(a0, a1, a2, a3);
        }
        if (t < 128) {
            float s = 0.0f;
#pragma unroll 4
            for (int r = 0; r < 128; ++r) s += sKf[r * 132 + t];
            g_Ksp[tile][nh * 128 + t] = s;
        }
        __syncthreads();
    }
}

// ---------------- K2: Z + msg + output projection ----------------
__global__ __launch_bounds__(256, 1)
void k2_kernel(float* __restrict__ out) {
    extern __shared__ unsigned char sm[];
    const uint32_t sb = smem_u32(sm);
    const int t = threadIdx.x, lane = t & 31, wid = t >> 5;
    const int wm = wid & 1, wn = wid >> 1;
    const int tile = blockIdx.x, row0 = tile * 128, b = tile >> 6;

    float* sZ  = (float*)(sm + K2_Z);
    float* sKs = (float*)(sm + K2_KS);
    const uint32_t aH = sb + SM_AH, aL = sb + SM_AL;
    const uint32_t bH = sb + SM_BH, bL = sb + SM_BL;

    // load Qf tile into padded A smem
#pragma unroll
    for (int p = 0; p < 2; ++p) {
        const uint4* src = (const uint4*)(g_Qf + (size_t)tile * 131072 + p * 65536);
        unsigned char* dst = sm + (p ? SM_AL : SM_AH);
#pragma unroll
        for (int i = 0; i < 16; ++i) {
            int s = t + i * 256;
            int r = s >> 5, qq = s & 31;
            *(uint4*)(dst + r * 528 + qq * 16) = src[(size_t)r * 32 + qq];
        }
    }
    // load BD (all 8 heads) + Ksum
    {
        const uint4* src = (const uint4*)&g_BD[b][0][0][0][0];
        uint4* dst = (uint4*)(sm + K2_BD);
#pragma unroll
        for (int i = 0; i < 10; ++i) dst[t + i * 256] = src[t + i * 256];
        if (t < 64) ((float4*)sKs)[t] = ((const float4*)(g_Ksum + b * 256))[t];
    }
    __syncthreads();

    // Z = 1/(Qf . Ksum + eps)
#pragma unroll
    for (int i = 0; i < 4; ++i) {
        int task = t + i * 256;
        int r = task >> 3, h = task & 7;
        float dot = 0.0f;
#pragma unroll
        for (int dp = 0; dp < 16; ++dp) {
            int c = h * 32 + dp * 2;
            uint32_t off = (uint32_t)(r * 264 + c) * 2;
            uint32_t hw = *(const uint32_t*)(sm + SM_AH + off);
            uint32_t lw = *(const uint32_t*)(sm + SM_AL + off);
            __nv_bfloat162 hv, lv;
            memcpy(&hv, &hw, 4); memcpy(&lv, &lw, 4);
            float x0 = __bfloat162float(hv.x) + __bfloat162float(lv.x);
            float x1 = __bfloat162float(hv.y) + __bfloat162float(lv.y);
            dot += x0 * sKs[c] + x1 * sKs[c + 1];
        }
        sZ[r * 8 + h] = 1.0f / (dot + 1e-6f);
    }
    __syncthreads();

    // msg per head: m128 x n32(e) x k32(d), then scale by Z and overwrite A
    for (int nh = 0; nh < 2; ++nh) {
        int head = nh * 4 + wn;
        float acc[4][4][4];
#pragma unroll
        for (int ma = 0; ma < 4; ++ma)
#pragma unroll
            for (int na = 0; na < 4; ++na)
#pragma unroll
                for (int i = 0; i < 4; ++i) acc[ma][na][i] = 0.0f;
        uint32_t bdH = sb + K2_BD + head * 5120;
        uint32_t bdL = bdH + 2560;
        mma_block(acc, aH, aL, wm * 64, head * 32,      bdH, bdL, 0, 0,  lane);
        mma_block(acc, aH, aL, wm * 64, head * 32 + 16, bdH, bdL, 0, 16, lane);
        __syncwarp();
#pragma unroll
        for (int ma = 0; ma < 4; ++ma) {
            int r1 = wm * 64 + ma * 16 + (lane >> 2);
            int r2 = r1 + 8;
            float z1 = sZ[r1 * 8 + head], z2 = sZ[r2 * 8 + head];
#pragma unroll
            for (int na = 0; na < 4; ++na) {
                int cg = head * 32 + na * 8 + (lane & 3) * 2;
                float x0 = acc[ma][na][0] * z1, x1 = acc[ma][na][1] * z1;
                float x2 = acc[ma][na][2] * z2, x3 = acc[ma][na][3] * z2;
                __nv_bfloat16 h0, l0, h1, l1, h2, l2, h3, l3;
                hilo(x0, h0, l0); hilo(x1, h1, l1);
                hilo(x2, h2, l2); hilo(x3, h3, l3);
                uint32_t o1 = (uint32_t)(r1 * 264 + cg) * 2;
                uint32_t o2 = (uint32_t)(r2 * 264 + cg) * 2;
                *(uint32_t*)(sm + SM_AH + o1) = pk(h0, h1);
                *(uint32_t*)(sm + SM_AL + o1) = pk(l0, l1);
                *(uint32_t*)(sm + SM_AH + o2) = pk(h2, h3);
                *(uint32_t*)(sm + SM_AL + o2) = pk(l2, l3);
            }
        }
    }
    __syncthreads();

    // out = msg @ Wm^T  (register-pipelined weight staging)
    for (int nh = 0; nh < 2; ++nh) {
        float acc[4][4][4];
#pragma unroll
        for (int ma = 0; ma < 4; ++ma)
#pragma unroll
            for (int na = 0; na < 4; ++na)
#pragma unroll
                for (int i = 0; i < 4; ++i) acc[ma][na][i] = 0.0f;
        run_wgemm(acc, sm, aH, aL, bH, bL, t, lane, wm, wn, 3, nh);
#pragma unroll
        for (int ma = 0; ma < 4; ++ma) {
            int r1 = wm * 64 + ma * 16 + (lane >> 2);
            int r2 = r1 + 8;
#pragma unroll
            for (int na = 0; na < 4; ++na) {
                int cg = nh * 128 + wn * 32 + na * 8 + (lane & 3) * 2;
                *(float2*)(out + (size_t)(row0 + r1) * 256 + cg) =
                    make_float2(acc[ma][na][0], acc[ma][na][1]);
                *(float2*)(out + (size_t)(row0 + r2) * 256 + cg) =
                    make_float2(acc[ma][na][2], acc[ma][na][3]);
            }
        }
    }
}

// ---------------------------------------------------------------------------
extern "C" void kernel_launch(void* const* d_in, const int* in_sizes, int n_in,
                              void* d_out, int out_size) {
    const float* q  = (const float*)d_in[0];
    const float* k  = (const float*)d_in[1];
    const float* v  = (const float*)d_in[2];
    const float* Wq = (const float*)d_in[3];
    const float* bq = (const float*)d_in[4];
    const float* Wk = (const float*)d_in[5];
    const float* bk = (const float*)d_in[6];
    const float* Wv = (const float*)d_in[7];
    const float* bv = (const float*)d_in[8];
    const float* Wm = (const float*)d_in[9];
    float* out = (float*)d_out;

    cudaFuncSetAttribute(k1_kernel, cudaFuncAttributeMaxDynamicSharedMemorySize, K1_SMEM);
    cudaFuncSetAttribute(k2_kernel, cudaFuncAttributeMaxDynamicSharedMemorySize, K2_SMEM);

    prep_w_kernel<<<128, 256>>>(Wq, Wk, Wv, Wm);
    k1_kernel<<<NT, 256, K1_SMEM>>>(q, k, v, bq, bk, bv);
    reduce_bd_kernel<<<256, 256>>>();
    k2_kernel<<<NT, 256, K2_SMEM>>>(out);
}

// round 7
// speedup vs baseline: 2.3095x; 1.0208x over previous
#include <cuda_runtime.h>
#include <cuda_bf16.h>
#include <math.h>
#include <stdint.h>
#include <string.h>

// LoFTR linear attention via ldmatrix + mma.sync (bf16 hi/lo split, base sm_103 ISA).
// B=8, L=8192, E=256, H=8, D=32. 512 tiles x 128 rows.
// Round 7: 512 threads / 16 warps (m32n32 warp tiles) for latency hiding.

#define Es 256
#define NT 512
#define NTHREADS 512

// ---------------- device scratch ----------------
__device__ __nv_bfloat16 g_W[4][2][256][256];            // [mat][hi/lo][n][k]
__device__ unsigned char g_Qf[(size_t)NT * 131072];      // [tile][hi/lo][128][256] bf16
__device__ float g_KVp[NT][8192];                        // per-tile KV partials
__device__ float g_Ksp[NT][256];                         // per-tile Ksum partials
__device__ float g_Ksum[8 * 256];
__device__ __nv_bfloat16 g_BD[8][8][2][32][40];          // [b][h][hi/lo][e][d(pad 40)] = KV^T

// ---------------- helpers ----------------
__device__ __forceinline__ float fmap(float x) { return x > 0.0f ? x + 1.0f : expf(x); }

__device__ __forceinline__ void hilo(float x, __nv_bfloat16& h, __nv_bfloat16& l) {
    h = __float2bfloat16(x);
    l = __float2bfloat16(x - __bfloat162float(h));
}
__device__ __forceinline__ uint32_t pk(__nv_bfloat16 a, __nv_bfloat16 b) {
    __nv_bfloat162 v = __halves2bfloat162(a, b);
    uint32_t r; memcpy(&r, &v, 4); return r;
}
__device__ __forceinline__ uint32_t smem_u32(const void* p) {
    uint32_t a;
    asm("{ .reg .u64 t; cvta.to.shared.u64 t, %1; cvt.u32.u64 %0, t; }" : "=r"(a) : "l"(p));
    return a;
}
__device__ __forceinline__ void ldsm4(uint32_t& r0, uint32_t& r1, uint32_t& r2, uint32_t& r3,
                                      uint32_t a) {
    asm volatile("ldmatrix.sync.aligned.m8n8.x4.shared.b16 {%0,%1,%2,%3}, [%4];"
                 : "=r"(r0), "=r"(r1), "=r"(r2), "=r"(r3) : "r"(a));
}
__device__ __forceinline__ void mma16816(float* d, const uint32_t* a, uint32_t b0, uint32_t b1) {
    asm volatile(
        "mma.sync.aligned.m16n8k16.row.col.f32.bf16.bf16.f32 "
        "{%0,%1,%2,%3},{%4,%5,%6,%7},{%8,%9},{%0,%1,%2,%3};"
        : "+f"(d[0]), "+f"(d[1]), "+f"(d[2]), "+f"(d[3])
        : "r"(a[0]), "r"(a[1]), "r"(a[2]), "r"(a[3]), "r"(b0), "r"(b1));
}

// smem layout shared by k1/k2 (bytes)
#define SM_AH 0               // A hi: 128 x 264 bf16 = 67584
#define SM_AL 67584           // A lo
#define SM_BH 135168          // B chunk hi: 128 x 40 bf16 = 10240
#define SM_BL 145408          // B chunk lo
#define K1_KF 155648          // Kf fp32: 128 x 132 = 67584
#define K1_BIAS 223232        // bq|bk|bv: 3 x 256 fp32
#define K1_SMEM 226304
#define K2_BD 155648          // 8 heads x 2 x 32 x 40 bf16 = 40960
#define K2_Z  196608          // 128 x 8 fp32
#define K2_KS 200704          // 256 fp32
#define K2_SMEM 201728

// A operand: stride 264 bf16; B operand: stride 40 bf16.
// Warp computes m32 x n32 with 2x4 m16n8 atoms; 3 split products (hh, hl, lh).
__device__ __forceinline__ void mma_block(float acc[2][4][4],
                                          uint32_t aH, uint32_t aL, int m0, int ka,
                                          uint32_t bH, uint32_t bL, int n0, int kb, int lane) {
    uint32_t Ah[2][4], Al[2][4], Bh[2][4], Bl[2][4];
    int ar = m0 + (lane & 15);
    int ac = ka + ((lane >> 4) << 3);
    uint32_t aoff = (uint32_t)(ar * 264 + ac) * 2;
#pragma unroll
    for (int ma = 0; ma < 2; ++ma) {
        ldsm4(Ah[ma][0], Ah[ma][1], Ah[ma][2], Ah[ma][3], aH + aoff + ma * 16 * 528);
        ldsm4(Al[ma][0], Al[ma][1], Al[ma][2], Al[ma][3], aL + aoff + ma * 16 * 528);
    }
    int br = n0 + (lane & 7) + ((lane >> 4) << 3);
    int bc = kb + (((lane >> 3) & 1) << 3);
    uint32_t boff = (uint32_t)(br * 40 + bc) * 2;
#pragma unroll
    for (int nb = 0; nb < 2; ++nb) {
        ldsm4(Bh[nb][0], Bh[nb][1], Bh[nb][2], Bh[nb][3], bH + boff + nb * 16 * 80);
        ldsm4(Bl[nb][0], Bl[nb][1], Bl[nb][2], Bl[nb][3], bL + boff + nb * 16 * 80);
    }
#pragma unroll
    for (int ma = 0; ma < 2; ++ma)
#pragma unroll
        for (int na = 0; na < 4; ++na) {
            uint32_t b0h = Bh[na >> 1][(na & 1) * 2], b1h = Bh[na >> 1][(na & 1) * 2 + 1];
            uint32_t b0l = Bl[na >> 1][(na & 1) * 2], b1l = Bl[na >> 1][(na & 1) * 2 + 1];
            mma16816(acc[ma][na], Ah[ma], b0h, b1h);
            mma16816(acc[ma][na], Ah[ma], b0l, b1l);
            mma16816(acc[ma][na], Al[ma], b0h, b1h);
        }
}

__device__ __forceinline__ void build_A(unsigned char* sm, int t, int row0,
                                        const float* __restrict__ X) {
    __syncthreads();
#pragma unroll
    for (int i = 0; i < 16; ++i) {
        int idx = t + i * NTHREADS;
        int r = idx >> 6, c = (idx & 63) * 4;
        float4 xv = *(const float4*)(X + (size_t)(row0 + r) * Es + c);
        __nv_bfloat16 h0, l0, h1, l1, h2, l2, h3, l3;
        hilo(xv.x, h0, l0); hilo(xv.y, h1, l1);
        hilo(xv.z, h2, l2); hilo(xv.w, h3, l3);
        uint32_t off = (uint32_t)(r * 264 + c) * 2;
        *(uint2*)(sm + SM_AH + off) = make_uint2(pk(h0, h1), pk(h2, h3));
        *(uint2*)(sm + SM_AL + off) = make_uint2(pk(l0, l1), pk(l2, l3));
    }
    __syncthreads();
}

// ---- register-pipelined weight staging (512 threads: 2 uint4 each) ----
__device__ __forceinline__ void ldg_WB(uint4 r[2], int mat, int nh, int kc, int t) {
    const uint4* srcH = (const uint4*)&g_W[mat][0][nh * 128][kc * 32];
    const uint4* srcL = (const uint4*)&g_W[mat][1][nh * 128][kc * 32];
    r[0] = srcH[(size_t)(t >> 2) * 32 + (t & 3)];
    r[1] = srcL[(size_t)(t >> 2) * 32 + (t & 3)];
}
__device__ __forceinline__ void st_WB(unsigned char* sm, const uint4 r[2], int t) {
    *(uint4*)(sm + SM_BH + (t >> 2) * 80 + (t & 3) * 16) = r[0];
    *(uint4*)(sm + SM_BL + (t >> 2) * 80 + (t & 3) * 16) = r[1];
}

// Full 256-deep GEMM pass against weights of `mat`, n-half `nh`.
__device__ __forceinline__ void run_wgemm(float acc[2][4][4], unsigned char* sm,
                                          uint32_t aH, uint32_t aL,
                                          uint32_t bHa, uint32_t bLa,
                                          int t, int lane, int wm, int wn,
                                          int mat, int nh) {
    uint4 wreg[2];
    ldg_WB(wreg, mat, nh, 0, t);
    for (int kc = 0; kc < 8; ++kc) {
        __syncthreads();
        st_WB(sm, wreg, t);
        __syncthreads();
        if (kc < 7) ldg_WB(wreg, mat, nh, kc + 1, t);
        mma_block(acc, aH, aL, wm * 32, kc * 32,      bHa, bLa, wn * 32, 0,  lane);
        mma_block(acc, aH, aL, wm * 32, kc * 32 + 16, bHa, bLa, wn * 32, 16, lane);
    }
}

// ---------------- prep kernels ----------------
__global__ __launch_bounds__(256) void prep_w_kernel(const float* __restrict__ Wq,
                                                     const float* __restrict__ Wk,
                                                     const float* __restrict__ Wv,
                                                     const float* __restrict__ Wm) {
    int id = blockIdx.x * 256 + threadIdx.x;   // 32768
    int m = id >> 13, rem = id & 8191, n = rem >> 5, g = rem & 31;
    const float* W = (m == 0) ? Wq : (m == 1) ? Wk : (m == 2) ? Wv : Wm;
    float4 a = *(const float4*)(W + (size_t)n * 256 + g * 8);
    float4 c = *(const float4*)(W + (size_t)n * 256 + g * 8 + 4);
    float xs[8] = {a.x, a.y, a.z, a.w, c.x, c.y, c.z, c.w};
    __nv_bfloat16 h[8], l[8];
#pragma unroll
    for (int p = 0; p < 8; ++p) hilo(xs[p], h[p], l[p]);
    *(uint4*)&g_W[m][0][n][g * 8] =
        make_uint4(pk(h[0], h[1]), pk(h[2], h[3]), pk(h[4], h[5]), pk(h[6], h[7]));
    *(uint4*)&g_W[m][1][n][g * 8] =
        make_uint4(pk(l[0], l[1]), pk(l[2], l[3]), pk(l[4], l[5]), pk(l[6], l[7]));
}

__global__ __launch_bounds__(256) void reduce_bd_kernel() {
    int id = blockIdx.x * 256 + threadIdx.x;   // 65536
    int b = id >> 13, i = id & 8191;
    float s = 0.0f;
#pragma unroll 8
    for (int j = 0; j < 64; ++j) s += g_KVp[b * 64 + j][i];
    int h = i >> 10, d = (i >> 5) & 31, e = i & 31;
    __nv_bfloat16 hi, lo; hilo(s, hi, lo);
    g_BD[b][h][0][e][d] = hi;
    g_BD[b][h][1][e][d] = lo;
    if (id < 2048) {
        int bb = id >> 8, c = id & 255;
        float ks = 0.0f;
#pragma unroll 8
        for (int j = 0; j < 64; ++j) ks += g_Ksp[bb * 64 + j][c];
        g_Ksum[bb * 256 + c] = ks;
    }
}

// ---------------- K1: projections + KV partials ----------------
__global__ __launch_bounds__(NTHREADS, 1)
void k1_kernel(const float* __restrict__ q, const float* __restrict__ kin,
               const float* __restrict__ vin,
               const float* __restrict__ bq, const float* __restrict__ bk,
               const float* __restrict__ bv) {
    extern __shared__ unsigned char sm[];
    const uint32_t sb = smem_u32(sm);
    const int t = threadIdx.x, lane = t & 31, wid = t >> 5;
    const int wm = wid & 3, wn = wid >> 2;
    const int tile = blockIdx.x, row0 = tile * 128;

    float* sKf = (float*)(sm + K1_KF);
    float* sV  = (float*)(sm + SM_AH);     // alias: valid after V MMAs complete
    float* sB  = (float*)(sm + K1_BIAS);

    if (t < 192) {
        const float* src = (t < 64) ? bq : (t < 128) ? bk : bv;
        ((float4*)sB)[t] = ((const float4*)src)[t & 63];
    }

    const uint32_t aH = sb + SM_AH, aL = sb + SM_AL;
    const uint32_t bH = sb + SM_BH, bL = sb + SM_BL;

    // ---- Phase Q ----
    build_A(sm, t, row0, q);
    for (int nh = 0; nh < 2; ++nh) {
        float acc[2][4][4];
#pragma unroll
        for (int ma = 0; ma < 2; ++ma)
#pragma unroll
            for (int na = 0; na < 4; ++na)
#pragma unroll
                for (int i = 0; i < 4; ++i) acc[ma][na][i] = 0.0f;
        run_wgemm(acc, sm, aH, aL, bH, bL, t, lane, wm, wn, 0, nh);
        // epilogue: bias + fmap -> hi/lo -> g_Qf
        unsigned char* dH = g_Qf + (size_t)tile * 131072;
        unsigned char* dL = dH + 65536;
#pragma unroll
        for (int ma = 0; ma < 2; ++ma) {
            int r1 = wm * 32 + ma * 16 + (lane >> 2);
            int r2 = r1 + 8;
#pragma unroll
            for (int na = 0; na < 4; ++na) {
                int cg = nh * 128 + wn * 32 + na * 8 + (lane & 3) * 2;
                float x0 = fmap(acc[ma][na][0] + sB[cg]);
                float x1 = fmap(acc[ma][na][1] + sB[cg + 1]);
                float x2 = fmap(acc[ma][na][2] + sB[cg]);
                float x3 = fmap(acc[ma][na][3] + sB[cg + 1]);
                __nv_bfloat16 h0, l0, h1, l1, h2, l2, h3, l3;
                hilo(x0, h0, l0); hilo(x1, h1, l1);
                hilo(x2, h2, l2); hilo(x3, h3, l3);
                *(uint32_t*)(dH + (uint32_t)(r1 * 256 + cg) * 2) = pk(h0, h1);
                *(uint32_t*)(dL + (uint32_t)(r1 * 256 + cg) * 2) = pk(l0, l1);
                *(uint32_t*)(dH + (uint32_t)(r2 * 256 + cg) * 2) = pk(h2, h3);
                *(uint32_t*)(dL + (uint32_t)(r2 * 256 + cg) * 2) = pk(l2, l3);
            }
        }
    }

    // ---- Phase K/V per n-half (4 heads at a time) ----
    for (int nh = 0; nh < 2; ++nh) {
        // K projection
        build_A(sm, t, row0, kin);
        {
            float acc[2][4][4];
#pragma unroll
            for (int ma = 0; ma < 2; ++ma)
#pragma unroll
                for (int na = 0; na < 4; ++na)
#pragma unroll
                    for (int i = 0; i < 4; ++i) acc[ma][na][i] = 0.0f;
            run_wgemm(acc, sm, aH, aL, bH, bL, t, lane, wm, wn, 1, nh);
#pragma unroll
            for (int ma = 0; ma < 2; ++ma) {
                int r1 = wm * 32 + ma * 16 + (lane >> 2);
                int r2 = r1 + 8;
#pragma unroll
                for (int na = 0; na < 4; ++na) {
                    int lc = wn * 32 + na * 8 + (lane & 3) * 2;
                    int cg = nh * 128 + lc;
                    sKf[r1 * 132 + lc]     = fmap(acc[ma][na][0] + sB[256 + cg]);
                    sKf[r1 * 132 + lc + 1] = fmap(acc[ma][na][1] + sB[256 + cg + 1]);
                    sKf[r2 * 132 + lc]     = fmap(acc[ma][na][2] + sB[256 + cg]);
                    sKf[r2 * 132 + lc + 1] = fmap(acc[ma][na][3] + sB[256 + cg + 1]);
                }
            }
        }
        // V projection
        build_A(sm, t, row0, vin);
        {
            float acc[2][4][4];
#pragma unroll
            for (int ma = 0; ma < 2; ++ma)
#pragma unroll
                for (int na = 0; na < 4; ++na)
#pragma unroll
                    for (int i = 0; i < 4; ++i) acc[ma][na][i] = 0.0f;
            run_wgemm(acc, sm, aH, aL, bH, bL, t, lane, wm, wn, 2, nh);
            __syncthreads();   // all V MMAs done before aliasing A region with sV
#pragma unroll
            for (int ma = 0; ma < 2; ++ma) {
                int r1 = wm * 32 + ma * 16 + (lane >> 2);
                int r2 = r1 + 8;
#pragma unroll
                for (int na = 0; na < 4; ++na) {
                    int lc = wn * 32 + na * 8 + (lane & 3) * 2;
                    int cg = nh * 128 + lc;
                    sV[r1 * 132 + lc]     = acc[ma][na][0] + sB[512 + cg];
                    sV[r1 * 132 + lc + 1] = acc[ma][na][1] + sB[512 + cg + 1];
                    sV[r2 * 132 + lc]     = acc[ma][na][2] + sB[512 + cg];
                    sV[r2 * 132 + lc + 1] = acc[ma][na][3] + sB[512 + cg + 1];
                }
            }
        }
        __syncthreads();
        // KV partials: 4 heads x 32d x 32e, each over 128 rows
        for (int o4 = t; o4 < 1024; o4 += NTHREADS) {
            int h = o4 >> 8, d = (o4 >> 3) & 31, e0 = (o4 & 7) * 4;
            float a0 = 0, a1 = 0, a2 = 0, a3 = 0;
#pragma unroll 4
            for (int r = 0; r < 128; ++r) {
                float kf = sKf[r * 132 + h * 32 + d];
                float4 vv = *(const float4*)&sV[r * 132 + h * 32 + e0];
                a0 += kf * vv.x; a1 += kf * vv.y; a2 += kf * vv.z; a3 += kf * vv.w;
            }
            int hg = nh * 4 + h;
            *(float4*)&g_KVp[tile][(hg * 32 + d) * 32 + e0] = make_float4(a0, a1, a2, a3);
        }
        if (t < 128) {
            float s = 0.0f;
#pragma unroll 4
            for (int r = 0; r < 128; ++r) s += sKf[r * 132 + t];
            g_Ksp[tile][nh * 128 + t] = s;
        }
        __syncthreads();
    }
}

// ---------------- K2: Z + msg + output projection ----------------
__global__ __launch_bounds__(NTHREADS, 1)
void k2_kernel(float* __restrict__ out) {
    extern __shared__ unsigned char sm[];
    const uint32_t sb = smem_u32(sm);
    const int t = threadIdx.x, lane = t & 31, wid = t >> 5;
    const int wm = wid & 3, wn = wid >> 2;
    const int tile = blockIdx.x, row0 = tile * 128, b = tile >> 6;

    float* sZ  = (float*)(sm + K2_Z);
    float* sKs = (float*)(sm + K2_KS);
    const uint32_t aH = sb + SM_AH, aL = sb + SM_AL;
    const uint32_t bH = sb + SM_BH, bL = sb + SM_BL;

    // load Qf tile into padded A smem
#pragma unroll
    for (int p = 0; p < 2; ++p) {
        const uint4* src = (const uint4*)(g_Qf + (size_t)tile * 131072 + p * 65536);
        unsigned char* dst = sm + (p ? SM_AL : SM_AH);
#pragma unroll
        for (int i = 0; i < 8; ++i) {
            int s = t + i * NTHREADS;
            int r = s >> 5, qq = s & 31;
            *(uint4*)(dst + r * 528 + qq * 16) = src[(size_t)r * 32 + qq];
        }
    }
    // load BD (all 8 heads) + Ksum
    {
        const uint4* src = (const uint4*)&g_BD[b][0][0][0][0];
        uint4* dst = (uint4*)(sm + K2_BD);
#pragma unroll
        for (int i = 0; i < 5; ++i) dst[t + i * NTHREADS] = src[t + i * NTHREADS];
        if (t < 64) ((float4*)sKs)[t] = ((const float4*)(g_Ksum + b * 256))[t];
    }
    __syncthreads();

    // Z = 1/(Qf . Ksum + eps)
#pragma unroll
    for (int i = 0; i < 2; ++i) {
        int task = t + i * NTHREADS;
        int r = task >> 3, h = task & 7;
        float dot = 0.0f;
#pragma unroll
        for (int dp = 0; dp < 16; ++dp) {
            int c = h * 32 + dp * 2;
            uint32_t off = (uint32_t)(r * 264 + c) * 2;
            uint32_t hw = *(const uint32_t*)(sm + SM_AH + off);
            uint32_t lw = *(const uint32_t*)(sm + SM_AL + off);
            __nv_bfloat162 hv, lv;
            memcpy(&hv, &hw, 4); memcpy(&lv, &lw, 4);
            float x0 = __bfloat162float(hv.x) + __bfloat162float(lv.x);
            float x1 = __bfloat162float(hv.y) + __bfloat162float(lv.y);
            dot += x0 * sKs[c] + x1 * sKs[c + 1];
        }
        sZ[r * 8 + h] = 1.0f / (dot + 1e-6f);
    }
    __syncthreads();

    // msg per head: m128 x n32(e) x k32(d), then scale by Z and overwrite A
    for (int nh = 0; nh < 2; ++nh) {
        int head = nh * 4 + wn;
        float acc[2][4][4];
#pragma unroll
        for (int ma = 0; ma < 2; ++ma)
#pragma unroll
            for (int na = 0; na < 4; ++na)
#pragma unroll
                for (int i = 0; i < 4; ++i) acc[ma][na][i] = 0.0f;
        uint32_t bdH = sb + K2_BD + head * 5120;
        uint32_t bdL = bdH + 2560;
        mma_block(acc, aH, aL, wm * 32, head * 32,      bdH, bdL, 0, 0,  lane);
        mma_block(acc, aH, aL, wm * 32, head * 32 + 16, bdH, bdL, 0, 16, lane);
        __syncwarp();
#pragma unroll
        for (int ma = 0; ma < 2; ++ma) {
            int r1 = wm * 32 + ma * 16 + (lane >> 2);
            int r2 = r1 + 8;
            float z1 = sZ[r1 * 8 + head], z2 = sZ[r2 * 8 + head];
#pragma unroll
            for (int na = 0; na < 4; ++na) {
                int cg = head * 32 + na * 8 + (lane & 3) * 2;
                float x0 = acc[ma][na][0] * z1, x1 = acc[ma][na][1] * z1;
                float x2 = acc[ma][na][2] * z2, x3 = acc[ma][na][3] * z2;
                __nv_bfloat16 h0, l0, h1, l1, h2, l2, h3, l3;
                hilo(x0, h0, l0); hilo(x1, h1, l1);
                hilo(x2, h2, l2); hilo(x3, h3, l3);
                uint32_t o1 = (uint32_t)(r1 * 264 + cg) * 2;
                uint32_t o2 = (uint32_t)(r2 * 264 + cg) * 2;
                *(uint32_t*)(sm + SM_AH + o1) = pk(h0, h1);
                *(uint32_t*)(sm + SM_AL + o1) = pk(l0, l1);
                *(uint32_t*)(sm + SM_AH + o2) = pk(h2, h3);
                *(uint32_t*)(sm + SM_AL + o2) = pk(l2, l3);
            }
        }
    }
    __syncthreads();

    // out = msg @ Wm^T  (register-pipelined weight staging)
    for (int nh = 0; nh < 2; ++nh) {
        float acc[2][4][4];
#pragma unroll
        for (int ma = 0; ma < 2; ++ma)
#pragma unroll
            for (int na = 0; na < 4; ++na)
#pragma unroll
                for (int i = 0; i < 4; ++i) acc[ma][na][i] = 0.0f;
        run_wgemm(acc, sm, aH, aL, bH, bL, t, lane, wm, wn, 3, nh);
#pragma unroll
        for (int ma = 0; ma < 2; ++ma) {
            int r1 = wm * 32 + ma * 16 + (lane >> 2);
            int r2 = r1 + 8;
#pragma unroll
            for (int na = 0; na < 4; ++na) {
                int cg = nh * 128 + wn * 32 + na * 8 + (lane & 3) * 2;
                *(float2*)(out + (size_t)(row0 + r1) * 256 + cg) =
                    make_float2(acc[ma][na][0], acc[ma][na][1]);
                *(float2*)(out + (size_t)(row0 + r2) * 256 + cg) =
                    make_float2(acc[ma][na][2], acc[ma][na][3]);
            }
        }
    }
}

// ---------------------------------------------------------------------------
extern "C" void kernel_launch(void* const* d_in, const int* in_sizes, int n_in,
                              void* d_out, int out_size) {
    const float* q  = (const float*)d_in[0];
    const float* k  = (const float*)d_in[1];
    const float* v  = (const float*)d_in[2];
    const float* Wq = (const float*)d_in[3];
    const float* bq = (const float*)d_in[4];
    const float* Wk = (const float*)d_in[5];
    const float* bk = (const float*)d_in[6];
    const float* Wv = (const float*)d_in[7];
    const float* bv = (const float*)d_in[8];
    const float* Wm = (const float*)d_in[9];
    float* out = (float*)d_out;

    cudaFuncSetAttribute(k1_kernel, cudaFuncAttributeMaxDynamicSharedMemorySize, K1_SMEM);
    cudaFuncSetAttribute(k2_kernel, cudaFuncAttributeMaxDynamicSharedMemorySize, K2_SMEM);

    prep_w_kernel<<<128, 256>>>(Wq, Wk, Wv, Wm);
    k1_kernel<<<NT, NTHREADS, K1_SMEM>>>(q, k, v, bq, bk, bv);
    reduce_bd_kernel<<<256, 256>>>();
    k2_kernel<<<NT, NTHREADS, K2_SMEM>>>(out);
}

// round 8
// speedup vs baseline: 2.6305x; 1.1390x over previous
#include <cuda_runtime.h>
#include <cuda_bf16.h>
#include <cuda_fp16.h>
#include <math.h>
#include <stdint.h>
#include <string.h>

// LoFTR linear attention via ldmatrix + mma.sync (bf16 hi/lo split, base sm_103 ISA).
// B=8, L=8192, E=256, H=8, D=32. 512 tiles x 128 rows.
// Round 8: fp16 Kf/V + MMA-based KV reduction; 3 build_A; m64n32 tiles @ 256 thr.

#define Es 256
#define NT 512

// ---------------- device scratch ----------------
__device__ __nv_bfloat16 g_W[4][2][256][256];            // [mat][hi/lo][n][k]
__device__ unsigned char g_Qf[(size_t)NT * 131072];      // [tile][hi/lo][128][256] bf16
__device__ float g_KVp[NT][8192];                        // per-tile KV partials
__device__ float g_Ksp[NT][256];                         // per-tile Ksum partials
__device__ float g_Ksum[8 * 256];
__device__ __nv_bfloat16 g_BD[8][8][2][32][40];          // [b][h][hi/lo][e][d(pad 40)] = KV^T

// ---------------- helpers ----------------
__device__ __forceinline__ float fmap(float x) { return x > 0.0f ? x + 1.0f : expf(x); }

__device__ __forceinline__ void hilo(float x, __nv_bfloat16& h, __nv_bfloat16& l) {
    h = __float2bfloat16(x);
    l = __float2bfloat16(x - __bfloat162float(h));
}
__device__ __forceinline__ uint32_t pk(__nv_bfloat16 a, __nv_bfloat16 b) {
    __nv_bfloat162 v = __halves2bfloat162(a, b);
    uint32_t r; memcpy(&r, &v, 4); return r;
}
__device__ __forceinline__ uint32_t pkh(float a, float b) {
    __half2 v = __floats2half2_rn(a, b);
    uint32_t r; memcpy(&r, &v, 4); return r;
}
__device__ __forceinline__ uint32_t smem_u32(const void* p) {
    uint32_t a;
    asm("{ .reg .u64 t; cvta.to.shared.u64 t, %1; cvt.u32.u64 %0, t; }" : "=r"(a) : "l"(p));
    return a;
}
__device__ __forceinline__ void ldsm4(uint32_t& r0, uint32_t& r1, uint32_t& r2, uint32_t& r3,
                                      uint32_t a) {
    asm volatile("ldmatrix.sync.aligned.m8n8.x4.shared.b16 {%0,%1,%2,%3}, [%4];"
                 : "=r"(r0), "=r"(r1), "=r"(r2), "=r"(r3) : "r"(a));
}
__device__ __forceinline__ void ldsm4t(uint32_t& r0, uint32_t& r1, uint32_t& r2, uint32_t& r3,
                                       uint32_t a) {
    asm volatile("ldmatrix.sync.aligned.m8n8.x4.trans.shared.b16 {%0,%1,%2,%3}, [%4];"
                 : "=r"(r0), "=r"(r1), "=r"(r2), "=r"(r3) : "r"(a));
}
__device__ __forceinline__ void mma16816(float* d, const uint32_t* a, uint32_t b0, uint32_t b1) {
    asm volatile(
        "mma.sync.aligned.m16n8k16.row.col.f32.bf16.bf16.f32 "
        "{%0,%1,%2,%3},{%4,%5,%6,%7},{%8,%9},{%0,%1,%2,%3};"
        : "+f"(d[0]), "+f"(d[1]), "+f"(d[2]), "+f"(d[3])
        : "r"(a[0]), "r"(a[1]), "r"(a[2]), "r"(a[3]), "r"(b0), "r"(b1));
}
__device__ __forceinline__ void mma16816h(float* d, const uint32_t* a, uint32_t b0, uint32_t b1) {
    asm volatile(
        "mma.sync.aligned.m16n8k16.row.col.f32.f16.f16.f32 "
        "{%0,%1,%2,%3},{%4,%5,%6,%7},{%8,%9},{%0,%1,%2,%3};"
        : "+f"(d[0]), "+f"(d[1]), "+f"(d[2]), "+f"(d[3])
        : "r"(a[0]), "r"(a[1]), "r"(a[2]), "r"(a[3]), "r"(b0), "r"(b1));
}

// smem layout (bytes)
#define SM_AH 0               // A hi: 128 x 264 bf16 = 67584  (k1: V fp16 aliases here)
#define SM_AL 67584           // A lo
#define SM_BH 135168          // B chunk hi: 128 x 40 bf16 = 10240
#define SM_BL 145408          // B chunk lo
#define K1_KF 155648          // Kf fp16: 128 x 264 = 67584
#define K1_BIAS 223232        // bq|bk|bv: 3 x 256 fp32
#define K1_SMEM 226304
#define K2_BD 155648          // 8 heads x 2 x 32 x 40 bf16 = 40960
#define K2_Z  196608          // 128 x 8 fp32
#define K2_KS 200704          // 256 fp32
#define K2_SMEM 201728

// A stride 264 bf16; B stride 40 bf16. m64n32 warp tile, 3 split products.
__device__ __forceinline__ void mma_block64(float acc[4][4][4],
                                            uint32_t aH, uint32_t aL, int m0, int ka,
                                            uint32_t bH, uint32_t bL, int n0, int kb, int lane) {
    uint32_t Ah[4][4], Al[4][4], Bh[2][4], Bl[2][4];
    int ar = m0 + (lane & 15);
    int ac = ka + ((lane >> 4) << 3);
    uint32_t aoff = (uint32_t)(ar * 264 + ac) * 2;
#pragma unroll
    for (int ma = 0; ma < 4; ++ma) {
        ldsm4(Ah[ma][0], Ah[ma][1], Ah[ma][2], Ah[ma][3], aH + aoff + ma * 16 * 528);
        ldsm4(Al[ma][0], Al[ma][1], Al[ma][2], Al[ma][3], aL + aoff + ma * 16 * 528);
    }
    int br = n0 + (lane & 7) + ((lane >> 4) << 3);
    int bc = kb + (((lane >> 3) & 1) << 3);
    uint32_t boff = (uint32_t)(br * 40 + bc) * 2;
#pragma unroll
    for (int nb = 0; nb < 2; ++nb) {
        ldsm4(Bh[nb][0], Bh[nb][1], Bh[nb][2], Bh[nb][3], bH + boff + nb * 16 * 80);
        ldsm4(Bl[nb][0], Bl[nb][1], Bl[nb][2], Bl[nb][3], bL + boff + nb * 16 * 80);
    }
#pragma unroll
    for (int ma = 0; ma < 4; ++ma)
#pragma unroll
        for (int na = 0; na < 4; ++na) {
            uint32_t b0h = Bh[na >> 1][(na & 1) * 2], b1h = Bh[na >> 1][(na & 1) * 2 + 1];
            uint32_t b0l = Bl[na >> 1][(na & 1) * 2], b1l = Bl[na >> 1][(na & 1) * 2 + 1];
            mma16816(acc[ma][na], Ah[ma], b0h, b1h);
            mma16816(acc[ma][na], Ah[ma], b0l, b1l);
            mma16816(acc[ma][na], Al[ma], b0h, b1h);
        }
}

// m32n32 warp tile (used for the m-split V passes)
__device__ __forceinline__ void mma_block32(float acc[2][4][4],
                                            uint32_t aH, uint32_t aL, int m0, int ka,
                                            uint32_t bH, uint32_t bL, int n0, int kb, int lane) {
    uint32_t Ah[2][4], Al[2][4], Bh[2][4], Bl[2][4];
    int ar = m0 + (lane & 15);
    int ac = ka + ((lane >> 4) << 3);
    uint32_t aoff = (uint32_t)(ar * 264 + ac) * 2;
#pragma unroll
    for (int ma = 0; ma < 2; ++ma) {
        ldsm4(Ah[ma][0], Ah[ma][1], Ah[ma][2], Ah[ma][3], aH + aoff + ma * 16 * 528);
        ldsm4(Al[ma][0], Al[ma][1], Al[ma][2], Al[ma][3], aL + aoff + ma * 16 * 528);
    }
    int br = n0 + (lane & 7) + ((lane >> 4) << 3);
    int bc = kb + (((lane >> 3) & 1) << 3);
    uint32_t boff = (uint32_t)(br * 40 + bc) * 2;
#pragma unroll
    for (int nb = 0; nb < 2; ++nb) {
        ldsm4(Bh[nb][0], Bh[nb][1], Bh[nb][2], Bh[nb][3], bH + boff + nb * 16 * 80);
        ldsm4(Bl[nb][0], Bl[nb][1], Bl[nb][2], Bl[nb][3], bL + boff + nb * 16 * 80);
    }
#pragma unroll
    for (int ma = 0; ma < 2; ++ma)
#pragma unroll
        for (int na = 0; na < 4; ++na) {
            uint32_t b0h = Bh[na >> 1][(na & 1) * 2], b1h = Bh[na >> 1][(na & 1) * 2 + 1];
            uint32_t b0l = Bl[na >> 1][(na & 1) * 2], b1l = Bl[na >> 1][(na & 1) * 2 + 1];
            mma16816(acc[ma][na], Ah[ma], b0h, b1h);
            mma16816(acc[ma][na], Ah[ma], b0l, b1l);
            mma16816(acc[ma][na], Al[ma], b0h, b1h);
        }
}

__device__ __forceinline__ void build_A(unsigned char* sm, int t, int row0,
                                        const float* __restrict__ X) {
    __syncthreads();
#pragma unroll
    for (int i = 0; i < 32; ++i) {
        int idx = t + i * 256;
        int r = idx >> 6, c = (idx & 63) * 4;
        float4 xv = *(const float4*)(X + (size_t)(row0 + r) * Es + c);
        __nv_bfloat16 h0, l0, h1, l1, h2, l2, h3, l3;
        hilo(xv.x, h0, l0); hilo(xv.y, h1, l1);
        hilo(xv.z, h2, l2); hilo(xv.w, h3, l3);
        uint32_t off = (uint32_t)(r * 264 + c) * 2;
        *(uint2*)(sm + SM_AH + off) = make_uint2(pk(h0, h1), pk(h2, h3));
        *(uint2*)(sm + SM_AL + off) = make_uint2(pk(l0, l1), pk(l2, l3));
    }
    __syncthreads();
}

// ---- register-pipelined weight staging (256 threads: 4 uint4 each) ----
__device__ __forceinline__ void ldg_WB(uint4 r[4], int mat, int nh, int kc, int t) {
    const uint4* srcH = (const uint4*)&g_W[mat][0][nh * 128][kc * 32];
    const uint4* srcL = (const uint4*)&g_W[mat][1][nh * 128][kc * 32];
    int s0 = t, s1 = t + 256;
    r[0] = srcH[(size_t)(s0 >> 2) * 32 + (s0 & 3)];
    r[1] = srcH[(size_t)(s1 >> 2) * 32 + (s1 & 3)];
    r[2] = srcL[(size_t)(s0 >> 2) * 32 + (s0 & 3)];
    r[3] = srcL[(size_t)(s1 >> 2) * 32 + (s1 & 3)];
}
__device__ __forceinline__ void st_WB(unsigned char* sm, const uint4 r[4], int t) {
    int s0 = t, s1 = t + 256;
    *(uint4*)(sm + SM_BH + (s0 >> 2) * 80 + (s0 & 3) * 16) = r[0];
    *(uint4*)(sm + SM_BH + (s1 >> 2) * 80 + (s1 & 3) * 16) = r[1];
    *(uint4*)(sm + SM_BL + (s0 >> 2) * 80 + (s0 & 3) * 16) = r[2];
    *(uint4*)(sm + SM_BL + (s1 >> 2) * 80 + (s1 & 3) * 16) = r[3];
}

__device__ __forceinline__ void run_wgemm64(float acc[4][4][4], unsigned char* sm,
                                            uint32_t aH, uint32_t aL,
                                            uint32_t bHa, uint32_t bLa,
                                            int t, int lane, int m0, int n0,
                                            int mat, int nh) {
    uint4 wreg[4];
    ldg_WB(wreg, mat, nh, 0, t);
    for (int kc = 0; kc < 8; ++kc) {
        __syncthreads();
        st_WB(sm, wreg, t);
        __syncthreads();
        if (kc < 7) ldg_WB(wreg, mat, nh, kc + 1, t);
        mma_block64(acc, aH, aL, m0, kc * 32,      bHa, bLa, n0, 0,  lane);
        mma_block64(acc, aH, aL, m0, kc * 32 + 16, bHa, bLa, n0, 16, lane);
    }
}
__device__ __forceinline__ void run_wgemm32(float acc[2][4][4], unsigned char* sm,
                                            uint32_t aH, uint32_t aL,
                                            uint32_t bHa, uint32_t bLa,
                                            int t, int lane, int m0, int n0,
                                            int mat, int nh) {
    uint4 wreg[4];
    ldg_WB(wreg, mat, nh, 0, t);
    for (int kc = 0; kc < 8; ++kc) {
        __syncthreads();
        st_WB(sm, wreg, t);
        __syncthreads();
        if (kc < 7) ldg_WB(wreg, mat, nh, kc + 1, t);
        mma_block32(acc, aH, aL, m0, kc * 32,      bHa, bLa, n0, 0,  lane);
        mma_block32(acc, aH, aL, m0, kc * 32 + 16, bHa, bLa, n0, 16, lane);
    }
}

// ---------------- prep kernels ----------------
__global__ __launch_bounds__(256) void prep_w_kernel(const float* __restrict__ Wq,
                                                     const float* __restrict__ Wk,
                                                     const float* __restrict__ Wv,
                                                     const float* __restrict__ Wm) {
    int id = blockIdx.x * 256 + threadIdx.x;   // 32768
    int m = id >> 13, rem = id & 8191, n = rem >> 5, g = rem & 31;
    const float* W = (m == 0) ? Wq : (m == 1) ? Wk : (m == 2) ? Wv : Wm;
    float4 a = *(const float4*)(W + (size_t)n * 256 + g * 8);
    float4 c = *(const float4*)(W + (size_t)n * 256 + g * 8 + 4);
    float xs[8] = {a.x, a.y, a.z, a.w, c.x, c.y, c.z, c.w};
    __nv_bfloat16 h[8], l[8];
#pragma unroll
    for (int p = 0; p < 8; ++p) hilo(xs[p], h[p], l[p]);
    *(uint4*)&g_W[m][0][n][g * 8] =
        make_uint4(pk(h[0], h[1]), pk(h[2], h[3]), pk(h[4], h[5]), pk(h[6], h[7]));
    *(uint4*)&g_W[m][1][n][g * 8] =
        make_uint4(pk(l[0], l[1]), pk(l[2], l[3]), pk(l[4], l[5]), pk(l[6], l[7]));
}

__global__ __launch_bounds__(256) void reduce_bd_kernel() {
    int id = blockIdx.x * 256 + threadIdx.x;   // 65536
    int b = id >> 13, i = id & 8191;
    float s = 0.0f;
#pragma unroll 8
    for (int j = 0; j < 64; ++j) s += g_KVp[b * 64 + j][i];
    int h = i >> 10, d = (i >> 5) & 31, e = i & 31;
    __nv_bfloat16 hi, lo; hilo(s, hi, lo);
    g_BD[b][h][0][e][d] = hi;
    g_BD[b][h][1][e][d] = lo;
    if (id < 2048) {
        int bb = id >> 8, c = id & 255;
        float ks = 0.0f;
#pragma unroll 8
        for (int j = 0; j < 64; ++j) ks += g_Ksp[bb * 64 + j][c];
        g_Ksum[bb * 256 + c] = ks;
    }
}

// ---------------- K1: projections + KV via MMA ----------------
__global__ __launch_bounds__(256, 1)
void k1_kernel(const float* __restrict__ q, const float* __restrict__ kin,
               const float* __restrict__ vin,
               const float* __restrict__ bq, const float* __restrict__ bk,
               const float* __restrict__ bv) {
    extern __shared__ unsigned char sm[];
    const uint32_t sb = smem_u32(sm);
    const int t = threadIdx.x, lane = t & 31, wid = t >> 5;
    const int wm = wid & 1, wn = wid >> 1;
    const int tile = blockIdx.x, row0 = tile * 128;

    float* sB = (float*)(sm + K1_BIAS);
    if (t < 192) {
        const float* src = (t < 64) ? bq : (t < 128) ? bk : bv;
        ((float4*)sB)[t] = ((const float4*)src)[t & 63];
    }

    const uint32_t aH = sb + SM_AH, aL = sb + SM_AL;
    const uint32_t bH = sb + SM_BH, bL = sb + SM_BL;
    const uint32_t kfb = sb + K1_KF;   // Kf fp16, stride 264
    const uint32_t vfb = sb + SM_AH;   // V fp16, aliases A region, stride 264

    // ---- Phase Q ----
    build_A(sm, t, row0, q);
    for (int nh = 0; nh < 2; ++nh) {
        float acc[4][4][4];
#pragma unroll
        for (int ma = 0; ma < 4; ++ma)
#pragma unroll
            for (int na = 0; na < 4; ++na)
#pragma unroll
                for (int i = 0; i < 4; ++i) acc[ma][na][i] = 0.0f;
        run_wgemm64(acc, sm, aH, aL, bH, bL, t, lane, wm * 64, wn * 32, 0, nh);
        unsigned char* dH = g_Qf + (size_t)tile * 131072;
        unsigned char* dL = dH + 65536;
#pragma unroll
        for (int ma = 0; ma < 4; ++ma) {
            int r1 = wm * 64 + ma * 16 + (lane >> 2);
            int r2 = r1 + 8;
#pragma unroll
            for (int na = 0; na < 4; ++na) {
                int cg = nh * 128 + wn * 32 + na * 8 + (lane & 3) * 2;
                float x0 = fmap(acc[ma][na][0] + sB[cg]);
                float x1 = fmap(acc[ma][na][1] + sB[cg + 1]);
                float x2 = fmap(acc[ma][na][2] + sB[cg]);
                float x3 = fmap(acc[ma][na][3] + sB[cg + 1]);
                __nv_bfloat16 h0, l0, h1, l1, h2, l2, h3, l3;
                hilo(x0, h0, l0); hilo(x1, h1, l1);
                hilo(x2, h2, l2); hilo(x3, h3, l3);
                *(uint32_t*)(dH + (uint32_t)(r1 * 256 + cg) * 2) = pk(h0, h1);
                *(uint32_t*)(dL + (uint32_t)(r1 * 256 + cg) * 2) = pk(l0, l1);
                *(uint32_t*)(dH + (uint32_t)(r2 * 256 + cg) * 2) = pk(h2, h3);
                *(uint32_t*)(dL + (uint32_t)(r2 * 256 + cg) * 2) = pk(l2, l3);
            }
        }
    }

    // ---- Phase K: single build_A, Kf -> fp16 dedicated region ----
    build_A(sm, t, row0, kin);
    for (int nh = 0; nh < 2; ++nh) {
        float acc[4][4][4];
#pragma unroll
        for (int ma = 0; ma < 4; ++ma)
#pragma unroll
            for (int na = 0; na < 4; ++na)
#pragma unroll
                for (int i = 0; i < 4; ++i) acc[ma][na][i] = 0.0f;
        run_wgemm64(acc, sm, aH, aL, bH, bL, t, lane, wm * 64, wn * 32, 1, nh);
#pragma unroll
        for (int ma = 0; ma < 4; ++ma) {
            int r1 = wm * 64 + ma * 16 + (lane >> 2);
            int r2 = r1 + 8;
#pragma unroll
            for (int na = 0; na < 4; ++na) {
                int cg = nh * 128 + wn * 32 + na * 8 + (lane & 3) * 2;
                *(uint32_t*)(sm + K1_KF + (uint32_t)(r1 * 264 + cg) * 2) =
                    pkh(fmap(acc[ma][na][0] + sB[256 + cg]),
                        fmap(acc[ma][na][1] + sB[256 + cg + 1]));
                *(uint32_t*)(sm + K1_KF + (uint32_t)(r2 * 264 + cg) * 2) =
                    pkh(fmap(acc[ma][na][2] + sB[256 + cg]),
                        fmap(acc[ma][na][3] + sB[256 + cg + 1]));
            }
        }
    }

    // ---- Phase V: single build_A, m-split passes, V -> fp16 into A region ----
    build_A(sm, t, row0, vin);
    for (int mh = 0; mh < 2; ++mh) {
        const int m0 = mh * 64 + wm * 32;   // grid 2x4 of m32n32 within (m64, n128)
        float acc0[2][4][4], acc1[2][4][4];
#pragma unroll
        for (int ma = 0; ma < 2; ++ma)
#pragma unroll
            for (int na = 0; na < 4; ++na)
#pragma unroll
                for (int i = 0; i < 4; ++i) { acc0[ma][na][i] = 0.0f; acc1[ma][na][i] = 0.0f; }
        run_wgemm32(acc0, sm, aH, aL, bH, bL, t, lane, m0, wn * 32, 2, 0);
        run_wgemm32(acc1, sm, aH, aL, bH, bL, t, lane, m0, wn * 32, 2, 1);
        __syncthreads();   // all MMAs of this m-half done before overwriting its A rows
#pragma unroll
        for (int nh = 0; nh < 2; ++nh) {
            float (*acc)[4][4] = nh ? acc1 : acc0;
#pragma unroll
            for (int ma = 0; ma < 2; ++ma) {
                int r1 = m0 + ma * 16 + (lane >> 2);
                int r2 = r1 + 8;
#pragma unroll
                for (int na = 0; na < 4; ++na) {
                    int cg = nh * 128 + wn * 32 + na * 8 + (lane & 3) * 2;
                    *(uint32_t*)(sm + (uint32_t)(r1 * 264 + cg) * 2) =
                        pkh(acc[ma][na][0] + sB[512 + cg], acc[ma][na][1] + sB[512 + cg + 1]);
                    *(uint32_t*)(sm + (uint32_t)(r2 * 264 + cg) * 2) =
                        pkh(acc[ma][na][2] + sB[512 + cg], acc[ma][na][3] + sB[512 + cg + 1]);
                }
            }
        }
    }
    __syncthreads();

    // ---- KV via MMA: warp = head, m32(d) x n32(e) x k128(r), fp16 single product ----
    {
        const int head = wid;
        float acc[2][4][4];
#pragma unroll
        for (int ma = 0; ma < 2; ++ma)
#pragma unroll
            for (int na = 0; na < 4; ++na)
#pragma unroll
                for (int i = 0; i < 4; ++i) acc[ma][na][i] = 0.0f;
        for (int ks = 0; ks < 8; ++ks) {
            const int r0 = ks * 16;
            uint32_t At[2][4], Bt[2][4];
            // A = Kf^T fragments via ldsm.trans from row-major Kf
            int arow = r0 + ((lane >> 4) << 3) + (lane & 7);
            int acol = head * 32 + (((lane >> 3) & 1) << 3);
#pragma unroll
            for (int ma = 0; ma < 2; ++ma)
                ldsm4t(At[ma][0], At[ma][1], At[ma][2], At[ma][3],
                       kfb + (uint32_t)(arow * 264 + acol + ma * 16) * 2);
            // B = V^T fragments via ldsm.trans from row-major V
            int brow = r0 + (((lane >> 3) & 1) << 3) + (lane & 7);
            int bcol = head * 32 + ((lane >> 4) << 3);
#pragma unroll
            for (int nb = 0; nb < 2; ++nb)
                ldsm4t(Bt[nb][0], Bt[nb][1], Bt[nb][2], Bt[nb][3],
                       vfb + (uint32_t)(brow * 264 + bcol + nb * 16) * 2);
#pragma unroll
            for (int ma = 0; ma < 2; ++ma)
#pragma unroll
                for (int na = 0; na < 4; ++na)
                    mma16816h(acc[ma][na], At[ma],
                              Bt[na >> 1][(na & 1) * 2], Bt[na >> 1][(na & 1) * 2 + 1]);
        }
#pragma unroll
        for (int ma = 0; ma < 2; ++ma) {
            int d1 = ma * 16 + (lane >> 2), d2 = d1 + 8;
#pragma unroll
            for (int na = 0; na < 4; ++na) {
                int e = na * 8 + (lane & 3) * 2;
                *(float2*)&g_KVp[tile][(head * 32 + d1) * 32 + e] =
                    make_float2(acc[ma][na][0], acc[ma][na][1]);
                *(float2*)&g_KVp[tile][(head * 32 + d2) * 32 + e] =
                    make_float2(acc[ma][na][2], acc[ma][na][3]);
            }
        }
    }

    // ---- Ksum: column sums of fp16 Kf ----
    {
        float s = 0.0f;
#pragma unroll 8
        for (int r = 0; r < 128; ++r)
            s += __half2float(*(const __half*)(sm + K1_KF + (uint32_t)(r * 264 + t) * 2));
        g_Ksp[tile][t] = s;
    }
}

// ---------------- K2: Z + msg + output projection (round-6 config) ----------------
__global__ __launch_bounds__(256, 1)
void k2_kernel(float* __restrict__ out) {
    extern __shared__ unsigned char sm[];
    const uint32_t sb = smem_u32(sm);
    const int t = threadIdx.x, lane = t & 31, wid = t >> 5;
    const int wm = wid & 1, wn = wid >> 1;
    const int tile = blockIdx.x, row0 = tile * 128, b = tile >> 6;

    float* sZ  = (float*)(sm + K2_Z);
    float* sKs = (float*)(sm + K2_KS);
    const uint32_t aH = sb + SM_AH, aL = sb + SM_AL;
    const uint32_t bH = sb + SM_BH, bL = sb + SM_BL;

#pragma unroll
    for (int p = 0; p < 2; ++p) {
        const uint4* src = (const uint4*)(g_Qf + (size_t)tile * 131072 + p * 65536);
        unsigned char* dst = sm + (p ? SM_AL : SM_AH);
#pragma unroll
        for (int i = 0; i < 16; ++i) {
            int s = t + i * 256;
            int r = s >> 5, qq = s & 31;
            *(uint4*)(dst + r * 528 + qq * 16) = src[(size_t)r * 32 + qq];
        }
    }
    {
        const uint4* src = (const uint4*)&g_BD[b][0][0][0][0];
        uint4* dst = (uint4*)(sm + K2_BD);
#pragma unroll
        for (int i = 0; i < 10; ++i) dst[t + i * 256] = src[t + i * 256];
        if (t < 64) ((float4*)sKs)[t] = ((const float4*)(g_Ksum + b * 256))[t];
    }
    __syncthreads();

#pragma unroll
    for (int i = 0; i < 4; ++i) {
        int task = t + i * 256;
        int r = task >> 3, h = task & 7;
        float dot = 0.0f;
#pragma unroll
        for (int dp = 0; dp < 16; ++dp) {
            int c = h * 32 + dp * 2;
            uint32_t off = (uint32_t)(r * 264 + c) * 2;
            uint32_t hw = *(const uint32_t*)(sm + SM_AH + off);
            uint32_t lw = *(const uint32_t*)(sm + SM_AL + off);
            __nv_bfloat162 hv, lv;
            memcpy(&hv, &hw, 4); memcpy(&lv, &lw, 4);
            float x0 = __bfloat162float(hv.x) + __bfloat162float(lv.x);
            float x1 = __bfloat162float(hv.y) + __bfloat162float(lv.y);
            dot += x0 * sKs[c] + x1 * sKs[c + 1];
        }
        sZ[r * 8 + h] = 1.0f / (dot + 1e-6f);
    }
    __syncthreads();

    for (int nh = 0; nh < 2; ++nh) {
        int head = nh * 4 + wn;
        float acc[4][4][4];
#pragma unroll
        for (int ma = 0; ma < 4; ++ma)
#pragma unroll
            for (int na = 0; na < 4; ++na)
#pragma unroll
                for (int i = 0; i < 4; ++i) acc[ma][na][i] = 0.0f;
        uint32_t bdH = sb + K2_BD + head * 5120;
        uint32_t bdL = bdH + 2560;
        mma_block64(acc, aH, aL, wm * 64, head * 32,      bdH, bdL, 0, 0,  lane);
        mma_block64(acc, aH, aL, wm * 64, head * 32 + 16, bdH, bdL, 0, 16, lane);
        __syncwarp();
#pragma unroll
        for (int ma = 0; ma < 4; ++ma) {
            int r1 = wm * 64 + ma * 16 + (lane >> 2);
            int r2 = r1 + 8;
            float z1 = sZ[r1 * 8 + head], z2 = sZ[r2 * 8 + head];
#pragma unroll
            for (int na = 0; na < 4; ++na) {
                int cg = head * 32 + na * 8 + (lane & 3) * 2;
                float x0 = acc[ma][na][0] * z1, x1 = acc[ma][na][1] * z1;
                float x2 = acc[ma][na][2] * z2, x3 = acc[ma][na][3] * z2;
                __nv_bfloat16 h0, l0, h1, l1, h2, l2, h3, l3;
                hilo(x0, h0, l0); hilo(x1, h1, l1);
                hilo(x2, h2, l2); hilo(x3, h3, l3);
                uint32_t o1 = (uint32_t)(r1 * 264 + cg) * 2;
                uint32_t o2 = (uint32_t)(r2 * 264 + cg) * 2;
                *(uint32_t*)(sm + SM_AH + o1) = pk(h0, h1);
                *(uint32_t*)(sm + SM_AL + o1) = pk(l0, l1);
                *(uint32_t*)(sm + SM_AH + o2) = pk(h2, h3);
                *(uint32_t*)(sm + SM_AL + o2) = pk(l2, l3);
            }
        }
    }
    __syncthreads();

    for (int nh = 0; nh < 2; ++nh) {
        float acc[4][4][4];
#pragma unroll
        for (int ma = 0; ma < 4; ++ma)
#pragma unroll
            for (int na = 0; na < 4; ++na)
#pragma unroll
                for (int i = 0; i < 4; ++i) acc[ma][na][i] = 0.0f;
        run_wgemm64(acc, sm, aH, aL, bH, bL, t, lane, wm * 64, wn * 32, 3, nh);
#pragma unroll
        for (int ma = 0; ma < 4; ++ma) {
            int r1 = wm * 64 + ma * 16 + (lane >> 2);
            int r2 = r1 + 8;
#pragma unroll
            for (int na = 0; na < 4; ++na) {
                int cg = nh * 128 + wn * 32 + na * 8 + (lane & 3) * 2;
                *(float2*)(out + (size_t)(row0 + r1) * 256 + cg) =
                    make_float2(acc[ma][na][0], acc[ma][na][1]);
                *(float2*)(out + (size_t)(row0 + r2) * 256 + cg) =
                    make_float2(acc[ma][na][2], acc[ma][na][3]);
            }
        }
    }
}

// ---------------------------------------------------------------------------
extern "C" void kernel_launch(void* const* d_in, const int* in_sizes, int n_in,
                              void* d_out, int out_size) {
    const float* q  = (const float*)d_in[0];
    const float* k  = (const float*)d_in[1];
    const float* v  = (const float*)d_in[2];
    const float* Wq = (const float*)d_in[3];
    const float* bq = (const float*)d_in[4];
    const float* Wk = (const float*)d_in[5];
    const float* bk = (const float*)d_in[6];
    const float* Wv = (const float*)d_in[7];
    const float* bv = (const float*)d_in[8];
    const float* Wm = (const float*)d_in[9];
    float* out = (float*)d_out;

    cudaFuncSetAttribute(k1_kernel, cudaFuncAttributeMaxDynamicSharedMemorySize, K1_SMEM);
    cudaFuncSetAttribute(k2_kernel, cudaFuncAttributeMaxDynamicSharedMemorySize, K2_SMEM);

    prep_w_kernel<<<128, 256>>>(Wq, Wk, Wv, Wm);
    k1_kernel<<<NT, 256, K1_SMEM>>>(q, k, v, bq, bk, bv);
    reduce_bd_kernel<<<256, 256>>>();
    k2_kernel<<<NT, 256, K2_SMEM>>>(out);
}

// round 9
// speedup vs baseline: 2.8451x; 1.0816x over previous
#include <cuda_runtime.h>
#include <cuda_bf16.h>
#include <cuda_fp16.h>
#include <math.h>
#include <stdint.h>
#include <string.h>

// LoFTR linear attention via ldmatrix + mma.sync (bf16 hi/lo split, base sm_103 ISA).
// B=8, L=8192, E=256, H=8, D=32. 512 tiles x 128 rows.
// Round 9: fp16-single Qf/msg, 2-product msg/out GEMMs, cp.async staging in k2.

#define Es 256
#define NT 512

// ---------------- device scratch ----------------
__device__ __nv_bfloat16 g_W[4][2][256][256];            // [mat][hi/lo][n][k]; mat3 = fp16 bits
__device__ __half g_Qf[(size_t)NT * 32768];              // [tile][128][256] fp16
__device__ float g_KVp[NT][8192];                        // per-tile KV partials
__device__ float g_Ksp[NT][256];                         // per-tile Ksum partials
__device__ float g_Ksum[8 * 256];
__device__ __half g_BD[8][8][2][32][40];                 // [b][h][hi/lo][e][d(pad 40)] = KV^T

// ---------------- helpers ----------------
__device__ __forceinline__ float fmap(float x) { return x > 0.0f ? x + 1.0f : expf(x); }

__device__ __forceinline__ void hilo(float x, __nv_bfloat16& h, __nv_bfloat16& l) {
    h = __float2bfloat16(x);
    l = __float2bfloat16(x - __bfloat162float(h));
}
__device__ __forceinline__ uint32_t pk(__nv_bfloat16 a, __nv_bfloat16 b) {
    __nv_bfloat162 v = __halves2bfloat162(a, b);
    uint32_t r; memcpy(&r, &v, 4); return r;
}
__device__ __forceinline__ uint32_t pkh(float a, float b) {
    __half2 v = __floats2half2_rn(a, b);
    uint32_t r; memcpy(&r, &v, 4); return r;
}
__device__ __forceinline__ uint32_t smem_u32(const void* p) {
    uint32_t a;
    asm("{ .reg .u64 t; cvta.to.shared.u64 t, %1; cvt.u32.u64 %0, t; }" : "=r"(a) : "l"(p));
    return a;
}
__device__ __forceinline__ void ldsm4(uint32_t& r0, uint32_t& r1, uint32_t& r2, uint32_t& r3,
                                      uint32_t a) {
    asm volatile("ldmatrix.sync.aligned.m8n8.x4.shared.b16 {%0,%1,%2,%3}, [%4];"
                 : "=r"(r0), "=r"(r1), "=r"(r2), "=r"(r3) : "r"(a));
}
__device__ __forceinline__ void ldsm4t(uint32_t& r0, uint32_t& r1, uint32_t& r2, uint32_t& r3,
                                       uint32_t a) {
    asm volatile("ldmatrix.sync.aligned.m8n8.x4.trans.shared.b16 {%0,%1,%2,%3}, [%4];"
                 : "=r"(r0), "=r"(r1), "=r"(r2), "=r"(r3) : "r"(a));
}
__device__ __forceinline__ void mma16816(float* d, const uint32_t* a, uint32_t b0, uint32_t b1) {
    asm volatile(
        "mma.sync.aligned.m16n8k16.row.col.f32.bf16.bf16.f32 "
        "{%0,%1,%2,%3},{%4,%5,%6,%7},{%8,%9},{%0,%1,%2,%3};"
        : "+f"(d[0]), "+f"(d[1]), "+f"(d[2]), "+f"(d[3])
        : "r"(a[0]), "r"(a[1]), "r"(a[2]), "r"(a[3]), "r"(b0), "r"(b1));
}
__device__ __forceinline__ void mma16816h(float* d, const uint32_t* a, uint32_t b0, uint32_t b1) {
    asm volatile(
        "mma.sync.aligned.m16n8k16.row.col.f32.f16.f16.f32 "
        "{%0,%1,%2,%3},{%4,%5,%6,%7},{%8,%9},{%0,%1,%2,%3};"
        : "+f"(d[0]), "+f"(d[1]), "+f"(d[2]), "+f"(d[3])
        : "r"(a[0]), "r"(a[1]), "r"(a[2]), "r"(a[3]), "r"(b0), "r"(b1));
}
__device__ __forceinline__ void cp16(uint32_t dst, const void* src) {
    asm volatile("cp.async.ca.shared.global [%0], [%1], 16;" :: "r"(dst), "l"(src));
}

// ---------------- k1 smem layout (bytes) ----------------
#define SM_AH 0               // A hi: 128 x 264 bf16 = 67584  (k1: V fp16 aliases here)
#define SM_AL 67584           // A lo
#define SM_BH 135168          // B chunk hi: 128 x 40 bf16 = 10240
#define SM_BL 145408          // B chunk lo
#define K1_KF 155648          // Kf fp16: 128 x 264 = 67584
#define K1_BIAS 223232        // bq|bk|bv: 3 x 256 fp32
#define K1_SMEM 226304

// ---------------- k2 smem layout (bytes) ----------------
#define J_A  0                // fp16 Qf/msg: 128 x 264 = 67584
#define J_B0 67584            // staging buf0: hi 10240 + lo 10240
#define J_B1 88064            // staging buf1
#define J_BD 108544           // 8 heads x 2 x 32 x 40 fp16 = 40960
#define J_Z  149504           // 128 x 8 fp32
#define J_KS 153600           // 256 fp32
#define K2_SMEM 154624

// A stride 264 bf16; B stride 40 bf16. m64n32 warp tile, 3 split products (bf16).
__device__ __forceinline__ void mma_block64(float acc[4][4][4],
                                            uint32_t aH, uint32_t aL, int m0, int ka,
                                            uint32_t bH, uint32_t bL, int n0, int kb, int lane) {
    uint32_t Ah[4][4], Al[4][4], Bh[2][4], Bl[2][4];
    int ar = m0 + (lane & 15);
    int ac = ka + ((lane >> 4) << 3);
    uint32_t aoff = (uint32_t)(ar * 264 + ac) * 2;
#pragma unroll
    for (int ma = 0; ma < 4; ++ma) {
        ldsm4(Ah[ma][0], Ah[ma][1], Ah[ma][2], Ah[ma][3], aH + aoff + ma * 16 * 528);
        ldsm4(Al[ma][0], Al[ma][1], Al[ma][2], Al[ma][3], aL + aoff + ma * 16 * 528);
    }
    int br = n0 + (lane & 7) + ((lane >> 4) << 3);
    int bc = kb + (((lane >> 3) & 1) << 3);
    uint32_t boff = (uint32_t)(br * 40 + bc) * 2;
#pragma unroll
    for (int nb = 0; nb < 2; ++nb) {
        ldsm4(Bh[nb][0], Bh[nb][1], Bh[nb][2], Bh[nb][3], bH + boff + nb * 16 * 80);
        ldsm4(Bl[nb][0], Bl[nb][1], Bl[nb][2], Bl[nb][3], bL + boff + nb * 16 * 80);
    }
#pragma unroll
    for (int ma = 0; ma < 4; ++ma)
#pragma unroll
        for (int na = 0; na < 4; ++na) {
            uint32_t b0h = Bh[na >> 1][(na & 1) * 2], b1h = Bh[na >> 1][(na & 1) * 2 + 1];
            uint32_t b0l = Bl[na >> 1][(na & 1) * 2], b1l = Bl[na >> 1][(na & 1) * 2 + 1];
            mma16816(acc[ma][na], Ah[ma], b0h, b1h);
            mma16816(acc[ma][na], Ah[ma], b0l, b1l);
            mma16816(acc[ma][na], Al[ma], b0h, b1h);
        }
}

// m32n32 warp tile (k1 m-split V passes)
__device__ __forceinline__ void mma_block32(float acc[2][4][4],
                                            uint32_t aH, uint32_t aL, int m0, int ka,
                                            uint32_t bH, uint32_t bL, int n0, int kb, int lane) {
    uint32_t Ah[2][4], Al[2][4], Bh[2][4], Bl[2][4];
    int ar = m0 + (lane & 15);
    int ac = ka + ((lane >> 4) << 3);
    uint32_t aoff = (uint32_t)(ar * 264 + ac) * 2;
#pragma unroll
    for (int ma = 0; ma < 2; ++ma) {
        ldsm4(Ah[ma][0], Ah[ma][1], Ah[ma][2], Ah[ma][3], aH + aoff + ma * 16 * 528);
        ldsm4(Al[ma][0], Al[ma][1], Al[ma][2], Al[ma][3], aL + aoff + ma * 16 * 528);
    }
    int br = n0 + (lane & 7) + ((lane >> 4) << 3);
    int bc = kb + (((lane >> 3) & 1) << 3);
    uint32_t boff = (uint32_t)(br * 40 + bc) * 2;
#pragma unroll
    for (int nb = 0; nb < 2; ++nb) {
        ldsm4(Bh[nb][0], Bh[nb][1], Bh[nb][2], Bh[nb][3], bH + boff + nb * 16 * 80);
        ldsm4(Bl[nb][0], Bl[nb][1], Bl[nb][2], Bl[nb][3], bL + boff + nb * 16 * 80);
    }
#pragma unroll
    for (int ma = 0; ma < 2; ++ma)
#pragma unroll
        for (int na = 0; na < 4; ++na) {
            uint32_t b0h = Bh[na >> 1][(na & 1) * 2], b1h = Bh[na >> 1][(na & 1) * 2 + 1];
            uint32_t b0l = Bl[na >> 1][(na & 1) * 2], b1l = Bl[na >> 1][(na & 1) * 2 + 1];
            mma16816(acc[ma][na], Ah[ma], b0h, b1h);
            mma16816(acc[ma][na], Ah[ma], b0l, b1l);
            mma16816(acc[ma][na], Al[ma], b0h, b1h);
        }
}

// fp16: A single (stride 264), B hi/lo (stride 40), 2 products. m64n32.
__device__ __forceinline__ void mma_blockF64(float acc[4][4][4],
                                             uint32_t aF, int m0, int ka,
                                             uint32_t bH, uint32_t bL, int n0, int kb, int lane) {
    uint32_t Af[4][4], Bh[2][4], Bl[2][4];
    int ar = m0 + (lane & 15);
    int ac = ka + ((lane >> 4) << 3);
    uint32_t aoff = (uint32_t)(ar * 264 + ac) * 2;
#pragma unroll
    for (int ma = 0; ma < 4; ++ma)
        ldsm4(Af[ma][0], Af[ma][1], Af[ma][2], Af[ma][3], aF + aoff + ma * 16 * 528);
    int br = n0 + (lane & 7) + ((lane >> 4) << 3);
    int bc = kb + (((lane >> 3) & 1) << 3);
    uint32_t boff = (uint32_t)(br * 40 + bc) * 2;
#pragma unroll
    for (int nb = 0; nb < 2; ++nb) {
        ldsm4(Bh[nb][0], Bh[nb][1], Bh[nb][2], Bh[nb][3], bH + boff + nb * 16 * 80);
        ldsm4(Bl[nb][0], Bl[nb][1], Bl[nb][2], Bl[nb][3], bL + boff + nb * 16 * 80);
    }
#pragma unroll
    for (int ma = 0; ma < 4; ++ma)
#pragma unroll
        for (int na = 0; na < 4; ++na) {
            uint32_t b0h = Bh[na >> 1][(na & 1) * 2], b1h = Bh[na >> 1][(na & 1) * 2 + 1];
            uint32_t b0l = Bl[na >> 1][(na & 1) * 2], b1l = Bl[na >> 1][(na & 1) * 2 + 1];
            mma16816h(acc[ma][na], Af[ma], b0h, b1h);
            mma16816h(acc[ma][na], Af[ma], b0l, b1l);
        }
}

__device__ __forceinline__ void build_A(unsigned char* sm, int t, int row0,
                                        const float* __restrict__ X) {
    __syncthreads();
#pragma unroll
    for (int i = 0; i < 32; ++i) {
        int idx = t + i * 256;
        int r = idx >> 6, c = (idx & 63) * 4;
        float4 xv = *(const float4*)(X + (size_t)(row0 + r) * Es + c);
        __nv_bfloat16 h0, l0, h1, l1, h2, l2, h3, l3;
        hilo(xv.x, h0, l0); hilo(xv.y, h1, l1);
        hilo(xv.z, h2, l2); hilo(xv.w, h3, l3);
        uint32_t off = (uint32_t)(r * 264 + c) * 2;
        *(uint2*)(sm + SM_AH + off) = make_uint2(pk(h0, h1), pk(h2, h3));
        *(uint2*)(sm + SM_AL + off) = make_uint2(pk(l0, l1), pk(l2, l3));
    }
    __syncthreads();
}

// ---- k1 register-pipelined weight staging (256 threads: 4 uint4 each) ----
__device__ __forceinline__ void ldg_WB(uint4 r[4], int mat, int nh, int kc, int t) {
    const uint4* srcH = (const uint4*)&g_W[mat][0][nh * 128][kc * 32];
    const uint4* srcL = (const uint4*)&g_W[mat][1][nh * 128][kc * 32];
    int s0 = t, s1 = t + 256;
    r[0] = srcH[(size_t)(s0 >> 2) * 32 + (s0 & 3)];
    r[1] = srcH[(size_t)(s1 >> 2) * 32 + (s1 & 3)];
    r[2] = srcL[(size_t)(s0 >> 2) * 32 + (s0 & 3)];
    r[3] = srcL[(size_t)(s1 >> 2) * 32 + (s1 & 3)];
}
__device__ __forceinline__ void st_WB(unsigned char* sm, const uint4 r[4], int t) {
    int s0 = t, s1 = t + 256;
    *(uint4*)(sm + SM_BH + (s0 >> 2) * 80 + (s0 & 3) * 16) = r[0];
    *(uint4*)(sm + SM_BH + (s1 >> 2) * 80 + (s1 & 3) * 16) = r[1];
    *(uint4*)(sm + SM_BL + (s0 >> 2) * 80 + (s0 & 3) * 16) = r[2];
    *(uint4*)(sm + SM_BL + (s1 >> 2) * 80 + (s1 & 3) * 16) = r[3];
}

__device__ __forceinline__ void run_wgemm64(float acc[4][4][4], unsigned char* sm,
                                            uint32_t aH, uint32_t aL,
                                            uint32_t bHa, uint32_t bLa,
                                            int t, int lane, int m0, int n0,
                                            int mat, int nh) {
    uint4 wreg[4];
    ldg_WB(wreg, mat, nh, 0, t);
    for (int kc = 0; kc < 8; ++kc) {
        __syncthreads();
        st_WB(sm, wreg, t);
        __syncthreads();
        if (kc < 7) ldg_WB(wreg, mat, nh, kc + 1, t);
        mma_block64(acc, aH, aL, m0, kc * 32,      bHa, bLa, n0, 0,  lane);
        mma_block64(acc, aH, aL, m0, kc * 32 + 16, bHa, bLa, n0, 16, lane);
    }
}
__device__ __forceinline__ void run_wgemm32(float acc[2][4][4], unsigned char* sm,
                                            uint32_t aH, uint32_t aL,
                                            uint32_t bHa, uint32_t bLa,
                                            int t, int lane, int m0, int n0,
                                            int mat, int nh) {
    uint4 wreg[4];
    ldg_WB(wreg, mat, nh, 0, t);
    for (int kc = 0; kc < 8; ++kc) {
        __syncthreads();
        st_WB(sm, wreg, t);
        __syncthreads();
        if (kc < 7) ldg_WB(wreg, mat, nh, kc + 1, t);
        mma_block32(acc, aH, aL, m0, kc * 32,      bHa, bLa, n0, 0,  lane);
        mma_block32(acc, aH, aL, m0, kc * 32 + 16, bHa, bLa, n0, 16, lane);
    }
}

// ---------------- prep kernels ----------------
__global__ __launch_bounds__(256) void prep_w_kernel(const float* __restrict__ Wq,
                                                     const float* __restrict__ Wk,
                                                     const float* __restrict__ Wv,
                                                     const float* __restrict__ Wm) {
    int id = blockIdx.x * 256 + threadIdx.x;   // 32768
    int m = id >> 13, rem = id & 8191, n = rem >> 5, g = rem & 31;
    const float* W = (m == 0) ? Wq : (m == 1) ? Wk : (m == 2) ? Wv : Wm;
    float4 a = *(const float4*)(W + (size_t)n * 256 + g * 8);
    float4 c = *(const float4*)(W + (size_t)n * 256 + g * 8 + 4);
    float xs[8] = {a.x, a.y, a.z, a.w, c.x, c.y, c.z, c.w};
    uint32_t H[4], L[4];
    if (m < 3) {
        __nv_bfloat16 h[8], l[8];
#pragma unroll
        for (int p = 0; p < 8; ++p) hilo(xs[p], h[p], l[p]);
#pragma unroll
        for (int p = 0; p < 4; ++p) { H[p] = pk(h[2*p], h[2*p+1]); L[p] = pk(l[2*p], l[2*p+1]); }
    } else {
        // Wm as fp16 hi/lo bits (consumed by k2's fp16 out-projection)
        float hh[8], ll[8];
#pragma unroll
        for (int p = 0; p < 8; ++p) {
            __half hv = __float2half_rn(xs[p]);
            hh[p] = __half2float(hv);
            ll[p] = xs[p] - hh[p];
        }
#pragma unroll
        for (int p = 0; p < 4; ++p) { H[p] = pkh(hh[2*p], hh[2*p+1]); L[p] = pkh(ll[2*p], ll[2*p+1]); }
    }
    *(uint4*)&g_W[m][0][n][g * 8] = make_uint4(H[0], H[1], H[2], H[3]);
    *(uint4*)&g_W[m][1][n][g * 8] = make_uint4(L[0], L[1], L[2], L[3]);
}

__global__ __launch_bounds__(256) void reduce_bd_kernel() {
    int id = blockIdx.x * 256 + threadIdx.x;   // 65536
    int b = id >> 13, i = id & 8191;
    float s = 0.0f;
#pragma unroll 8
    for (int j = 0; j < 64; ++j) s += g_KVp[b * 64 + j][i];
    int h = i >> 10, d = (i >> 5) & 31, e = i & 31;
    __half hi = __float2half_rn(s);
    __half lo = __float2half_rn(s - __half2float(hi));
    g_BD[b][h][0][e][d] = hi;
    g_BD[b][h][1][e][d] = lo;
    if (id < 2048) {
        int bb = id >> 8, c = id & 255;
        float ks = 0.0f;
#pragma unroll 8
        for (int j = 0; j < 64; ++j) ks += g_Ksp[bb * 64 + j][c];
        g_Ksum[bb * 256 + c] = ks;
    }
}

// ---------------- K1: projections + KV via MMA ----------------
__global__ __launch_bounds__(256, 1)
void k1_kernel(const float* __restrict__ q, const float* __restrict__ kin,
               const float* __restrict__ vin,
               const float* __restrict__ bq, const float* __restrict__ bk,
               const float* __restrict__ bv) {
    extern __shared__ unsigned char sm[];
    const uint32_t sb = smem_u32(sm);
    const int t = threadIdx.x, lane = t & 31, wid = t >> 5;
    const int wm = wid & 1, wn = wid >> 1;
    const int tile = blockIdx.x, row0 = tile * 128;

    float* sB = (float*)(sm + K1_BIAS);
    if (t < 192) {
        const float* src = (t < 64) ? bq : (t < 128) ? bk : bv;
        ((float4*)sB)[t] = ((const float4*)src)[t & 63];
    }

    const uint32_t aH = sb + SM_AH, aL = sb + SM_AL;
    const uint32_t bH = sb + SM_BH, bL = sb + SM_BL;
    const uint32_t kfb = sb + K1_KF;   // Kf fp16, stride 264
    const uint32_t vfb = sb + SM_AH;   // V fp16, aliases A region, stride 264

    // ---- Phase Q ----
    build_A(sm, t, row0, q);
    for (int nh = 0; nh < 2; ++nh) {
        float acc[4][4][4];
#pragma unroll
        for (int ma = 0; ma < 4; ++ma)
#pragma unroll
            for (int na = 0; na < 4; ++na)
#pragma unroll
                for (int i = 0; i < 4; ++i) acc[ma][na][i] = 0.0f;
        run_wgemm64(acc, sm, aH, aL, bH, bL, t, lane, wm * 64, wn * 32, 0, nh);
        __half* dQ = g_Qf + (size_t)tile * 32768;
#pragma unroll
        for (int ma = 0; ma < 4; ++ma) {
            int r1 = wm * 64 + ma * 16 + (lane >> 2);
            int r2 = r1 + 8;
#pragma unroll
            for (int na = 0; na < 4; ++na) {
                int cg = nh * 128 + wn * 32 + na * 8 + (lane & 3) * 2;
                float x0 = fmap(acc[ma][na][0] + sB[cg]);
                float x1 = fmap(acc[ma][na][1] + sB[cg + 1]);
                float x2 = fmap(acc[ma][na][2] + sB[cg]);
                float x3 = fmap(acc[ma][na][3] + sB[cg + 1]);
                *(uint32_t*)(dQ + r1 * 256 + cg) = pkh(x0, x1);
                *(uint32_t*)(dQ + r2 * 256 + cg) = pkh(x2, x3);
            }
        }
    }

    // ---- Phase K: Kf -> fp16 dedicated region ----
    build_A(sm, t, row0, kin);
    for (int nh = 0; nh < 2; ++nh) {
        float acc[4][4][4];
#pragma unroll
        for (int ma = 0; ma < 4; ++ma)
#pragma unroll
            for (int na = 0; na < 4; ++na)
#pragma unroll
                for (int i = 0; i < 4; ++i) acc[ma][na][i] = 0.0f;
        run_wgemm64(acc, sm, aH, aL, bH, bL, t, lane, wm * 64, wn * 32, 1, nh);
#pragma unroll
        for (int ma = 0; ma < 4; ++ma) {
            int r1 = wm * 64 + ma * 16 + (lane >> 2);
            int r2 = r1 + 8;
#pragma unroll
            for (int na = 0; na < 4; ++na) {
                int cg = nh * 128 + wn * 32 + na * 8 + (lane & 3) * 2;
                *(uint32_t*)(sm + K1_KF + (uint32_t)(r1 * 264 + cg) * 2) =
                    pkh(fmap(acc[ma][na][0] + sB[256 + cg]),
                        fmap(acc[ma][na][1] + sB[256 + cg + 1]));
                *(uint32_t*)(sm + K1_KF + (uint32_t)(r2 * 264 + cg) * 2) =
                    pkh(fmap(acc[ma][na][2] + sB[256 + cg]),
                        fmap(acc[ma][na][3] + sB[256 + cg + 1]));
            }
        }
    }

    // ---- Phase V: m-split passes, V -> fp16 into A region ----
    build_A(sm, t, row0, vin);
    for (int mh = 0; mh < 2; ++mh) {
        const int m0 = mh * 64 + wm * 32;
        float acc0[2][4][4], acc1[2][4][4];
#pragma unroll
        for (int ma = 0; ma < 2; ++ma)
#pragma unroll
            for (int na = 0; na < 4; ++na)
#pragma unroll
                for (int i = 0; i < 4; ++i) { acc0[ma][na][i] = 0.0f; acc1[ma][na][i] = 0.0f; }
        run_wgemm32(acc0, sm, aH, aL, bH, bL, t, lane, m0, wn * 32, 2, 0);
        run_wgemm32(acc1, sm, aH, aL, bH, bL, t, lane, m0, wn * 32, 2, 1);
        __syncthreads();
#pragma unroll
        for (int nh = 0; nh < 2; ++nh) {
            float (*acc)[4][4] = nh ? acc1 : acc0;
#pragma unroll
            for (int ma = 0; ma < 2; ++ma) {
                int r1 = m0 + ma * 16 + (lane >> 2);
                int r2 = r1 + 8;
#pragma unroll
                for (int na = 0; na < 4; ++na) {
                    int cg = nh * 128 + wn * 32 + na * 8 + (lane & 3) * 2;
                    *(uint32_t*)(sm + (uint32_t)(r1 * 264 + cg) * 2) =
                        pkh(acc[ma][na][0] + sB[512 + cg], acc[ma][na][1] + sB[512 + cg + 1]);
                    *(uint32_t*)(sm + (uint32_t)(r2 * 264 + cg) * 2) =
                        pkh(acc[ma][na][2] + sB[512 + cg], acc[ma][na][3] + sB[512 + cg + 1]);
                }
            }
        }
    }
    __syncthreads();

    // ---- KV via MMA: warp = head, m32(d) x n32(e) x k128(r), fp16 single product ----
    {
        const int head = wid;
        float acc[2][4][4];
#pragma unroll
        for (int ma = 0; ma < 2; ++ma)
#pragma unroll
            for (int na = 0; na < 4; ++na)
#pragma unroll
                for (int i = 0; i < 4; ++i) acc[ma][na][i] = 0.0f;
        for (int ks = 0; ks < 8; ++ks) {
            const int r0 = ks * 16;
            uint32_t At[2][4], Bt[2][4];
            int arow = r0 + ((lane >> 4) << 3) + (lane & 7);
            int acol = head * 32 + (((lane >> 3) & 1) << 3);
#pragma unroll
            for (int ma = 0; ma < 2; ++ma)
                ldsm4t(At[ma][0], At[ma][1], At[ma][2], At[ma][3],
                       kfb + (uint32_t)(arow * 264 + acol + ma * 16) * 2);
            int brow = r0 + (((lane >> 3) & 1) << 3) + (lane & 7);
            int bcol = head * 32 + ((lane >> 4) << 3);
#pragma unroll
            for (int nb = 0; nb < 2; ++nb)
                ldsm4t(Bt[nb][0], Bt[nb][1], Bt[nb][2], Bt[nb][3],
                       vfb + (uint32_t)(brow * 264 + bcol + nb * 16) * 2);
#pragma unroll
            for (int ma = 0; ma < 2; ++ma)
#pragma unroll
                for (int na = 0; na < 4; ++na)
                    mma16816h(acc[ma][na], At[ma],
                              Bt[na >> 1][(na & 1) * 2], Bt[na >> 1][(na & 1) * 2 + 1]);
        }
#pragma unroll
        for (int ma = 0; ma < 2; ++ma) {
            int d1 = ma * 16 + (lane >> 2), d2 = d1 + 8;
#pragma unroll
            for (int na = 0; na < 4; ++na) {
                int e = na * 8 + (lane & 3) * 2;
                *(float2*)&g_KVp[tile][(head * 32 + d1) * 32 + e] =
                    make_float2(acc[ma][na][0], acc[ma][na][1]);
                *(float2*)&g_KVp[tile][(head * 32 + d2) * 32 + e] =
                    make_float2(acc[ma][na][2], acc[ma][na][3]);
            }
        }
    }

    // ---- Ksum: column sums of fp16 Kf ----
    {
        float s = 0.0f;
#pragma unroll 8
        for (int r = 0; r < 128; ++r)
            s += __half2float(*(const __half*)(sm + K1_KF + (uint32_t)(r * 264 + t) * 2));
        g_Ksp[tile][t] = s;
    }
}

// ---------------- K2: Z + msg + output projection (fp16 path) ----------------
__global__ __launch_bounds__(256, 1)
void k2_kernel(float* __restrict__ out) {
    extern __shared__ unsigned char sm[];
    const uint32_t sb = smem_u32(sm);
    const int t = threadIdx.x, lane = t & 31, wid = t >> 5;
    const int wm = wid & 1, wn = wid >> 1;
    const int tile = blockIdx.x, row0 = tile * 128, b = tile >> 6;

    float* sZ  = (float*)(sm + J_Z);
    float* sKs = (float*)(sm + J_KS);
    const uint32_t aA = sb + J_A;

    // load Qf (fp16) into padded A smem, stride 264
    {
        const uint4* src = (const uint4*)(g_Qf + (size_t)tile * 32768);
#pragma unroll
        for (int i = 0; i < 16; ++i) {
            int s = t + i * 256;
            int r = s >> 5, qq = s & 31;
            *(uint4*)(sm + J_A + r * 528 + qq * 16) = src[(size_t)r * 32 + qq];
        }
    }
    // load BD (fp16 hi/lo, all heads) + Ksum
    {
        const uint4* src = (const uint4*)&g_BD[b][0][0][0][0];
        uint4* dst = (uint4*)(sm + J_BD);
#pragma unroll
        for (int i = 0; i < 10; ++i) dst[t + i * 256] = src[t + i * 256];
        if (t < 64) ((float4*)sKs)[t] = ((const float4*)(g_Ksum + b * 256))[t];
    }
    __syncthreads();

    // Z = 1/(Qf . Ksum + eps)
#pragma unroll
    for (int i = 0; i < 4; ++i) {
        int task = t + i * 256;
        int r = task >> 3, h = task & 7;
        float dot = 0.0f;
#pragma unroll
        for (int dp = 0; dp < 16; ++dp) {
            int c = h * 32 + dp * 2;
            uint32_t w = *(const uint32_t*)(sm + J_A + (uint32_t)(r * 264 + c) * 2);
            __half2 hv; memcpy(&hv, &w, 4);
            dot += __half2float(hv.x) * sKs[c] + __half2float(hv.y) * sKs[c + 1];
        }
        sZ[r * 8 + h] = 1.0f / (dot + 1e-6f);
    }
    __syncthreads();

    // msg per head: fp16 A x fp16 BD(hi/lo), scale by Z, overwrite A with fp16 msg
    for (int nh = 0; nh < 2; ++nh) {
        int head = nh * 4 + wn;
        float acc[4][4][4];
#pragma unroll
        for (int ma = 0; ma < 4; ++ma)
#pragma unroll
            for (int na = 0; na < 4; ++na)
#pragma unroll
                for (int i = 0; i < 4; ++i) acc[ma][na][i] = 0.0f;
        uint32_t bdH = sb + J_BD + head * 5120;
        uint32_t bdL = bdH + 2560;
        mma_blockF64(acc, aA, wm * 64, head * 32,      bdH, bdL, 0, 0,  lane);
        mma_blockF64(acc, aA, wm * 64, head * 32 + 16, bdH, bdL, 0, 16, lane);
        __syncwarp();
#pragma unroll
        for (int ma = 0; ma < 4; ++ma) {
            int r1 = wm * 64 + ma * 16 + (lane >> 2);
            int r2 = r1 + 8;
            float z1 = sZ[r1 * 8 + head], z2 = sZ[r2 * 8 + head];
#pragma unroll
            for (int na = 0; na < 4; ++na) {
                int cg = head * 32 + na * 8 + (lane & 3) * 2;
                *(uint32_t*)(sm + J_A + (uint32_t)(r1 * 264 + cg) * 2) =
                    pkh(acc[ma][na][0] * z1, acc[ma][na][1] * z1);
                *(uint32_t*)(sm + J_A + (uint32_t)(r2 * 264 + cg) * 2) =
                    pkh(acc[ma][na][2] * z2, acc[ma][na][3] * z2);
            }
        }
    }
    __syncthreads();

    // out = msg @ Wm^T (fp16 2-product), cp.async double-buffered weight staging
    for (int nh = 0; nh < 2; ++nh) {
        float acc[4][4][4];
#pragma unroll
        for (int ma = 0; ma < 4; ++ma)
#pragma unroll
            for (int na = 0; na < 4; ++na)
#pragma unroll
                for (int i = 0; i < 4; ++i) acc[ma][na][i] = 0.0f;

        // prologue: stage kc=0 into buf0
#pragma unroll
        for (int p = 0; p < 2; ++p)
#pragma unroll
            for (int i = 0; i < 2; ++i) {
                int s = t + i * 256, r = s >> 2, qq = s & 3;
                cp16(sb + J_B0 + p * 10240 + r * 80 + qq * 16,
                     (const char*)&g_W[3][p][nh * 128 + r][0] + qq * 16);
            }
        asm volatile("cp.async.commit_group;" ::: "memory");

        for (int kc = 0; kc < 8; ++kc) {
            uint32_t bHa = sb + ((kc & 1) ? J_B1 : J_B0);
            uint32_t bLa = bHa + 10240;
            if (kc < 7) {
                uint32_t nb = sb + (((kc + 1) & 1) ? J_B1 : J_B0);
#pragma unroll
                for (int p = 0; p < 2; ++p)
#pragma unroll
                    for (int i = 0; i < 2; ++i) {
                        int s = t + i * 256, r = s >> 2, qq = s & 3;
                        cp16(nb + p * 10240 + r * 80 + qq * 16,
                             (const char*)&g_W[3][p][nh * 128 + r][(kc + 1) * 32] + qq * 16);
                    }
                asm volatile("cp.async.commit_group;" ::: "memory");
                asm volatile("cp.async.wait_group 1;" ::: "memory");
            } else {
                asm volatile("cp.async.wait_group 0;" ::: "memory");
            }
            __syncthreads();
            mma_blockF64(acc, aA, wm * 64, kc * 32,      bHa, bLa, wn * 32, 0,  lane);
            mma_blockF64(acc, aA, wm * 64, kc * 32 + 16, bHa, bLa, wn * 32, 16, lane);
            __syncthreads();
        }
#pragma unroll
        for (int ma = 0; ma < 4; ++ma) {
            int r1 = wm * 64 + ma * 16 + (lane >> 2);
            int r2 = r1 + 8;
#pragma unroll
            for (int na = 0; na < 4; ++na) {
                int cg = nh * 128 + wn * 32 + na * 8 + (lane & 3) * 2;
                *(float2*)(out + (size_t)(row0 + r1) * 256 + cg) =
                    make_float2(acc[ma][na][0], acc[ma][na][1]);
                *(float2*)(out + (size_t)(row0 + r2) * 256 + cg) =
                    make_float2(acc[ma][na][2], acc[ma][na][3]);
            }
        }
    }
}

// ---------------------------------------------------------------------------
extern "C" void kernel_launch(void* const* d_in, const int* in_sizes, int n_in,
                              void* d_out, int out_size) {
    const float* q  = (const float*)d_in[0];
    const float* k  = (const float*)d_in[1];
    const float* v  = (const float*)d_in[2];
    const float* Wq = (const float*)d_in[3];
    const float* bq = (const float*)d_in[4];
    const float* Wk = (const float*)d_in[5];
    const float* bk = (const float*)d_in[6];
    const float* Wv = (const float*)d_in[7];
    const float* bv = (const float*)d_in[8];
    const float* Wm = (const float*)d_in[9];
    float* out = (float*)d_out;

    cudaFuncSetAttribute(k1_kernel, cudaFuncAttributeMaxDynamicSharedMemorySize, K1_SMEM);
    cudaFuncSetAttribute(k2_kernel, cudaFuncAttributeMaxDynamicSharedMemorySize, K2_SMEM);

    prep_w_kernel<<<128, 256>>>(Wq, Wk, Wv, Wm);
    k1_kernel<<<NT, 256, K1_SMEM>>>(q, k, v, bq, bk, bv);
    reduce_bd_kernel<<<256, 256>>>();
    k2_kernel<<<NT, 256, K2_SMEM>>>(out);
}

// round 10
// speedup vs baseline: 3.2796x; 1.1527x over previous
#include <cuda_runtime.h>
#include <cuda_fp16.h>
#include <math.h>
#include <stdint.h>
#include <string.h>

// LoFTR linear attention via ldmatrix + mma.sync, fp16 operands / fp32 accum.
// B=8, L=8192, E=256, H=8, D=32. 512 tiles x 128 rows.
// Round 10: fp16-single everywhere (1-product GEMMs), fp32 accumulate.

#define Es 256
#define NT 512

// ---------------- device scratch ----------------
__device__ __half g_W[4][256][256];                      // [mat][n][k] fp16
__device__ __half g_Qf[(size_t)NT * 32768];              // [tile][128][256] fp16
__device__ float g_KVp[NT][8192];                        // per-tile KV partials
__device__ float g_Ksp[NT][256];                         // per-tile Ksum partials
__device__ float g_Ksum[8 * 256];
__device__ __half g_BD[8][8][32][40];                    // [b][h][e][d(pad 40)] = KV^T fp16

// ---------------- helpers ----------------
__device__ __forceinline__ float fmap(float x) { return x > 0.0f ? x + 1.0f : expf(x); }

__device__ __forceinline__ uint32_t pkh(float a, float b) {
    __half2 v = __floats2half2_rn(a, b);
    uint32_t r; memcpy(&r, &v, 4); return r;
}
__device__ __forceinline__ uint32_t smem_u32(const void* p) {
    uint32_t a;
    asm("{ .reg .u64 t; cvta.to.shared.u64 t, %1; cvt.u32.u64 %0, t; }" : "=r"(a) : "l"(p));
    return a;
}
__device__ __forceinline__ void ldsm4(uint32_t& r0, uint32_t& r1, uint32_t& r2, uint32_t& r3,
                                      uint32_t a) {
    asm volatile("ldmatrix.sync.aligned.m8n8.x4.shared.b16 {%0,%1,%2,%3}, [%4];"
                 : "=r"(r0), "=r"(r1), "=r"(r2), "=r"(r3) : "r"(a));
}
__device__ __forceinline__ void ldsm4t(uint32_t& r0, uint32_t& r1, uint32_t& r2, uint32_t& r3,
                                       uint32_t a) {
    asm volatile("ldmatrix.sync.aligned.m8n8.x4.trans.shared.b16 {%0,%1,%2,%3}, [%4];"
                 : "=r"(r0), "=r"(r1), "=r"(r2), "=r"(r3) : "r"(a));
}
__device__ __forceinline__ void mma16816h(float* d, const uint32_t* a, uint32_t b0, uint32_t b1) {
    asm volatile(
        "mma.sync.aligned.m16n8k16.row.col.f32.f16.f16.f32 "
        "{%0,%1,%2,%3},{%4,%5,%6,%7},{%8,%9},{%0,%1,%2,%3};"
        : "+f"(d[0]), "+f"(d[1]), "+f"(d[2]), "+f"(d[3])
        : "r"(a[0]), "r"(a[1]), "r"(a[2]), "r"(a[3]), "r"(b0), "r"(b1));
}
__device__ __forceinline__ void cp16(uint32_t dst, const void* src) {
    asm volatile("cp.async.ca.shared.global [%0], [%1], 16;" :: "r"(dst), "l"(src));
}

// ---------------- k1 smem layout (bytes) ----------------
#define SM_A   0              // A fp16: 128 x 264 = 67584  (V fp16 aliases here later)
#define SM_B   67584          // B chunk fp16: 128 x 40 = 10240
#define K1_KF  77824          // Kf fp16: 128 x 264 = 67584
#define K1_BIAS 145408        // bq|bk|bv: 3 x 256 fp32
#define K1_SMEM 148480

// ---------------- k2 smem layout (bytes) ----------------
#define J_A  0                // fp16 Qf/msg: 128 x 264 = 67584
#define J_B0 67584            // staging buf0: 10240
#define J_B1 77824            // staging buf1: 10240
#define J_BD 88064            // 8 heads x 32 x 40 fp16 = 20480
#define J_Z  108544           // 128 x 8 fp32
#define J_KS 112640           // 256 fp32
#define K2_SMEM 113664

// A stride 264 fp16; B stride 40 fp16. m64n32 warp tile, single product.
__device__ __forceinline__ void mma_block64s(float acc[4][4][4],
                                             uint32_t aF, int m0, int ka,
                                             uint32_t bF, int n0, int kb, int lane) {
    uint32_t Af[4][4], Bf[2][4];
    int ar = m0 + (lane & 15);
    int ac = ka + ((lane >> 4) << 3);
    uint32_t aoff = (uint32_t)(ar * 264 + ac) * 2;
#pragma unroll
    for (int ma = 0; ma < 4; ++ma)
        ldsm4(Af[ma][0], Af[ma][1], Af[ma][2], Af[ma][3], aF + aoff + ma * 16 * 528);
    int br = n0 + (lane & 7) + ((lane >> 4) << 3);
    int bc = kb + (((lane >> 3) & 1) << 3);
    uint32_t boff = (uint32_t)(br * 40 + bc) * 2;
#pragma unroll
    for (int nb = 0; nb < 2; ++nb)
        ldsm4(Bf[nb][0], Bf[nb][1], Bf[nb][2], Bf[nb][3], bF + boff + nb * 16 * 80);
#pragma unroll
    for (int ma = 0; ma < 4; ++ma)
#pragma unroll
        for (int na = 0; na < 4; ++na)
            mma16816h(acc[ma][na], Af[ma],
                      Bf[na >> 1][(na & 1) * 2], Bf[na >> 1][(na & 1) * 2 + 1]);
}

// m32n32 warp tile (k1 m-split V passes), single product.
__device__ __forceinline__ void mma_block32s(float acc[2][4][4],
                                             uint32_t aF, int m0, int ka,
                                             uint32_t bF, int n0, int kb, int lane) {
    uint32_t Af[2][4], Bf[2][4];
    int ar = m0 + (lane & 15);
    int ac = ka + ((lane >> 4) << 3);
    uint32_t aoff = (uint32_t)(ar * 264 + ac) * 2;
#pragma unroll
    for (int ma = 0; ma < 2; ++ma)
        ldsm4(Af[ma][0], Af[ma][1], Af[ma][2], Af[ma][3], aF + aoff + ma * 16 * 528);
    int br = n0 + (lane & 7) + ((lane >> 4) << 3);
    int bc = kb + (((lane >> 3) & 1) << 3);
    uint32_t boff = (uint32_t)(br * 40 + bc) * 2;
#pragma unroll
    for (int nb = 0; nb < 2; ++nb)
        ldsm4(Bf[nb][0], Bf[nb][1], Bf[nb][2], Bf[nb][3], bF + boff + nb * 16 * 80);
#pragma unroll
    for (int ma = 0; ma < 2; ++ma)
#pragma unroll
        for (int na = 0; na < 4; ++na)
            mma16816h(acc[ma][na], Af[ma],
                      Bf[na >> 1][(na & 1) * 2], Bf[na >> 1][(na & 1) * 2 + 1]);
}

// fp32 input -> fp16 A tile (stride 264)
__device__ __forceinline__ void build_A(unsigned char* sm, int t, int row0,
                                        const float* __restrict__ X) {
    __syncthreads();
#pragma unroll
    for (int i = 0; i < 32; ++i) {
        int idx = t + i * 256;
        int r = idx >> 6, c = (idx & 63) * 4;
        float4 xv = *(const float4*)(X + (size_t)(row0 + r) * Es + c);
        *(uint2*)(sm + SM_A + (uint32_t)(r * 264 + c) * 2) =
            make_uint2(pkh(xv.x, xv.y), pkh(xv.z, xv.w));
    }
    __syncthreads();
}

// ---- k1 register-pipelined weight staging (single fp16, 2 uint4/thread) ----
__device__ __forceinline__ void ldg_WB(uint4 r[2], int mat, int nh, int kc, int t) {
    const uint4* src = (const uint4*)&g_W[mat][nh * 128][kc * 32];
    int s0 = t, s1 = t + 256;
    r[0] = src[(size_t)(s0 >> 2) * 32 + (s0 & 3)];
    r[1] = src[(size_t)(s1 >> 2) * 32 + (s1 & 3)];
}
__device__ __forceinline__ void st_WB(unsigned char* sm, const uint4 r[2], int t) {
    int s0 = t, s1 = t + 256;
    *(uint4*)(sm + SM_B + (s0 >> 2) * 80 + (s0 & 3) * 16) = r[0];
    *(uint4*)(sm + SM_B + (s1 >> 2) * 80 + (s1 & 3) * 16) = r[1];
}

__device__ __forceinline__ void run_wgemm64s(float acc[4][4][4], unsigned char* sm,
                                             uint32_t aF, uint32_t bF,
                                             int t, int lane, int m0, int n0,
                                             int mat, int nh) {
    uint4 wreg[2];
    ldg_WB(wreg, mat, nh, 0, t);
    for (int kc = 0; kc < 8; ++kc) {
        __syncthreads();
        st_WB(sm, wreg, t);
        __syncthreads();
        if (kc < 7) ldg_WB(wreg, mat, nh, kc + 1, t);
        mma_block64s(acc, aF, m0, kc * 32,      bF, n0, 0,  lane);
        mma_block64s(acc, aF, m0, kc * 32 + 16, bF, n0, 16, lane);
    }
}
__device__ __forceinline__ void run_wgemm32s(float acc[2][4][4], unsigned char* sm,
                                             uint32_t aF, uint32_t bF,
                                             int t, int lane, int m0, int n0,
                                             int mat, int nh) {
    uint4 wreg[2];
    ldg_WB(wreg, mat, nh, 0, t);
    for (int kc = 0; kc < 8; ++kc) {
        __syncthreads();
        st_WB(sm, wreg, t);
        __syncthreads();
        if (kc < 7) ldg_WB(wreg, mat, nh, kc + 1, t);
        mma_block32s(acc, aF, m0, kc * 32,      bF, n0, 0,  lane);
        mma_block32s(acc, aF, m0, kc * 32 + 16, bF, n0, 16, lane);
    }
}

// ---------------- prep kernels ----------------
__global__ __launch_bounds__(256) void prep_w_kernel(const float* __restrict__ Wq,
                                                     const float* __restrict__ Wk,
                                                     const float* __restrict__ Wv,
                                                     const float* __restrict__ Wm) {
    int id = blockIdx.x * 256 + threadIdx.x;   // 32768
    int m = id >> 13, rem = id & 8191, n = rem >> 5, g = rem & 31;
    const float* W = (m == 0) ? Wq : (m == 1) ? Wk : (m == 2) ? Wv : Wm;
    float4 a = *(const float4*)(W + (size_t)n * 256 + g * 8);
    float4 c = *(const float4*)(W + (size_t)n * 256 + g * 8 + 4);
    *(uint4*)&g_W[m][n][g * 8] =
        make_uint4(pkh(a.x, a.y), pkh(a.z, a.w), pkh(c.x, c.y), pkh(c.z, c.w));
}

__global__ __launch_bounds__(256) void reduce_bd_kernel() {
    int id = blockIdx.x * 256 + threadIdx.x;   // 65536
    int b = id >> 13, i = id & 8191;
    float s = 0.0f;
#pragma unroll 8
    for (int j = 0; j < 64; ++j) s += g_KVp[b * 64 + j][i];
    int h = i >> 10, d = (i >> 5) & 31, e = i & 31;
    g_BD[b][h][e][d] = __float2half_rn(s);
    if (id < 2048) {
        int bb = id >> 8, c = id & 255;
        float ks = 0.0f;
#pragma unroll 8
        for (int j = 0; j < 64; ++j) ks += g_Ksp[bb * 64 + j][c];
        g_Ksum[bb * 256 + c] = ks;
    }
}

// ---------------- K1: projections + KV via MMA ----------------
__global__ __launch_bounds__(256, 1)
void k1_kernel(const float* __restrict__ q, const float* __restrict__ kin,
               const float* __restrict__ vin,
               const float* __restrict__ bq, const float* __restrict__ bk,
               const float* __restrict__ bv) {
    extern __shared__ unsigned char sm[];
    const uint32_t sb = smem_u32(sm);
    const int t = threadIdx.x, lane = t & 31, wid = t >> 5;
    const int wm = wid & 1, wn = wid >> 1;
    const int tile = blockIdx.x, row0 = tile * 128;

    float* sB = (float*)(sm + K1_BIAS);
    if (t < 192) {
        const float* src = (t < 64) ? bq : (t < 128) ? bk : bv;
        ((float4*)sB)[t] = ((const float4*)src)[t & 63];
    }

    const uint32_t aF = sb + SM_A, bF = sb + SM_B;
    const uint32_t kfb = sb + K1_KF;   // Kf fp16, stride 264
    const uint32_t vfb = sb + SM_A;    // V fp16 aliases A region, stride 264

    // ---- Phase Q ----
    build_A(sm, t, row0, q);
    for (int nh = 0; nh < 2; ++nh) {
        float acc[4][4][4];
#pragma unroll
        for (int ma = 0; ma < 4; ++ma)
#pragma unroll
            for (int na = 0; na < 4; ++na)
#pragma unroll
                for (int i = 0; i < 4; ++i) acc[ma][na][i] = 0.0f;
        run_wgemm64s(acc, sm, aF, bF, t, lane, wm * 64, wn * 32, 0, nh);
        __half* dQ = g_Qf + (size_t)tile * 32768;
#pragma unroll
        for (int ma = 0; ma < 4; ++ma) {
            int r1 = wm * 64 + ma * 16 + (lane >> 2);
            int r2 = r1 + 8;
#pragma unroll
            for (int na = 0; na < 4; ++na) {
                int cg = nh * 128 + wn * 32 + na * 8 + (lane & 3) * 2;
                *(uint32_t*)(dQ + r1 * 256 + cg) =
                    pkh(fmap(acc[ma][na][0] + sB[cg]), fmap(acc[ma][na][1] + sB[cg + 1]));
                *(uint32_t*)(dQ + r2 * 256 + cg) =
                    pkh(fmap(acc[ma][na][2] + sB[cg]), fmap(acc[ma][na][3] + sB[cg + 1]));
            }
        }
    }

    // ---- Phase K: Kf -> fp16 dedicated region ----
    build_A(sm, t, row0, kin);
    for (int nh = 0; nh < 2; ++nh) {
        float acc[4][4][4];
#pragma unroll
        for (int ma = 0; ma < 4; ++ma)
#pragma unroll
            for (int na = 0; na < 4; ++na)
#pragma unroll
                for (int i = 0; i < 4; ++i) acc[ma][na][i] = 0.0f;
        run_wgemm64s(acc, sm, aF, bF, t, lane, wm * 64, wn * 32, 1, nh);
#pragma unroll
        for (int ma = 0; ma < 4; ++ma) {
            int r1 = wm * 64 + ma * 16 + (lane >> 2);
            int r2 = r1 + 8;
#pragma unroll
            for (int na = 0; na < 4; ++na) {
                int cg = nh * 128 + wn * 32 + na * 8 + (lane & 3) * 2;
                *(uint32_t*)(sm + K1_KF + (uint32_t)(r1 * 264 + cg) * 2) =
                    pkh(fmap(acc[ma][na][0] + sB[256 + cg]),
                        fmap(acc[ma][na][1] + sB[256 + cg + 1]));
                *(uint32_t*)(sm + K1_KF + (uint32_t)(r2 * 264 + cg) * 2) =
                    pkh(fmap(acc[ma][na][2] + sB[256 + cg]),
                        fmap(acc[ma][na][3] + sB[256 + cg + 1]));
            }
        }
    }

    // ---- Phase V: m-split passes, V -> fp16 into A region ----
    build_A(sm, t, row0, vin);
    for (int mh = 0; mh < 2; ++mh) {
        const int m0 = mh * 64 + wm * 32;
        float acc0[2][4][4], acc1[2][4][4];
#pragma unroll
        for (int ma = 0; ma < 2; ++ma)
#pragma unroll
            for (int na = 0; na < 4; ++na)
#pragma unroll
                for (int i = 0; i < 4; ++i) { acc0[ma][na][i] = 0.0f; acc1[ma][na][i] = 0.0f; }
        run_wgemm32s(acc0, sm, aF, bF, t, lane, m0, wn * 32, 2, 0);
        run_wgemm32s(acc1, sm, aF, bF, t, lane, m0, wn * 32, 2, 1);
        __syncthreads();   // all MMAs of this m-half done before overwriting its A rows
#pragma unroll
        for (int nh = 0; nh < 2; ++nh) {
            float (*acc)[4][4] = nh ? acc1 : acc0;
#pragma unroll
            for (int ma = 0; ma < 2; ++ma) {
                int r1 = m0 + ma * 16 + (lane >> 2);
                int r2 = r1 + 8;
#pragma unroll
                for (int na = 0; na < 4; ++na) {
                    int cg = nh * 128 + wn * 32 + na * 8 + (lane & 3) * 2;
                    *(uint32_t*)(sm + (uint32_t)(r1 * 264 + cg) * 2) =
                        pkh(acc[ma][na][0] + sB[512 + cg], acc[ma][na][1] + sB[512 + cg + 1]);
                    *(uint32_t*)(sm + (uint32_t)(r2 * 264 + cg) * 2) =
                        pkh(acc[ma][na][2] + sB[512 + cg], acc[ma][na][3] + sB[512 + cg + 1]);
                }
            }
        }
    }
    __syncthreads();

    // ---- KV via MMA: warp = head, m32(d) x n32(e) x k128(r), fp16 ----
    {
        const int head = wid;
        float acc[2][4][4];
#pragma unroll
        for (int ma = 0; ma < 2; ++ma)
#pragma unroll
            for (int na = 0; na < 4; ++na)
#pragma unroll
                for (int i = 0; i < 4; ++i) acc[ma][na][i] = 0.0f;
        for (int ks = 0; ks < 8; ++ks) {
            const int r0 = ks * 16;
            uint32_t At[2][4], Bt[2][4];
            int arow = r0 + ((lane >> 4) << 3) + (lane & 7);
            int acol = head * 32 + (((lane >> 3) & 1) << 3);
#pragma unroll
            for (int ma = 0; ma < 2; ++ma)
                ldsm4t(At[ma][0], At[ma][1], At[ma][2], At[ma][3],
                       kfb + (uint32_t)(arow * 264 + acol + ma * 16) * 2);
            int brow = r0 + (((lane >> 3) & 1) << 3) + (lane & 7);
            int bcol = head * 32 + ((lane >> 4) << 3);
#pragma unroll
            for (int nb = 0; nb < 2; ++nb)
                ldsm4t(Bt[nb][0], Bt[nb][1], Bt[nb][2], Bt[nb][3],
                       vfb + (uint32_t)(brow * 264 + bcol + nb * 16) * 2);
#pragma unroll
            for (int ma = 0; ma < 2; ++ma)
#pragma unroll
                for (int na = 0; na < 4; ++na)
                    mma16816h(acc[ma][na], At[ma],
                              Bt[na >> 1][(na & 1) * 2], Bt[na >> 1][(na & 1) * 2 + 1]);
        }
#pragma unroll
        for (int ma = 0; ma < 2; ++ma) {
            int d1 = ma * 16 + (lane >> 2), d2 = d1 + 8;
#pragma unroll
            for (int na = 0; na < 4; ++na) {
                int e = na * 8 + (lane & 3) * 2;
                *(float2*)&g_KVp[tile][(head * 32 + d1) * 32 + e] =
                    make_float2(acc[ma][na][0], acc[ma][na][1]);
                *(float2*)&g_KVp[tile][(head * 32 + d2) * 32 + e] =
                    make_float2(acc[ma][na][2], acc[ma][na][3]);
            }
        }
    }

    // ---- Ksum: column sums of fp16 Kf ----
    {
        float s = 0.0f;
#pragma unroll 8
        for (int r = 0; r < 128; ++r)
            s += __half2float(*(const __half*)(sm + K1_KF + (uint32_t)(r * 264 + t) * 2));
        g_Ksp[tile][t] = s;
    }
}

// ---------------- K2: Z + msg + output projection (all fp16 single) ----------------
__global__ __launch_bounds__(256, 1)
void k2_kernel(float* __restrict__ out) {
    extern __shared__ unsigned char sm[];
    const uint32_t sb = smem_u32(sm);
    const int t = threadIdx.x, lane = t & 31, wid = t >> 5;
    const int wm = wid & 1, wn = wid >> 1;
    const int tile = blockIdx.x, row0 = tile * 128, b = tile >> 6;

    float* sZ  = (float*)(sm + J_Z);
    float* sKs = (float*)(sm + J_KS);
    const uint32_t aA = sb + J_A;

    // load Qf (fp16) into padded A smem, stride 264
    {
        const uint4* src = (const uint4*)(g_Qf + (size_t)tile * 32768);
#pragma unroll
        for (int i = 0; i < 16; ++i) {
            int s = t + i * 256;
            int r = s >> 5, qq = s & 31;
            *(uint4*)(sm + J_A + r * 528 + qq * 16) = src[(size_t)r * 32 + qq];
        }
    }
    // load BD (fp16, all heads) + Ksum
    {
        const uint4* src = (const uint4*)&g_BD[b][0][0][0];
        uint4* dst = (uint4*)(sm + J_BD);
#pragma unroll
        for (int i = 0; i < 5; ++i) dst[t + i * 256] = src[t + i * 256];
        if (t < 64) ((float4*)sKs)[t] = ((const float4*)(g_Ksum + b * 256))[t];
    }
    __syncthreads();

    // Z = 1/(Qf . Ksum + eps)
#pragma unroll
    for (int i = 0; i < 4; ++i) {
        int task = t + i * 256;
        int r = task >> 3, h = task & 7;
        float dot = 0.0f;
#pragma unroll
        for (int dp = 0; dp < 16; ++dp) {
            int c = h * 32 + dp * 2;
            uint32_t w = *(const uint32_t*)(sm + J_A + (uint32_t)(r * 264 + c) * 2);
            __half2 hv; memcpy(&hv, &w, 4);
            dot += __half2float(hv.x) * sKs[c] + __half2float(hv.y) * sKs[c + 1];
        }
        sZ[r * 8 + h] = 1.0f / (dot + 1e-6f);
    }
    __syncthreads();

    // msg per head: fp16 A x fp16 BD (single product), scale by Z, overwrite A
    for (int nh = 0; nh < 2; ++nh) {
        int head = nh * 4 + wn;
        float acc[4][4][4];
#pragma unroll
        for (int ma = 0; ma < 4; ++ma)
#pragma unroll
            for (int na = 0; na < 4; ++na)
#pragma unroll
                for (int i = 0; i < 4; ++i) acc[ma][na][i] = 0.0f;
        uint32_t bdF = sb + J_BD + head * 2560;
        mma_block64s(acc, aA, wm * 64, head * 32,      bdF, 0, 0,  lane);
        mma_block64s(acc, aA, wm * 64, head * 32 + 16, bdF, 0, 16, lane);
        __syncwarp();
#pragma unroll
        for (int ma = 0; ma < 4; ++ma) {
            int r1 = wm * 64 + ma * 16 + (lane >> 2);
            int r2 = r1 + 8;
            float z1 = sZ[r1 * 8 + head], z2 = sZ[r2 * 8 + head];
#pragma unroll
            for (int na = 0; na < 4; ++na) {
                int cg = head * 32 + na * 8 + (lane & 3) * 2;
                *(uint32_t*)(sm + J_A + (uint32_t)(r1 * 264 + cg) * 2) =
                    pkh(acc[ma][na][0] * z1, acc[ma][na][1] * z1);
                *(uint32_t*)(sm + J_A + (uint32_t)(r2 * 264 + cg) * 2) =
                    pkh(acc[ma][na][2] * z2, acc[ma][na][3] * z2);
            }
        }
    }
    __syncthreads();

    // out = msg @ Wm^T (fp16 single product), cp.async double-buffered staging
    for (int nh = 0; nh < 2; ++nh) {
        float acc[4][4][4];
#pragma unroll
        for (int ma = 0; ma < 4; ++ma)
#pragma unroll
            for (int na = 0; na < 4; ++na)
#pragma unroll
                for (int i = 0; i < 4; ++i) acc[ma][na][i] = 0.0f;

        // prologue: stage kc=0 into buf0
#pragma unroll
        for (int i = 0; i < 2; ++i) {
            int s = t + i * 256, r = s >> 2, qq = s & 3;
            cp16(sb + J_B0 + r * 80 + qq * 16,
                 (const char*)&g_W[3][nh * 128 + r][0] + qq * 16);
        }
        asm volatile("cp.async.commit_group;" ::: "memory");

        for (int kc = 0; kc < 8; ++kc) {
            uint32_t bFa = sb + ((kc & 1) ? J_B1 : J_B0);
            if (kc < 7) {
                uint32_t nb = sb + (((kc + 1) & 1) ? J_B1 : J_B0);
#pragma unroll
                for (int i = 0; i < 2; ++i) {
                    int s = t + i * 256, r = s >> 2, qq = s & 3;
                    cp16(nb + r * 80 + qq * 16,
                         (const char*)&g_W[3][nh * 128 + r][(kc + 1) * 32] + qq * 16);
                }
                asm volatile("cp.async.commit_group;" ::: "memory");
                asm volatile("cp.async.wait_group 1;" ::: "memory");
            } else {
                asm volatile("cp.async.wait_group 0;" ::: "memory");
            }
            __syncthreads();
            mma_block64s(acc, aA, wm * 64, kc * 32,      bFa, wn * 32, 0,  lane);
            mma_block64s(acc, aA, wm * 64, kc * 32 + 16, bFa, wn * 32, 16, lane);
            __syncthreads();
        }
#pragma unroll
        for (int ma = 0; ma < 4; ++ma) {
            int r1 = wm * 64 + ma * 16 + (lane >> 2);
            int r2 = r1 + 8;
#pragma unroll
            for (int na = 0; na < 4; ++na) {
                int cg = nh * 128 + wn * 32 + na * 8 + (lane & 3) * 2;
                *(float2*)(out + (size_t)(row0 + r1) * 256 + cg) =
                    make_float2(acc[ma][na][0], acc[ma][na][1]);
                *(float2*)(out + (size_t)(row0 + r2) * 256 + cg) =
                    make_float2(acc[ma][na][2], acc[ma][na][3]);
            }
        }
    }
}

// ---------------------------------------------------------------------------
extern "C" void kernel_launch(void* const* d_in, const int* in_sizes, int n_in,
                              void* d_out, int out_size) {
    const float* q  = (const float*)d_in[0];
    const float* k  = (const float*)d_in[1];
    const float* v  = (const float*)d_in[2];
    const float* Wq = (const float*)d_in[3];
    const float* bq = (const float*)d_in[4];
    const float* Wk = (const float*)d_in[5];
    const float* bk = (const float*)d_in[6];
    const float* Wv = (const float*)d_in[7];
    const float* bv = (const float*)d_in[8];
    const float* Wm = (const float*)d_in[9];
    float* out = (float*)d_out;

    cudaFuncSetAttribute(k1_kernel, cudaFuncAttributeMaxDynamicSharedMemorySize, K1_SMEM);
    cudaFuncSetAttribute(k2_kernel, cudaFuncAttributeMaxDynamicSharedMemorySize, K2_SMEM);

    prep_w_kernel<<<128, 256>>>(Wq, Wk, Wv, Wm);
    k1_kernel<<<NT, 256, K1_SMEM>>>(q, k, v, bq, bk, bv);
    reduce_bd_kernel<<<256, 256>>>();
    k2_kernel<<<NT, 256, K2_SMEM>>>(out);
}

// round 12
// speedup vs baseline: 5.2851x; 1.6115x over previous
#include <cuda_runtime.h>
#include <cuda_fp16.h>
#include <math.h>
#include <stdint.h>
#include <string.h>

// LoFTR linear attention via ldmatrix + mma.sync, fp16 operands / fp32 accum.
// B=8, L=8192, E=256, H=8, D=32.
// Round 11: k1 -> 64-row tiles (1024 CTAs), cp.async weight staging, 2 CTAs/SM.

#define Es 256
#define NT1 1024            // k1 tiles (64 rows)
#define NT2 512             // k2 tiles (128 rows)

// ---------------- device scratch ----------------
__device__ __half g_W[4][256][256];                      // [mat][n][k] fp16
__device__ __half g_Qf[(size_t)NT2 * 32768];             // [128][256] per k2-tile, fp16
__device__ float g_KVp[NT1][8192];                       // per-k1-tile KV partials
__device__ float g_Ksp[NT1][256];                        // per-k1-tile Ksum partials
__device__ float g_Ksum[8 * 256];
__device__ __half g_BD[8][8][32][40];                    // [b][h][e][d(pad 40)] = KV^T fp16

// ---------------- helpers ----------------
__device__ __forceinline__ float fmap(float x) { return x > 0.0f ? x + 1.0f : expf(x); }

__device__ __forceinline__ uint32_t pkh(float a, float b) {
    __half2 v = __floats2half2_rn(a, b);
    uint32_t r; memcpy(&r, &v, 4); return r;
}
__device__ __forceinline__ uint32_t smem_u32(const void* p) {
    uint32_t a;
    asm("{ .reg .u64 t; cvta.to.shared.u64 t, %1; cvt.u32.u64 %0, t; }" : "=r"(a) : "l"(p));
    return a;
}
__device__ __forceinline__ void ldsm4(uint32_t& r0, uint32_t& r1, uint32_t& r2, uint32_t& r3,
                                      uint32_t a) {
    asm volatile("ldmatrix.sync.aligned.m8n8.x4.shared.b16 {%0,%1,%2,%3}, [%4];"
                 : "=r"(r0), "=r"(r1), "=r"(r2), "=r"(r3) : "r"(a));
}
__device__ __forceinline__ void ldsm4t(uint32_t& r0, uint32_t& r1, uint32_t& r2, uint32_t& r3,
                                       uint32_t a) {
    asm volatile("ldmatrix.sync.aligned.m8n8.x4.trans.shared.b16 {%0,%1,%2,%3}, [%4];"
                 : "=r"(r0), "=r"(r1), "=r"(r2), "=r"(r3) : "r"(a));
}
__device__ __forceinline__ void mma16816h(float* d, const uint32_t* a, uint32_t b0, uint32_t b1) {
    asm volatile(
        "mma.sync.aligned.m16n8k16.row.col.f32.f16.f16.f32 "
        "{%0,%1,%2,%3},{%4,%5,%6,%7},{%8,%9},{%0,%1,%2,%3};"
        : "+f"(d[0]), "+f"(d[1]), "+f"(d[2]), "+f"(d[3])
        : "r"(a[0]), "r"(a[1]), "r"(a[2]), "r"(a[3]), "r"(b0), "r"(b1));
}
__device__ __forceinline__ void cp16(uint32_t dst, const void* src) {
    asm volatile("cp.async.ca.shared.global [%0], [%1], 16;" :: "r"(dst), "l"(src));
}

// ---------------- k1 smem layout (bytes) ----------------
#define S1_A    0             // A fp16: 64 x 264 = 33792 (V fp16 aliases here later)
#define S1_B0   33792         // staging buf0: 256 x 40 fp16 = 20480
#define S1_B1   54272         // staging buf1: 20480
#define S1_KF   74752         // Kf fp16: 64 x 264 = 33792
#define S1_BIAS 108544        // bq|bk|bv: 3 x 256 fp32
#define K1_SMEM 111616

// ---------------- k2 smem layout (bytes) ----------------
#define J_A  0                // fp16 Qf/msg: 128 x 264 = 67584
#define J_B0 67584            // staging buf0: 10240
#define J_B1 77824            // staging buf1: 10240
#define J_BD 88064            // 8 heads x 32 x 40 fp16 = 20480
#define J_Z  108544           // 128 x 8 fp32
#define J_KS 112640           // 256 fp32
#define K2_SMEM 113664

// A stride 264 fp16; B stride 40 fp16. m64n32 warp tile, single product.
__device__ __forceinline__ void mma_block64s(float acc[4][4][4],
                                             uint32_t aF, int m0, int ka,
                                             uint32_t bF, int n0, int kb, int lane) {
    uint32_t Af[4][4], Bf[2][4];
    int ar = m0 + (lane & 15);
    int ac = ka + ((lane >> 4) << 3);
    uint32_t aoff = (uint32_t)(ar * 264 + ac) * 2;
#pragma unroll
    for (int ma = 0; ma < 4; ++ma)
        ldsm4(Af[ma][0], Af[ma][1], Af[ma][2], Af[ma][3], aF + aoff + ma * 16 * 528);
    int br = n0 + (lane & 7) + ((lane >> 4) << 3);
    int bc = kb + (((lane >> 3) & 1) << 3);
    uint32_t boff = (uint32_t)(br * 40 + bc) * 2;
#pragma unroll
    for (int nb = 0; nb < 2; ++nb)
        ldsm4(Bf[nb][0], Bf[nb][1], Bf[nb][2], Bf[nb][3], bF + boff + nb * 16 * 80);
#pragma unroll
    for (int ma = 0; ma < 4; ++ma)
#pragma unroll
        for (int na = 0; na < 4; ++na)
            mma16816h(acc[ma][na], Af[ma],
                      Bf[na >> 1][(na & 1) * 2], Bf[na >> 1][(na & 1) * 2 + 1]);
}

// ---------------- prep kernels ----------------
__global__ __launch_bounds__(256) void prep_w_kernel(const float* __restrict__ Wq,
                                                     const float* __restrict__ Wk,
                                                     const float* __restrict__ Wv,
                                                     const float* __restrict__ Wm) {
    int id = blockIdx.x * 256 + threadIdx.x;   // 32768
    int m = id >> 13, rem = id & 8191, n = rem >> 5, g = rem & 31;
    const float* W = (m == 0) ? Wq : (m == 1) ? Wk : (m == 2) ? Wv : Wm;
    float4 a = *(const float4*)(W + (size_t)n * 256 + g * 8);
    float4 c = *(const float4*)(W + (size_t)n * 256 + g * 8 + 4);
    *(uint4*)&g_W[m][n][g * 8] =
        make_uint4(pkh(a.x, a.y), pkh(a.z, a.w), pkh(c.x, c.y), pkh(c.z, c.w));
}

__global__ __launch_bounds__(256) void reduce_bd_kernel() {
    int id = blockIdx.x * 256 + threadIdx.x;   // 65536
    int b = id >> 13, i = id & 8191;
    float s = 0.0f;
#pragma unroll 8
    for (int j = 0; j < 128; ++j) s += g_KVp[b * 128 + j][i];
    int h = i >> 10, d = (i >> 5) & 31, e = i & 31;
    g_BD[b][h][e][d] = __float2half_rn(s);
    if (id < 2048) {
        int bb = id >> 8, c = id & 255;
        float ks = 0.0f;
#pragma unroll 8
        for (int j = 0; j < 128; ++j) ks += g_Ksp[bb * 128 + j][c];
        g_Ksum[bb * 256 + c] = ks;
    }
}

// ---- k1 cp.async weight staging: full n256 chunk (256 rows x 32 cols fp16) ----
__device__ __forceinline__ void stage_W1(uint32_t buf, int mat, int kc, int t) {
#pragma unroll
    for (int i = 0; i < 4; ++i) {
        int s = t + i * 256, r = s >> 2, qq = s & 3;
        cp16(buf + r * 80 + qq * 16, (const char*)&g_W[mat][r][kc * 32] + qq * 16);
    }
}

// Full 256-deep GEMM pass: m64 (all rows), n0 = warp's 32 cols, cp.async pipelined.
__device__ __forceinline__ void run_gemm1(float acc[4][4][4], uint32_t sb,
                                          uint32_t aF, int t, int lane, int n0, int mat) {
    stage_W1(sb + S1_B0, mat, 0, t);
    asm volatile("cp.async.commit_group;" ::: "memory");
    for (int kc = 0; kc < 8; ++kc) {
        uint32_t bFa = sb + ((kc & 1) ? S1_B1 : S1_B0);
        if (kc < 7) {
            stage_W1(sb + (((kc + 1) & 1) ? S1_B1 : S1_B0), mat, kc + 1, t);
            asm volatile("cp.async.commit_group;" ::: "memory");
            asm volatile("cp.async.wait_group 1;" ::: "memory");
        } else {
            asm volatile("cp.async.wait_group 0;" ::: "memory");
        }
        __syncthreads();
        mma_block64s(acc, aF, 0, kc * 32,      bFa, n0, 0,  lane);
        mma_block64s(acc, aF, 0, kc * 32 + 16, bFa, n0, 16, lane);
        __syncthreads();
    }
}

// fp32 input -> fp16 A tile (64 rows, stride 264)
__device__ __forceinline__ void build_A1(unsigned char* sm, int t, int row0,
                                         const float* __restrict__ X) {
    __syncthreads();
#pragma unroll
    for (int i = 0; i < 16; ++i) {
        int idx = t + i * 256;
        int r = idx >> 6, c = (idx & 63) * 4;
        float4 xv = *(const float4*)(X + (size_t)(row0 + r) * Es + c);
        *(uint2*)(sm + S1_A + (uint32_t)(r * 264 + c) * 2) =
            make_uint2(pkh(xv.x, xv.y), pkh(xv.z, xv.w));
    }
    __syncthreads();
}

// ---------------- K1: projections + KV via MMA (64-row tiles, 2 CTAs/SM) ----------------
__global__ __launch_bounds__(256, 2)
void k1_kernel(const float* __restrict__ q, const float* __restrict__ kin,
               const float* __restrict__ vin,
               const float* __restrict__ bq, const float* __restrict__ bk,
               const float* __restrict__ bv) {
    extern __shared__ unsigned char sm[];
    const uint32_t sb = smem_u32(sm);
    const int t = threadIdx.x, lane = t & 31, wid = t >> 5;
    const int n0 = wid * 32;
    const int tile = blockIdx.x, row0 = tile * 64;

    float* sB = (float*)(sm + S1_BIAS);
    if (t < 192) {
        const float* src = (t < 64) ? bq : (t < 128) ? bk : bv;
        ((float4*)sB)[t] = ((const float4*)src)[t & 63];
    }

    const uint32_t aF = sb + S1_A;
    const uint32_t kfb = sb + S1_KF;   // Kf fp16, stride 264
    const uint32_t vfb = sb + S1_A;    // V fp16 aliases A region

    // ---- Phase Q ----
    build_A1(sm, t, row0, q);
    {
        float acc[4][4][4];
#pragma unroll
        for (int ma = 0; ma < 4; ++ma)
#pragma unroll
            for (int na = 0; na < 4; ++na)
#pragma unroll
                for (int i = 0; i < 4; ++i) acc[ma][na][i] = 0.0f;
        run_gemm1(acc, sb, aF, t, lane, n0, 0);
        __half* dQ = g_Qf + (size_t)tile * 16384;
#pragma unroll
        for (int ma = 0; ma < 4; ++ma) {
            int r1 = ma * 16 + (lane >> 2);
            int r2 = r1 + 8;
#pragma unroll
            for (int na = 0; na < 4; ++na) {
                int cg = n0 + na * 8 + (lane & 3) * 2;
                *(uint32_t*)(dQ + r1 * 256 + cg) =
                    pkh(fmap(acc[ma][na][0] + sB[cg]), fmap(acc[ma][na][1] + sB[cg + 1]));
                *(uint32_t*)(dQ + r2 * 256 + cg) =
                    pkh(fmap(acc[ma][na][2] + sB[cg]), fmap(acc[ma][na][3] + sB[cg + 1]));
            }
        }
    }

    // ---- Phase K: Kf -> fp16 dedicated region ----
    build_A1(sm, t, row0, kin);
    {
        float acc[4][4][4];
#pragma unroll
        for (int ma = 0; ma < 4; ++ma)
#pragma unroll
            for (int na = 0; na < 4; ++na)
#pragma unroll
                for (int i = 0; i < 4; ++i) acc[ma][na][i] = 0.0f;
        run_gemm1(acc, sb, aF, t, lane, n0, 1);
#pragma unroll
        for (int ma = 0; ma < 4; ++ma) {
            int r1 = ma * 16 + (lane >> 2);
            int r2 = r1 + 8;
#pragma unroll
            for (int na = 0; na < 4; ++na) {
                int cg = n0 + na * 8 + (lane & 3) * 2;
                *(uint32_t*)(sm + S1_KF + (uint32_t)(r1 * 264 + cg) * 2) =
                    pkh(fmap(acc[ma][na][0] + sB[256 + cg]),
                        fmap(acc[ma][na][1] + sB[256 + cg + 1]));
                *(uint32_t*)(sm + S1_KF + (uint32_t)(r2 * 264 + cg) * 2) =
                    pkh(fmap(acc[ma][na][2] + sB[256 + cg]),
                        fmap(acc[ma][na][3] + sB[256 + cg + 1]));
            }
        }
    }

    // ---- Phase V: single pass, V -> fp16 into A region after MMAs ----
    build_A1(sm, t, row0, vin);
    {
        float acc[4][4][4];
#pragma unroll
        for (int ma = 0; ma < 4; ++ma)
#pragma unroll
            for (int na = 0; na < 4; ++na)
#pragma unroll
                for (int i = 0; i < 4; ++i) acc[ma][na][i] = 0.0f;
        run_gemm1(acc, sb, aF, t, lane, n0, 2);
        __syncthreads();   // all V MMAs complete before overwriting A with V
#pragma unroll
        for (int ma = 0; ma < 4; ++ma) {
            int r1 = ma * 16 + (lane >> 2);
            int r2 = r1 + 8;
#pragma unroll
            for (int na = 0; na < 4; ++na) {
                int cg = n0 + na * 8 + (lane & 3) * 2;
                *(uint32_t*)(sm + (uint32_t)(r1 * 264 + cg) * 2) =
                    pkh(acc[ma][na][0] + sB[512 + cg], acc[ma][na][1] + sB[512 + cg + 1]);
                *(uint32_t*)(sm + (uint32_t)(r2 * 264 + cg) * 2) =
                    pkh(acc[ma][na][2] + sB[512 + cg], acc[ma][na][3] + sB[512 + cg + 1]);
            }
        }
    }
    __syncthreads();

    // ---- KV via MMA: warp = head, m32(d) x n32(e) x k64(r), fp16 ----
    {
        const int head = wid;
        float acc[2][4][4];
#pragma unroll
        for (int ma = 0; ma < 2; ++ma)
#pragma unroll
            for (int na = 0; na < 4; ++na)
#pragma unroll
                for (int i = 0; i < 4; ++i) acc[ma][na][i] = 0.0f;
        for (int ks = 0; ks < 4; ++ks) {
            const int r0 = ks * 16;
            uint32_t At[2][4], Bt[2][4];
            int arow = r0 + ((lane >> 4) << 3) + (lane & 7);
            int acol = head * 32 + (((lane >> 3) & 1) << 3);
#pragma unroll
            for (int ma = 0; ma < 2; ++ma)
                ldsm4t(At[ma][0], At[ma][1], At[ma][2], At[ma][3],
                       kfb + (uint32_t)(arow * 264 + acol + ma * 16) * 2);
            int brow = r0 + (((lane >> 3) & 1) << 3) + (lane & 7);
            int bcol = head * 32 + ((lane >> 4) << 3);
#pragma unroll
            for (int nb = 0; nb < 2; ++nb)
                ldsm4t(Bt[nb][0], Bt[nb][1], Bt[nb][2], Bt[nb][3],
                       vfb + (uint32_t)(brow * 264 + bcol + nb * 16) * 2);
#pragma unroll
            for (int ma = 0; ma < 2; ++ma)
#pragma unroll
                for (int na = 0; na < 4; ++na)
                    mma16816h(acc[ma][na], At[ma],
                              Bt[na >> 1][(na & 1) * 2], Bt[na >> 1][(na & 1) * 2 + 1]);
        }
#pragma unroll
        for (int ma = 0; ma < 2; ++ma) {
            int d1 = ma * 16 + (lane >> 2), d2 = d1 + 8;
#pragma unroll
            for (int na = 0; na < 4; ++na) {
                int e = na * 8 + (lane & 3) * 2;
                *(float2*)&g_KVp[tile][(head * 32 + d1) * 32 + e] =
                    make_float2(acc[ma][na][0], acc[ma][na][1]);
                *(float2*)&g_KVp[tile][(head * 32 + d2) * 32 + e] =
                    make_float2(acc[ma][na][2], acc[ma][na][3]);
            }
        }
    }

    // ---- Ksum: column sums of fp16 Kf (64 rows) ----
    {
        float s = 0.0f;
#pragma unroll 8
        for (int r = 0; r < 64; ++r)
            s += __half2float(*(const __half*)(sm + S1_KF + (uint32_t)(r * 264 + t) * 2));
        g_Ksp[tile][t] = s;
    }
}

// ---------------- K2: Z + msg + output projection (unchanged, fp16 single) ----------------
__global__ __launch_bounds__(256, 1)
void k2_kernel(float* __restrict__ out) {
    extern __shared__ unsigned char sm[];
    const uint32_t sb = smem_u32(sm);
    const int t = threadIdx.x, lane = t & 31, wid = t >> 5;
    const int wm = wid & 1, wn = wid >> 1;
    const int tile = blockIdx.x, row0 = tile * 128, b = tile >> 6;

    float* sZ  = (float*)(sm + J_Z);
    float* sKs = (float*)(sm + J_KS);
    const uint32_t aA = sb + J_A;

    {
        const uint4* src = (const uint4*)(g_Qf + (size_t)tile * 32768);
#pragma unroll
        for (int i = 0; i < 16; ++i) {
            int s = t + i * 256;
            int r = s >> 5, qq = s & 31;
            *(uint4*)(sm + J_A + r * 528 + qq * 16) = src[(size_t)r * 32 + qq];
        }
    }
    {
        const uint4* src = (const uint4*)&g_BD[b][0][0][0];
        uint4* dst = (uint4*)(sm + J_BD);
#pragma unroll
        for (int i = 0; i < 5; ++i) dst[t + i * 256] = src[t + i * 256];
        if (t < 64) ((float4*)sKs)[t] = ((const float4*)(g_Ksum + b * 256))[t];
    }
    __syncthreads();

#pragma unroll
    for (int i = 0; i < 4; ++i) {
        int task = t + i * 256;
        int r = task >> 3, h = task & 7;
        float dot = 0.0f;
#pragma unroll
        for (int dp = 0; dp < 16; ++dp) {
            int c = h * 32 + dp * 2;
            uint32_t w = *(const uint32_t*)(sm + J_A + (uint32_t)(r * 264 + c) * 2);
            __half2 hv; memcpy(&hv, &w, 4);
            dot += __half2float(hv.x) * sKs[c] + __half2float(hv.y) * sKs[c + 1];
        }
        sZ[r * 8 + h] = 1.0f / (dot + 1e-6f);
    }
    __syncthreads();

    for (int nh = 0; nh < 2; ++nh) {
        int head = nh * 4 + wn;
        float acc[4][4][4];
#pragma unroll
        for (int ma = 0; ma < 4; ++ma)
#pragma unroll
            for (int na = 0; na < 4; ++na)
#pragma unroll
                for (int i = 0; i < 4; ++i) acc[ma][na][i] = 0.0f;
        uint32_t bdF = sb + J_BD + head * 2560;
        mma_block64s(acc, aA, wm * 64, head * 32,      bdF, 0, 0,  lane);
        mma_block64s(acc, aA, wm * 64, head * 32 + 16, bdF, 0, 16, lane);
        __syncwarp();
#pragma unroll
        for (int ma = 0; ma < 4; ++ma) {
            int r1 = wm * 64 + ma * 16 + (lane >> 2);
            int r2 = r1 + 8;
            float z1 = sZ[r1 * 8 + head], z2 = sZ[r2 * 8 + head];
#pragma unroll
            for (int na = 0; na < 4; ++na) {
                int cg = head * 32 + na * 8 + (lane & 3) * 2;
                *(uint32_t*)(sm + J_A + (uint32_t)(r1 * 264 + cg) * 2) =
                    pkh(acc[ma][na][0] * z1, acc[ma][na][1] * z1);
                *(uint32_t*)(sm + J_A + (uint32_t)(r2 * 264 + cg) * 2) =
                    pkh(acc[ma][na][2] * z2, acc[ma][na][3] * z2);
            }
        }
    }
    __syncthreads();

    for (int nh = 0; nh < 2; ++nh) {
        float acc[4][4][4];
#pragma unroll
        for (int ma = 0; ma < 4; ++ma)
#pragma unroll
            for (int na = 0; na < 4; ++na)
#pragma unroll
                for (int i = 0; i < 4; ++i) acc[ma][na][i] = 0.0f;

#pragma unroll
        for (int i = 0; i < 2; ++i) {
            int s = t + i * 256, r = s >> 2, qq = s & 3;
            cp16(sb + J_B0 + r * 80 + qq * 16,
                 (const char*)&g_W[3][nh * 128 + r][0] + qq * 16);
        }
        asm volatile("cp.async.commit_group;" ::: "memory");

        for (int kc = 0; kc < 8; ++kc) {
            uint32_t bFa = sb + ((kc & 1) ? J_B1 : J_B0);
            if (kc < 7) {
                uint32_t nb = sb + (((kc + 1) & 1) ? J_B1 : J_B0);
#pragma unroll
                for (int i = 0; i < 2; ++i) {
                    int s = t + i * 256, r = s >> 2, qq = s & 3;
                    cp16(nb + r * 80 + qq * 16,
                         (const char*)&g_W[3][nh * 128 + r][(kc + 1) * 32] + qq * 16);
                }
                asm volatile("cp.async.commit_group;" ::: "memory");
                asm volatile("cp.async.wait_group 1;" ::: "memory");
            } else {
                asm volatile("cp.async.wait_group 0;" ::: "memory");
            }
            __syncthreads();
            mma_block64s(acc, aA, wm * 64, kc * 32,      bFa, wn * 32, 0,  lane);
            mma_block64s(acc, aA, wm * 64, kc * 32 + 16, bFa, wn * 32, 16, lane);
            __syncthreads();
        }
#pragma unroll
        for (int ma = 0; ma < 4; ++ma) {
            int r1 = wm * 64 + ma * 16 + (lane >> 2);
            int r2 = r1 + 8;
#pragma unroll
            for (int na = 0; na < 4; ++na) {
                int cg = nh * 128 + wn * 32 + na * 8 + (lane & 3) * 2;
                *(float2*)(out + (size_t)(row0 + r1) * 256 + cg) =
                    make_float2(acc[ma][na][0], acc[ma][na][1]);
                *(float2*)(out + (size_t)(row0 + r2) * 256 + cg) =
                    make_float2(acc[ma][na][2], acc[ma][na][3]);
            }
        }
    }
}

// ---------------------------------------------------------------------------
extern "C" void kernel_launch(void* const* d_in, const int* in_sizes, int n_in,
                              void* d_out, int out_size) {
    const float* q  = (const float*)d_in[0];
    const float* k  = (const float*)d_in[1];
    const float* v  = (const float*)d_in[2];
    const float* Wq = (const float*)d_in[3];
    const float* bq = (const float*)d_in[4];
    const float* Wk = (const float*)d_in[5];
    const float* bk = (const float*)d_in[6];
    const float* Wv = (const float*)d_in[7];
    const float* bv = (const float*)d_in[8];
    const float* Wm = (const float*)d_in[9];
    float* out = (float*)d_out;

    cudaFuncSetAttribute(k1_kernel, cudaFuncAttributeMaxDynamicSharedMemorySize, K1_SMEM);
    cudaFuncSetAttribute(k2_kernel, cudaFuncAttributeMaxDynamicSharedMemorySize, K2_SMEM);

    prep_w_kernel<<<128, 256>>>(Wq, Wk, Wv, Wm);
    k1_kernel<<<NT1, 256, K1_SMEM>>>(q, k, v, bq, bk, bv);
    reduce_bd_kernel<<<256, 256>>>();
    k2_kernel<<<NT2, 256, K2_SMEM>>>(out);
}

// round 13
// speedup vs baseline: 5.3196x; 1.0065x over previous
#include <cuda_runtime.h>
#include <cuda_fp16.h>
#include <math.h>
#include <stdint.h>
#include <string.h>

// LoFTR linear attention via ldmatrix + mma.sync, fp16 operands / fp32 accum.
// B=8, L=8192, E=256, H=8, D=32.
// Round 13: k2 -> 64-row tiles (1024 CTAs), 2 CTAs/SM (mirror of k1's round-11 win).

#define Es 256
#define NT1 1024            // k1 tiles (64 rows)
#define NT2 1024            // k2 tiles (64 rows)

// ---------------- device scratch ----------------
__device__ __half g_W[4][256][256];                      // [mat][n][k] fp16
__device__ __half g_Qf[(size_t)NT1 * 16384];             // [tile(64 rows)][64][256] fp16
__device__ float g_KVp[NT1][8192];                       // per-k1-tile KV partials
__device__ float g_Ksp[NT1][256];                        // per-k1-tile Ksum partials
__device__ float g_Ksum[8 * 256];
__device__ __half g_BD[8][8][32][40];                    // [b][h][e][d(pad 40)] = KV^T fp16

// ---------------- helpers ----------------
__device__ __forceinline__ float fmap(float x) { return x > 0.0f ? x + 1.0f : expf(x); }

__device__ __forceinline__ uint32_t pkh(float a, float b) {
    __half2 v = __floats2half2_rn(a, b);
    uint32_t r; memcpy(&r, &v, 4); return r;
}
__device__ __forceinline__ uint32_t smem_u32(const void* p) {
    uint32_t a;
    asm("{ .reg .u64 t; cvta.to.shared.u64 t, %1; cvt.u32.u64 %0, t; }" : "=r"(a) : "l"(p));
    return a;
}
__device__ __forceinline__ void ldsm4(uint32_t& r0, uint32_t& r1, uint32_t& r2, uint32_t& r3,
                                      uint32_t a) {
    asm volatile("ldmatrix.sync.aligned.m8n8.x4.shared.b16 {%0,%1,%2,%3}, [%4];"
                 : "=r"(r0), "=r"(r1), "=r"(r2), "=r"(r3) : "r"(a));
}
__device__ __forceinline__ void ldsm4t(uint32_t& r0, uint32_t& r1, uint32_t& r2, uint32_t& r3,
                                       uint32_t a) {
    asm volatile("ldmatrix.sync.aligned.m8n8.x4.trans.shared.b16 {%0,%1,%2,%3}, [%4];"
                 : "=r"(r0), "=r"(r1), "=r"(r2), "=r"(r3) : "r"(a));
}
__device__ __forceinline__ void mma16816h(float* d, const uint32_t* a, uint32_t b0, uint32_t b1) {
    asm volatile(
        "mma.sync.aligned.m16n8k16.row.col.f32.f16.f16.f32 "
        "{%0,%1,%2,%3},{%4,%5,%6,%7},{%8,%9},{%0,%1,%2,%3};"
        : "+f"(d[0]), "+f"(d[1]), "+f"(d[2]), "+f"(d[3])
        : "r"(a[0]), "r"(a[1]), "r"(a[2]), "r"(a[3]), "r"(b0), "r"(b1));
}
__device__ __forceinline__ void cp16(uint32_t dst, const void* src) {
    asm volatile("cp.async.ca.shared.global [%0], [%1], 16;" :: "r"(dst), "l"(src));
}

// ---------------- k1 smem layout (bytes) ----------------
#define S1_A    0             // A fp16: 64 x 264 = 33792 (V fp16 aliases here later)
#define S1_B0   33792         // staging buf0: 256 x 40 fp16 = 20480
#define S1_B1   54272         // staging buf1: 20480
#define S1_KF   74752         // Kf fp16: 64 x 264 = 33792
#define S1_BIAS 108544        // bq|bk|bv: 3 x 256 fp32
#define K1_SMEM 111616

// ---------------- k2 smem layout (bytes) ----------------
#define J_A  0                // fp16 Qf/msg: 64 x 264 = 33792
#define J_B0 33792            // staging buf0: 256 x 40 fp16 = 20480
#define J_B1 54272            // staging buf1: 20480
#define J_BD 74752            // 8 heads x 32 x 40 fp16 = 20480
#define J_Z  95232            // 64 x 8 fp32 = 2048
#define J_KS 97280            // 256 fp32 = 1024
#define K2_SMEM 98304

// A stride 264 fp16; B stride 40 fp16. m64n32 warp tile, single product.
__device__ __forceinline__ void mma_block64s(float acc[4][4][4],
                                             uint32_t aF, int m0, int ka,
                                             uint32_t bF, int n0, int kb, int lane) {
    uint32_t Af[4][4], Bf[2][4];
    int ar = m0 + (lane & 15);
    int ac = ka + ((lane >> 4) << 3);
    uint32_t aoff = (uint32_t)(ar * 264 + ac) * 2;
#pragma unroll
    for (int ma = 0; ma < 4; ++ma)
        ldsm4(Af[ma][0], Af[ma][1], Af[ma][2], Af[ma][3], aF + aoff + ma * 16 * 528);
    int br = n0 + (lane & 7) + ((lane >> 4) << 3);
    int bc = kb + (((lane >> 3) & 1) << 3);
    uint32_t boff = (uint32_t)(br * 40 + bc) * 2;
#pragma unroll
    for (int nb = 0; nb < 2; ++nb)
        ldsm4(Bf[nb][0], Bf[nb][1], Bf[nb][2], Bf[nb][3], bF + boff + nb * 16 * 80);
#pragma unroll
    for (int ma = 0; ma < 4; ++ma)
#pragma unroll
        for (int na = 0; na < 4; ++na)
            mma16816h(acc[ma][na], Af[ma],
                      Bf[na >> 1][(na & 1) * 2], Bf[na >> 1][(na & 1) * 2 + 1]);
}

// ---------------- prep kernels ----------------
__global__ __launch_bounds__(256) void prep_w_kernel(const float* __restrict__ Wq,
                                                     const float* __restrict__ Wk,
                                                     const float* __restrict__ Wv,
                                                     const float* __restrict__ Wm) {
    int id = blockIdx.x * 256 + threadIdx.x;   // 32768
    int m = id >> 13, rem = id & 8191, n = rem >> 5, g = rem & 31;
    const float* W = (m == 0) ? Wq : (m == 1) ? Wk : (m == 2) ? Wv : Wm;
    float4 a = *(const float4*)(W + (size_t)n * 256 + g * 8);
    float4 c = *(const float4*)(W + (size_t)n * 256 + g * 8 + 4);
    *(uint4*)&g_W[m][n][g * 8] =
        make_uint4(pkh(a.x, a.y), pkh(a.z, a.w), pkh(c.x, c.y), pkh(c.z, c.w));
}

__global__ __launch_bounds__(256) void reduce_bd_kernel() {
    int id = blockIdx.x * 256 + threadIdx.x;   // 65536
    int b = id >> 13, i = id & 8191;
    float s = 0.0f;
#pragma unroll 8
    for (int j = 0; j < 128; ++j) s += g_KVp[b * 128 + j][i];
    int h = i >> 10, d = (i >> 5) & 31, e = i & 31;
    g_BD[b][h][e][d] = __float2half_rn(s);
    if (id < 2048) {
        int bb = id >> 8, c = id & 255;
        float ks = 0.0f;
#pragma unroll 8
        for (int j = 0; j < 128; ++j) ks += g_Ksp[bb * 128 + j][c];
        g_Ksum[bb * 256 + c] = ks;
    }
}

// ---- cp.async weight staging: full n256 chunk (256 rows x 32 cols fp16) ----
__device__ __forceinline__ void stage_W(uint32_t buf, int mat, int kc, int t) {
#pragma unroll
    for (int i = 0; i < 4; ++i) {
        int s = t + i * 256, r = s >> 2, qq = s & 3;
        cp16(buf + r * 80 + qq * 16, (const char*)&g_W[mat][r][kc * 32] + qq * 16);
    }
}

// Full 256-deep GEMM pass: m64 (all rows), n0 = warp's 32 cols, cp.async pipelined.
// b0/b1 = staging buffer smem offsets.
__device__ __forceinline__ void run_gemm(float acc[4][4][4], uint32_t sb,
                                         uint32_t aF, uint32_t b0, uint32_t b1,
                                         int t, int lane, int n0, int mat) {
    stage_W(sb + b0, mat, 0, t);
    asm volatile("cp.async.commit_group;" ::: "memory");
    for (int kc = 0; kc < 8; ++kc) {
        uint32_t bFa = sb + ((kc & 1) ? b1 : b0);
        if (kc < 7) {
            stage_W(sb + (((kc + 1) & 1) ? b1 : b0), mat, kc + 1, t);
            asm volatile("cp.async.commit_group;" ::: "memory");
            asm volatile("cp.async.wait_group 1;" ::: "memory");
        } else {
            asm volatile("cp.async.wait_group 0;" ::: "memory");
        }
        __syncthreads();
        mma_block64s(acc, aF, 0, kc * 32,      bFa, n0, 0,  lane);
        mma_block64s(acc, aF, 0, kc * 32 + 16, bFa, n0, 16, lane);
        __syncthreads();
    }
}

// fp32 input -> fp16 A tile (64 rows, stride 264)
__device__ __forceinline__ void build_A1(unsigned char* sm, int t, int row0,
                                         const float* __restrict__ X) {
    __syncthreads();
#pragma unroll
    for (int i = 0; i < 16; ++i) {
        int idx = t + i * 256;
        int r = idx >> 6, c = (idx & 63) * 4;
        float4 xv = *(const float4*)(X + (size_t)(row0 + r) * Es + c);
        *(uint2*)(sm + S1_A + (uint32_t)(r * 264 + c) * 2) =
            make_uint2(pkh(xv.x, xv.y), pkh(xv.z, xv.w));
    }
    __syncthreads();
}

// ---------------- K1: projections + KV via MMA (64-row tiles, 2 CTAs/SM) ----------------
__global__ __launch_bounds__(256, 2)
void k1_kernel(const float* __restrict__ q, const float* __restrict__ kin,
               const float* __restrict__ vin,
               const float* __restrict__ bq, const float* __restrict__ bk,
               const float* __restrict__ bv) {
    extern __shared__ unsigned char sm[];
    const uint32_t sb = smem_u32(sm);
    const int t = threadIdx.x, lane = t & 31, wid = t >> 5;
    const int n0 = wid * 32;
    const int tile = blockIdx.x, row0 = tile * 64;

    float* sB = (float*)(sm + S1_BIAS);
    if (t < 192) {
        const float* src = (t < 64) ? bq : (t < 128) ? bk : bv;
        ((float4*)sB)[t] = ((const float4*)src)[t & 63];
    }

    const uint32_t aF = sb + S1_A;
    const uint32_t kfb = sb + S1_KF;   // Kf fp16, stride 264
    const uint32_t vfb = sb + S1_A;    // V fp16 aliases A region

    // ---- Phase Q ----
    build_A1(sm, t, row0, q);
    {
        float acc[4][4][4];
#pragma unroll
        for (int ma = 0; ma < 4; ++ma)
#pragma unroll
            for (int na = 0; na < 4; ++na)
#pragma unroll
                for (int i = 0; i < 4; ++i) acc[ma][na][i] = 0.0f;
        run_gemm(acc, sb, aF, S1_B0, S1_B1, t, lane, n0, 0);
        __half* dQ = g_Qf + (size_t)tile * 16384;
#pragma unroll
        for (int ma = 0; ma < 4; ++ma) {
            int r1 = ma * 16 + (lane >> 2);
            int r2 = r1 + 8;
#pragma unroll
            for (int na = 0; na < 4; ++na) {
                int cg = n0 + na * 8 + (lane & 3) * 2;
                *(uint32_t*)(dQ + r1 * 256 + cg) =
                    pkh(fmap(acc[ma][na][0] + sB[cg]), fmap(acc[ma][na][1] + sB[cg + 1]));
                *(uint32_t*)(dQ + r2 * 256 + cg) =
                    pkh(fmap(acc[ma][na][2] + sB[cg]), fmap(acc[ma][na][3] + sB[cg + 1]));
            }
        }
    }

    // ---- Phase K: Kf -> fp16 dedicated region ----
    build_A1(sm, t, row0, kin);
    {
        float acc[4][4][4];
#pragma unroll
        for (int ma = 0; ma < 4; ++ma)
#pragma unroll
            for (int na = 0; na < 4; ++na)
#pragma unroll
                for (int i = 0; i < 4; ++i) acc[ma][na][i] = 0.0f;
        run_gemm(acc, sb, aF, S1_B0, S1_B1, t, lane, n0, 1);
#pragma unroll
        for (int ma = 0; ma < 4; ++ma) {
            int r1 = ma * 16 + (lane >> 2);
            int r2 = r1 + 8;
#pragma unroll
            for (int na = 0; na < 4; ++na) {
                int cg = n0 + na * 8 + (lane & 3) * 2;
                *(uint32_t*)(sm + S1_KF + (uint32_t)(r1 * 264 + cg) * 2) =
                    pkh(fmap(acc[ma][na][0] + sB[256 + cg]),
                        fmap(acc[ma][na][1] + sB[256 + cg + 1]));
                *(uint32_t*)(sm + S1_KF + (uint32_t)(r2 * 264 + cg) * 2) =
                    pkh(fmap(acc[ma][na][2] + sB[256 + cg]),
                        fmap(acc[ma][na][3] + sB[256 + cg + 1]));
            }
        }
    }

    // ---- Phase V: single pass, V -> fp16 into A region after MMAs ----
    build_A1(sm, t, row0, vin);
    {
        float acc[4][4][4];
#pragma unroll
        for (int ma = 0; ma < 4; ++ma)
#pragma unroll
            for (int na = 0; na < 4; ++na)
#pragma unroll
                for (int i = 0; i < 4; ++i) acc[ma][na][i] = 0.0f;
        run_gemm(acc, sb, aF, S1_B0, S1_B1, t, lane, n0, 2);
        __syncthreads();   // all V MMAs complete before overwriting A with V
#pragma unroll
        for (int ma = 0; ma < 4; ++ma) {
            int r1 = ma * 16 + (lane >> 2);
            int r2 = r1 + 8;
#pragma unroll
            for (int na = 0; na < 4; ++na) {
                int cg = n0 + na * 8 + (lane & 3) * 2;
                *(uint32_t*)(sm + (uint32_t)(r1 * 264 + cg) * 2) =
                    pkh(acc[ma][na][0] + sB[512 + cg], acc[ma][na][1] + sB[512 + cg + 1]);
                *(uint32_t*)(sm + (uint32_t)(r2 * 264 + cg) * 2) =
                    pkh(acc[ma][na][2] + sB[512 + cg], acc[ma][na][3] + sB[512 + cg + 1]);
            }
        }
    }
    __syncthreads();

    // ---- KV via MMA: warp = head, m32(d) x n32(e) x k64(r), fp16 ----
    {
        const int head = wid;
        float acc[2][4][4];
#pragma unroll
        for (int ma = 0; ma < 2; ++ma)
#pragma unroll
            for (int na = 0; na < 4; ++na)
#pragma unroll
                for (int i = 0; i < 4; ++i) acc[ma][na][i] = 0.0f;
        for (int ks = 0; ks < 4; ++ks) {
            const int r0 = ks * 16;
            uint32_t At[2][4], Bt[2][4];
            int arow = r0 + ((lane >> 4) << 3) + (lane & 7);
            int acol = head * 32 + (((lane >> 3) & 1) << 3);
#pragma unroll
            for (int ma = 0; ma < 2; ++ma)
                ldsm4t(At[ma][0], At[ma][1], At[ma][2], At[ma][3],
                       kfb + (uint32_t)(arow * 264 + acol + ma * 16) * 2);
            int brow = r0 + (((lane >> 3) & 1) << 3) + (lane & 7);
            int bcol = head * 32 + ((lane >> 4) << 3);
#pragma unroll
            for (int nb = 0; nb < 2; ++nb)
                ldsm4t(Bt[nb][0], Bt[nb][1], Bt[nb][2], Bt[nb][3],
                       vfb + (uint32_t)(brow * 264 + bcol + nb * 16) * 2);
#pragma unroll
            for (int ma = 0; ma < 2; ++ma)
#pragma unroll
                for (int na = 0; na < 4; ++na)
                    mma16816h(acc[ma][na], At[ma],
                              Bt[na >> 1][(na & 1) * 2], Bt[na >> 1][(na & 1) * 2 + 1]);
        }
#pragma unroll
        for (int ma = 0; ma < 2; ++ma) {
            int d1 = ma * 16 + (lane >> 2), d2 = d1 + 8;
#pragma unroll
            for (int na = 0; na < 4; ++na) {
                int e = na * 8 + (lane & 3) * 2;
                *(float2*)&g_KVp[tile][(head * 32 + d1) * 32 + e] =
                    make_float2(acc[ma][na][0], acc[ma][na][1]);
                *(float2*)&g_KVp[tile][(head * 32 + d2) * 32 + e] =
                    make_float2(acc[ma][na][2], acc[ma][na][3]);
            }
        }
    }

    // ---- Ksum: column sums of fp16 Kf (64 rows) ----
    {
        float s = 0.0f;
#pragma unroll 8
        for (int r = 0; r < 64; ++r)
            s += __half2float(*(const __half*)(sm + S1_KF + (uint32_t)(r * 264 + t) * 2));
        g_Ksp[tile][t] = s;
    }
}

// ---------------- K2: Z + msg + out-proj (64-row tiles, 2 CTAs/SM) ----------------
__global__ __launch_bounds__(256, 2)
void k2_kernel(float* __restrict__ out) {
    extern __shared__ unsigned char sm[];
    const uint32_t sb = smem_u32(sm);
    const int t = threadIdx.x, lane = t & 31, wid = t >> 5;
    const int tile = blockIdx.x, row0 = tile * 64, b = tile >> 7;

    float* sZ  = (float*)(sm + J_Z);
    float* sKs = (float*)(sm + J_KS);
    const uint32_t aA = sb + J_A;

    // load Qf (fp16, 64 rows) into padded A smem, stride 264
    {
        const uint4* src = (const uint4*)(g_Qf + (size_t)tile * 16384);
#pragma unroll
        for (int i = 0; i < 8; ++i) {
            int s = t + i * 256;
            int r = s >> 5, qq = s & 31;
            *(uint4*)(sm + J_A + r * 528 + qq * 16) = src[(size_t)r * 32 + qq];
        }
    }
    // load BD (fp16, all heads) + Ksum
    {
        const uint4* src = (const uint4*)&g_BD[b][0][0][0];
        uint4* dst = (uint4*)(sm + J_BD);
#pragma unroll
        for (int i = 0; i < 5; ++i) dst[t + i * 256] = src[t + i * 256];
        if (t < 64) ((float4*)sKs)[t] = ((const float4*)(g_Ksum + b * 256))[t];
    }
    __syncthreads();

    // Z = 1/(Qf . Ksum + eps)   (64 rows x 8 heads = 512 tasks)
#pragma unroll
    for (int i = 0; i < 2; ++i) {
        int task = t + i * 256;
        int r = task >> 3, h = task & 7;
        float dot = 0.0f;
#pragma unroll
        for (int dp = 0; dp < 16; ++dp) {
            int c = h * 32 + dp * 2;
            uint32_t w = *(const uint32_t*)(sm + J_A + (uint32_t)(r * 264 + c) * 2);
            __half2 hv; memcpy(&hv, &w, 4);
            dot += __half2float(hv.x) * sKs[c] + __half2float(hv.y) * sKs[c + 1];
        }
        sZ[r * 8 + h] = 1.0f / (dot + 1e-6f);
    }
    __syncthreads();

    // msg: warp = head, m64 (all rows) x n32(e) x k32(d); scale by Z, overwrite A
    {
        const int head = wid;
        float acc[4][4][4];
#pragma unroll
        for (int ma = 0; ma < 4; ++ma)
#pragma unroll
            for (int na = 0; na < 4; ++na)
#pragma unroll
                for (int i = 0; i < 4; ++i) acc[ma][na][i] = 0.0f;
        uint32_t bdF = sb + J_BD + head * 2560;
        mma_block64s(acc, aA, 0, head * 32,      bdF, 0, 0,  lane);
        mma_block64s(acc, aA, 0, head * 32 + 16, bdF, 0, 16, lane);
        __syncthreads();   // all warps done reading A before overwriting
#pragma unroll
        for (int ma = 0; ma < 4; ++ma) {
            int r1 = ma * 16 + (lane >> 2);
            int r2 = r1 + 8;
            float z1 = sZ[r1 * 8 + head], z2 = sZ[r2 * 8 + head];
#pragma unroll
            for (int na = 0; na < 4; ++na) {
                int cg = head * 32 + na * 8 + (lane & 3) * 2;
                *(uint32_t*)(sm + J_A + (uint32_t)(r1 * 264 + cg) * 2) =
                    pkh(acc[ma][na][0] * z1, acc[ma][na][1] * z1);
                *(uint32_t*)(sm + J_A + (uint32_t)(r2 * 264 + cg) * 2) =
                    pkh(acc[ma][na][2] * z2, acc[ma][na][3] * z2);
            }
        }
    }
    __syncthreads();

    // out = msg @ Wm^T: warp = n32 slice, m64 all rows, cp.async pipelined
    {
        float acc[4][4][4];
#pragma unroll
        for (int ma = 0; ma < 4; ++ma)
#pragma unroll
            for (int na = 0; na < 4; ++na)
#pragma unroll
                for (int i = 0; i < 4; ++i) acc[ma][na][i] = 0.0f;
        run_gemm(acc, sb, aA, J_B0, J_B1, t, lane, wid * 32, 3);
#pragma unroll
        for (int ma = 0; ma < 4; ++ma) {
            int r1 = ma * 16 + (lane >> 2);
            int r2 = r1 + 8;
#pragma unroll
            for (int na = 0; na < 4; ++na) {
                int cg = wid * 32 + na * 8 + (lane & 3) * 2;
                *(float2*)(out + (size_t)(row0 + r1) * 256 + cg) =
                    make_float2(acc[ma][na][0], acc[ma][na][1]);
                *(float2*)(out + (size_t)(row0 + r2) * 256 + cg) =
                    make_float2(acc[ma][na][2], acc[ma][na][3]);
            }
        }
    }
}

// ---------------------------------------------------------------------------
extern "C" void kernel_launch(void* const* d_in, const int* in_sizes, int n_in,
                              void* d_out, int out_size) {
    const float* q  = (const float*)d_in[0];
    const float* k  = (const float*)d_in[1];
    const float* v  = (const float*)d_in[2];
    const float* Wq = (const float*)d_in[3];
    const float* bq = (const float*)d_in[4];
    const float* Wk = (const float*)d_in[5];
    const float* bk = (const float*)d_in[6];
    const float* Wv = (const float*)d_in[7];
    const float* bv = (const float*)d_in[8];
    const float* Wm = (const float*)d_in[9];
    float* out = (float*)d_out;

    cudaFuncSetAttribute(k1_kernel, cudaFuncAttributeMaxDynamicSharedMemorySize, K1_SMEM);
    cudaFuncSetAttribute(k2_kernel, cudaFuncAttributeMaxDynamicSharedMemorySize, K2_SMEM);

    prep_w_kernel<<<128, 256>>>(Wq, Wk, Wv, Wm);
    k1_kernel<<<NT1, 256, K1_SMEM>>>(q, k, v, bq, bk, bv);
    reduce_bd_kernel<<<256, 256>>>();
    k2_kernel<<<NT2, 256, K2_SMEM>>>(out);
}

// round 14
// speedup vs baseline: 5.7353x; 1.0781x over previous
#include <cuda_runtime.h>
#include <cuda_fp16.h>
#include <math.h>
#include <stdint.h>
#include <string.h>

// LoFTR linear attention via ldmatrix + mma.sync, fp16 operands / fp32 accum.
// B=8, L=8192, E=256, H=8, D=32.
// Round 14: Q-projection moved into k2 (no Qf scratch round-trip); fp16 KV partials.

#define Es 256
#define NT1 1024            // k1 tiles (64 rows)
#define NT2 1024            // k2 tiles (64 rows)

// ---------------- device scratch ----------------
__device__ __half g_W[4][256][256];                      // [mat][n][k] fp16
__device__ __half g_KVp[NT1][8192];                      // per-k1-tile KV partials (fp16)
__device__ float g_Ksp[NT1][256];                        // per-k1-tile Ksum partials
__device__ float g_Ksum[8 * 256];
__device__ __half g_BD[8][8][32][40];                    // [b][h][e][d(pad 40)] = KV^T fp16

// ---------------- helpers ----------------
__device__ __forceinline__ float fmap(float x) { return x > 0.0f ? x + 1.0f : expf(x); }

__device__ __forceinline__ uint32_t pkh(float a, float b) {
    __half2 v = __floats2half2_rn(a, b);
    uint32_t r; memcpy(&r, &v, 4); return r;
}
__device__ __forceinline__ uint32_t smem_u32(const void* p) {
    uint32_t a;
    asm("{ .reg .u64 t; cvta.to.shared.u64 t, %1; cvt.u32.u64 %0, t; }" : "=r"(a) : "l"(p));
    return a;
}
__device__ __forceinline__ void ldsm4(uint32_t& r0, uint32_t& r1, uint32_t& r2, uint32_t& r3,
                                      uint32_t a) {
    asm volatile("ldmatrix.sync.aligned.m8n8.x4.shared.b16 {%0,%1,%2,%3}, [%4];"
                 : "=r"(r0), "=r"(r1), "=r"(r2), "=r"(r3) : "r"(a));
}
__device__ __forceinline__ void ldsm4t(uint32_t& r0, uint32_t& r1, uint32_t& r2, uint32_t& r3,
                                       uint32_t a) {
    asm volatile("ldmatrix.sync.aligned.m8n8.x4.trans.shared.b16 {%0,%1,%2,%3}, [%4];"
                 : "=r"(r0), "=r"(r1), "=r"(r2), "=r"(r3) : "r"(a));
}
__device__ __forceinline__ void mma16816h(float* d, const uint32_t* a, uint32_t b0, uint32_t b1) {
    asm volatile(
        "mma.sync.aligned.m16n8k16.row.col.f32.f16.f16.f32 "
        "{%0,%1,%2,%3},{%4,%5,%6,%7},{%8,%9},{%0,%1,%2,%3};"
        : "+f"(d[0]), "+f"(d[1]), "+f"(d[2]), "+f"(d[3])
        : "r"(a[0]), "r"(a[1]), "r"(a[2]), "r"(a[3]), "r"(b0), "r"(b1));
}
__device__ __forceinline__ void cp16(uint32_t dst, const void* src) {
    asm volatile("cp.async.ca.shared.global [%0], [%1], 16;" :: "r"(dst), "l"(src));
}

// ---------------- k1 smem layout (bytes) ----------------
#define S1_A    0             // A fp16: 64 x 264 = 33792 (V fp16 aliases here later)
#define S1_B0   33792         // staging buf0: 256 x 40 fp16 = 20480
#define S1_B1   54272         // staging buf1: 20480
#define S1_KF   74752         // Kf fp16: 64 x 264 = 33792
#define S1_BIAS 108544        // bk|bv: 2 x 256 fp32 = 2048
#define K1_SMEM 110592

// ---------------- k2 smem layout (bytes) ----------------
#define J_A  0                // fp16 q/Qf/msg: 64 x 264 = 33792
#define J_B0 33792            // staging buf0: 20480
#define J_B1 54272            // staging buf1: 20480
#define J_BD 74752            // 8 heads x 32 x 40 fp16 = 20480
#define J_Z  95232            // 64 x 8 fp32 = 2048
#define J_KS 97280            // 256 fp32 = 1024
#define J_BQ 98304            // bq: 256 fp32 = 1024
#define K2_SMEM 99328

// A stride 264 fp16; B stride 40 fp16. m64n32 warp tile, single product.
__device__ __forceinline__ void mma_block64s(float acc[4][4][4],
                                             uint32_t aF, int m0, int ka,
                                             uint32_t bF, int n0, int kb, int lane) {
    uint32_t Af[4][4], Bf[2][4];
    int ar = m0 + (lane & 15);
    int ac = ka + ((lane >> 4) << 3);
    uint32_t aoff = (uint32_t)(ar * 264 + ac) * 2;
#pragma unroll
    for (int ma = 0; ma < 4; ++ma)
        ldsm4(Af[ma][0], Af[ma][1], Af[ma][2], Af[ma][3], aF + aoff + ma * 16 * 528);
    int br = n0 + (lane & 7) + ((lane >> 4) << 3);
    int bc = kb + (((lane >> 3) & 1) << 3);
    uint32_t boff = (uint32_t)(br * 40 + bc) * 2;
#pragma unroll
    for (int nb = 0; nb < 2; ++nb)
        ldsm4(Bf[nb][0], Bf[nb][1], Bf[nb][2], Bf[nb][3], bF + boff + nb * 16 * 80);
#pragma unroll
    for (int ma = 0; ma < 4; ++ma)
#pragma unroll
        for (int na = 0; na < 4; ++na)
            mma16816h(acc[ma][na], Af[ma],
                      Bf[na >> 1][(na & 1) * 2], Bf[na >> 1][(na & 1) * 2 + 1]);
}

// ---------------- prep kernels ----------------
__global__ __launch_bounds__(256) void prep_w_kernel(const float* __restrict__ Wq,
                                                     const float* __restrict__ Wk,
                                                     const float* __restrict__ Wv,
                                                     const float* __restrict__ Wm) {
    int id = blockIdx.x * 256 + threadIdx.x;   // 32768
    int m = id >> 13, rem = id & 8191, n = rem >> 5, g = rem & 31;
    const float* W = (m == 0) ? Wq : (m == 1) ? Wk : (m == 2) ? Wv : Wm;
    float4 a = *(const float4*)(W + (size_t)n * 256 + g * 8);
    float4 c = *(const float4*)(W + (size_t)n * 256 + g * 8 + 4);
    *(uint4*)&g_W[m][n][g * 8] =
        make_uint4(pkh(a.x, a.y), pkh(a.z, a.w), pkh(c.x, c.y), pkh(c.z, c.w));
}

__global__ __launch_bounds__(256) void reduce_bd_kernel() {
    int id = blockIdx.x * 256 + threadIdx.x;   // 65536
    int b = id >> 13, i = id & 8191;
    float s = 0.0f;
#pragma unroll 8
    for (int j = 0; j < 128; ++j) s += __half2float(g_KVp[b * 128 + j][i]);
    int h = i >> 10, d = (i >> 5) & 31, e = i & 31;
    g_BD[b][h][e][d] = __float2half_rn(s);
    if (id < 2048) {
        int bb = id >> 8, c = id & 255;
        float ks = 0.0f;
#pragma unroll 8
        for (int j = 0; j < 128; ++j) ks += g_Ksp[bb * 128 + j][c];
        g_Ksum[bb * 256 + c] = ks;
    }
}

// ---- cp.async weight staging: full n256 chunk (256 rows x 32 cols fp16) ----
__device__ __forceinline__ void stage_W(uint32_t buf, int mat, int kc, int t) {
#pragma unroll
    for (int i = 0; i < 4; ++i) {
        int s = t + i * 256, r = s >> 2, qq = s & 3;
        cp16(buf + r * 80 + qq * 16, (const char*)&g_W[mat][r][kc * 32] + qq * 16);
    }
}

// Full 256-deep GEMM pass: m64 (all rows), n0 = warp's 32 cols, cp.async pipelined.
__device__ __forceinline__ void run_gemm(float acc[4][4][4], uint32_t sb,
                                         uint32_t aF, uint32_t b0, uint32_t b1,
                                         int t, int lane, int n0, int mat) {
    stage_W(sb + b0, mat, 0, t);
    asm volatile("cp.async.commit_group;" ::: "memory");
    for (int kc = 0; kc < 8; ++kc) {
        uint32_t bFa = sb + ((kc & 1) ? b1 : b0);
        if (kc < 7) {
            stage_W(sb + (((kc + 1) & 1) ? b1 : b0), mat, kc + 1, t);
            asm volatile("cp.async.commit_group;" ::: "memory");
            asm volatile("cp.async.wait_group 1;" ::: "memory");
        } else {
            asm volatile("cp.async.wait_group 0;" ::: "memory");
        }
        __syncthreads();
        mma_block64s(acc, aF, 0, kc * 32,      bFa, n0, 0,  lane);
        mma_block64s(acc, aF, 0, kc * 32 + 16, bFa, n0, 16, lane);
        __syncthreads();
    }
}

// fp32 input -> fp16 A tile (64 rows, stride 264, smem offset 0)
__device__ __forceinline__ void build_A(unsigned char* sm, int t, int row0,
                                        const float* __restrict__ X) {
    __syncthreads();
#pragma unroll
    for (int i = 0; i < 16; ++i) {
        int idx = t + i * 256;
        int r = idx >> 6, c = (idx & 63) * 4;
        float4 xv = *(const float4*)(X + (size_t)(row0 + r) * Es + c);
        *(uint2*)(sm + (uint32_t)(r * 264 + c) * 2) =
            make_uint2(pkh(xv.x, xv.y), pkh(xv.z, xv.w));
    }
    __syncthreads();
}

// ---------------- K1: K/V projections + KV via MMA (64-row tiles) ----------------
__global__ __launch_bounds__(256, 2)
void k1_kernel(const float* __restrict__ kin, const float* __restrict__ vin,
               const float* __restrict__ bk, const float* __restrict__ bv) {
    extern __shared__ unsigned char sm[];
    const uint32_t sb = smem_u32(sm);
    const int t = threadIdx.x, lane = t & 31, wid = t >> 5;
    const int n0 = wid * 32;
    const int tile = blockIdx.x, row0 = tile * 64;

    float* sB = (float*)(sm + S1_BIAS);
    if (t < 128) {
        const float* src = (t < 64) ? bk : bv;
        ((float4*)sB)[t] = ((const float4*)src)[t & 63];
    }

    const uint32_t aF = sb + S1_A;
    const uint32_t kfb = sb + S1_KF;   // Kf fp16, stride 264
    const uint32_t vfb = sb + S1_A;    // V fp16 aliases A region

    // ---- Phase K: Kf -> fp16 dedicated region ----
    build_A(sm, t, row0, kin);
    {
        float acc[4][4][4];
#pragma unroll
        for (int ma = 0; ma < 4; ++ma)
#pragma unroll
            for (int na = 0; na < 4; ++na)
#pragma unroll
                for (int i = 0; i < 4; ++i) acc[ma][na][i] = 0.0f;
        run_gemm(acc, sb, aF, S1_B0, S1_B1, t, lane, n0, 1);
#pragma unroll
        for (int ma = 0; ma < 4; ++ma) {
            int r1 = ma * 16 + (lane >> 2);
            int r2 = r1 + 8;
#pragma unroll
            for (int na = 0; na < 4; ++na) {
                int cg = n0 + na * 8 + (lane & 3) * 2;
                *(uint32_t*)(sm + S1_KF + (uint32_t)(r1 * 264 + cg) * 2) =
                    pkh(fmap(acc[ma][na][0] + sB[cg]), fmap(acc[ma][na][1] + sB[cg + 1]));
                *(uint32_t*)(sm + S1_KF + (uint32_t)(r2 * 264 + cg) * 2) =
                    pkh(fmap(acc[ma][na][2] + sB[cg]), fmap(acc[ma][na][3] + sB[cg + 1]));
            }
        }
    }

    // ---- Phase V: single pass, V -> fp16 into A region after MMAs ----
    build_A(sm, t, row0, vin);
    {
        float acc[4][4][4];
#pragma unroll
        for (int ma = 0; ma < 4; ++ma)
#pragma unroll
            for (int na = 0; na < 4; ++na)
#pragma unroll
                for (int i = 0; i < 4; ++i) acc[ma][na][i] = 0.0f;
        run_gemm(acc, sb, aF, S1_B0, S1_B1, t, lane, n0, 2);
        __syncthreads();   // all V MMAs complete before overwriting A with V
#pragma unroll
        for (int ma = 0; ma < 4; ++ma) {
            int r1 = ma * 16 + (lane >> 2);
            int r2 = r1 + 8;
#pragma unroll
            for (int na = 0; na < 4; ++na) {
                int cg = n0 + na * 8 + (lane & 3) * 2;
                *(uint32_t*)(sm + (uint32_t)(r1 * 264 + cg) * 2) =
                    pkh(acc[ma][na][0] + sB[256 + cg], acc[ma][na][1] + sB[256 + cg + 1]);
                *(uint32_t*)(sm + (uint32_t)(r2 * 264 + cg) * 2) =
                    pkh(acc[ma][na][2] + sB[256 + cg], acc[ma][na][3] + sB[256 + cg + 1]);
            }
        }
    }
    __syncthreads();

    // ---- KV via MMA: warp = head, m32(d) x n32(e) x k64(r), fp16 ----
    {
        const int head = wid;
        float acc[2][4][4];
#pragma unroll
        for (int ma = 0; ma < 2; ++ma)
#pragma unroll
            for (int na = 0; na < 4; ++na)
#pragma unroll
                for (int i = 0; i < 4; ++i) acc[ma][na][i] = 0.0f;
        for (int ks = 0; ks < 4; ++ks) {
            const int r0 = ks * 16;
            uint32_t At[2][4], Bt[2][4];
            int arow = r0 + ((lane >> 4) << 3) + (lane & 7);
            int acol = head * 32 + (((lane >> 3) & 1) << 3);
#pragma unroll
            for (int ma = 0; ma < 2; ++ma)
                ldsm4t(At[ma][0], At[ma][1], At[ma][2], At[ma][3],
                       kfb + (uint32_t)(arow * 264 + acol + ma * 16) * 2);
            int brow = r0 + (((lane >> 3) & 1) << 3) + (lane & 7);
            int bcol = head * 32 + ((lane >> 4) << 3);
#pragma unroll
            for (int nb = 0; nb < 2; ++nb)
                ldsm4t(Bt[nb][0], Bt[nb][1], Bt[nb][2], Bt[nb][3],
                       vfb + (uint32_t)(brow * 264 + bcol + nb * 16) * 2);
#pragma unroll
            for (int ma = 0; ma < 2; ++ma)
#pragma unroll
                for (int na = 0; na < 4; ++na)
                    mma16816h(acc[ma][na], At[ma],
                              Bt[na >> 1][(na & 1) * 2], Bt[na >> 1][(na & 1) * 2 + 1]);
        }
#pragma unroll
        for (int ma = 0; ma < 2; ++ma) {
            int d1 = ma * 16 + (lane >> 2), d2 = d1 + 8;
#pragma unroll
            for (int na = 0; na < 4; ++na) {
                int e = na * 8 + (lane & 3) * 2;
                *(uint32_t*)&g_KVp[tile][(head * 32 + d1) * 32 + e] =
                    pkh(acc[ma][na][0], acc[ma][na][1]);
                *(uint32_t*)&g_KVp[tile][(head * 32 + d2) * 32 + e] =
                    pkh(acc[ma][na][2], acc[ma][na][3]);
            }
        }
    }

    // ---- Ksum: column sums of fp16 Kf (64 rows) ----
    {
        float s = 0.0f;
#pragma unroll 8
        for (int r = 0; r < 64; ++r)
            s += __half2float(*(const __half*)(sm + S1_KF + (uint32_t)(r * 264 + t) * 2));
        g_Ksp[tile][t] = s;
    }
}

// ---------------- K2: Q-proj + Z + msg + out-proj (64-row tiles) ----------------
__global__ __launch_bounds__(256, 2)
void k2_kernel(const float* __restrict__ q, const float* __restrict__ bq,
               float* __restrict__ out) {
    extern __shared__ unsigned char sm[];
    const uint32_t sb = smem_u32(sm);
    const int t = threadIdx.x, lane = t & 31, wid = t >> 5;
    const int tile = blockIdx.x, row0 = tile * 64, b = tile >> 7;

    float* sZ  = (float*)(sm + J_Z);
    float* sKs = (float*)(sm + J_KS);
    float* sBq = (float*)(sm + J_BQ);
    const uint32_t aA = sb + J_A;

    // load BD (fp16, all heads) + Ksum + bq
    {
        const uint4* src = (const uint4*)&g_BD[b][0][0][0];
        uint4* dst = (uint4*)(sm + J_BD);
#pragma unroll
        for (int i = 0; i < 5; ++i) dst[t + i * 256] = src[t + i * 256];
        if (t < 64) ((float4*)sKs)[t] = ((const float4*)(g_Ksum + b * 256))[t];
        else if (t < 128) ((float4*)sBq)[t - 64] = ((const float4*)bq)[t - 64];
    }

    // ---- Phase Qf: A = q tile; GEMM x Wq; fmap epilogue in place ----
    build_A(sm, t, row0, q);
    {
        float acc[4][4][4];
#pragma unroll
        for (int ma = 0; ma < 4; ++ma)
#pragma unroll
            for (int na = 0; na < 4; ++na)
#pragma unroll
                for (int i = 0; i < 4; ++i) acc[ma][na][i] = 0.0f;
        run_gemm(acc, sb, aA, J_B0, J_B1, t, lane, wid * 32, 0);
        __syncthreads();   // all Q MMAs complete before overwriting A with Qf
#pragma unroll
        for (int ma = 0; ma < 4; ++ma) {
            int r1 = ma * 16 + (lane >> 2);
            int r2 = r1 + 8;
#pragma unroll
            for (int na = 0; na < 4; ++na) {
                int cg = wid * 32 + na * 8 + (lane & 3) * 2;
                *(uint32_t*)(sm + J_A + (uint32_t)(r1 * 264 + cg) * 2) =
                    pkh(fmap(acc[ma][na][0] + sBq[cg]), fmap(acc[ma][na][1] + sBq[cg + 1]));
                *(uint32_t*)(sm + J_A + (uint32_t)(r2 * 264 + cg) * 2) =
                    pkh(fmap(acc[ma][na][2] + sBq[cg]), fmap(acc[ma][na][3] + sBq[cg + 1]));
            }
        }
    }
    __syncthreads();

    // Z = 1/(Qf . Ksum + eps)   (64 rows x 8 heads = 512 tasks)
#pragma unroll
    for (int i = 0; i < 2; ++i) {
        int task = t + i * 256;
        int r = task >> 3, h = task & 7;
        float dot = 0.0f;
#pragma unroll
        for (int dp = 0; dp < 16; ++dp) {
            int c = h * 32 + dp * 2;
            uint32_t w = *(const uint32_t*)(sm + J_A + (uint32_t)(r * 264 + c) * 2);
            __half2 hv; memcpy(&hv, &w, 4);
            dot += __half2float(hv.x) * sKs[c] + __half2float(hv.y) * sKs[c + 1];
        }
        sZ[r * 8 + h] = 1.0f / (dot + 1e-6f);
    }
    __syncthreads();

    // msg: warp = head, m64 x n32(e) x k32(d); scale by Z, overwrite A
    {
        const int head = wid;
        float acc[4][4][4];
#pragma unroll
        for (int ma = 0; ma < 4; ++ma)
#pragma unroll
            for (int na = 0; na < 4; ++na)
#pragma unroll
                for (int i = 0; i < 4; ++i) acc[ma][na][i] = 0.0f;
        uint32_t bdF = sb + J_BD + head * 2560;
        mma_block64s(acc, aA, 0, head * 32,      bdF, 0, 0,  lane);
        mma_block64s(acc, aA, 0, head * 32 + 16, bdF, 0, 16, lane);
        __syncthreads();   // all warps done reading A before overwriting
#pragma unroll
        for (int ma = 0; ma < 4; ++ma) {
            int r1 = ma * 16 + (lane >> 2);
            int r2 = r1 + 8;
            float z1 = sZ[r1 * 8 + head], z2 = sZ[r2 * 8 + head];
#pragma unroll
            for (int na = 0; na < 4; ++na) {
                int cg = head * 32 + na * 8 + (lane & 3) * 2;
                *(uint32_t*)(sm + J_A + (uint32_t)(r1 * 264 + cg) * 2) =
                    pkh(acc[ma][na][0] * z1, acc[ma][na][1] * z1);
                *(uint32_t*)(sm + J_A + (uint32_t)(r2 * 264 + cg) * 2) =
                    pkh(acc[ma][na][2] * z2, acc[ma][na][3] * z2);
            }
        }
    }
    __syncthreads();

    // out = msg @ Wm^T: warp = n32 slice, m64 all rows, cp.async pipelined
    {
        float acc[4][4][4];
#pragma unroll
        for (int ma = 0; ma < 4; ++ma)
#pragma unroll
            for (int na = 0; na < 4; ++na)
#pragma unroll
                for (int i = 0; i < 4; ++i) acc[ma][na][i] = 0.0f;
        run_gemm(acc, sb, aA, J_B0, J_B1, t, lane, wid * 32, 3);
#pragma unroll
        for (int ma = 0; ma < 4; ++ma) {
            int r1 = ma * 16 + (lane >> 2);
            int r2 = r1 + 8;
#pragma unroll
            for (int na = 0; na < 4; ++na) {
                int cg = wid * 32 + na * 8 + (lane & 3) * 2;
                *(float2*)(out + (size_t)(row0 + r1) * 256 + cg) =
                    make_float2(acc[ma][na][0], acc[ma][na][1]);
                *(float2*)(out + (size_t)(row0 + r2) * 256 + cg) =
                    make_float2(acc[ma][na][2], acc[ma][na][3]);
            }
        }
    }
}

// ---------------------------------------------------------------------------
extern "C" void kernel_launch(void* const* d_in, const int* in_sizes, int n_in,
                              void* d_out, int out_size) {
    const float* q  = (const float*)d_in[0];
    const float* k  = (const float*)d_in[1];
    const float* v  = (const float*)d_in[2];
    const float* Wq = (const float*)d_in[3];
    const float* bq = (const float*)d_in[4];
    const float* Wk = (const float*)d_in[5];
    const float* bk = (const float*)d_in[6];
    const float* Wv = (const float*)d_in[7];
    const float* bv = (const float*)d_in[8];
    const float* Wm = (const float*)d_in[9];
    float* out = (float*)d_out;

    cudaFuncSetAttribute(k1_kernel, cudaFuncAttributeMaxDynamicSharedMemorySize, K1_SMEM);
    cudaFuncSetAttribute(k2_kernel, cudaFuncAttributeMaxDynamicSharedMemorySize, K2_SMEM);

    prep_w_kernel<<<128, 256>>>(Wq, Wk, Wv, Wm);
    k1_kernel<<<NT1, 256, K1_SMEM>>>(k, v, bk, bv);
    reduce_bd_kernel<<<256, 256>>>();
    k2_kernel<<<NT2, 256, K2_SMEM>>>(q, bq, out);
}